// round 4
// baseline (speedup 1.0000x reference)
#include <cuda_runtime.h>
#include <math.h>

#define EPSF 1e-5f
#define PI_OVER_32 0.09817477042468103f

// ---------------- constant permutations ----------------
__constant__ int c_IDX[16]  = {0,7,10,13,1,4,11,14,2,5,8,15,3,6,9,12};
__constant__ int c_BACK[16] = {0,4,8,12,5,9,13,1,10,14,2,6,15,3,7,11};

// ---------------- device scratch (no allocs allowed) ----------------
__device__ float  g_u  [16*16*256*256];   // unfolded+IDX-permuted  [b,16,L,d]
__device__ float  g_y  [16*16*256*256];   // concat(x1..x4)         [b,16,L,d]
__device__ float  g_acc[16*4*256*256];    // running sum x1+..+xk
__device__ float  g_t  [16*4*256*256];    // transformer state
__device__ float  g_ln [16*4*256*256];    // LN output
__device__ float  g_qkv[16*4*256*96];
__device__ float  g_att[16*4*256*32];
__device__ float  g_mlp[16*4*256*512];
__device__ float  g_zp [16*64*64*256];    // folded image [b,h,w,c] (c fastest)
__device__ float2 g_f1 [16*64*33*256];
__device__ float2 g_f2 [16*64*33*256];
__device__ float  g_zf [16*256*64*64];    // filtered image, channel-major
__device__ float  g_c3 [16*256*64*64];    // conv3+bn+silu output

// ---------------- tiny utility kernels ----------------
__global__ void zero_kernel(float* __restrict__ p) {
    p[(size_t)blockIdx.x * 256 + threadIdx.x] = 0.f;
}

// u[b,j,l,c] = x[b,c, ph*4+ky, pw*4+kx], kp = IDX[j]
__global__ void unfold_kernel(const float* __restrict__ x, float* __restrict__ u) {
    int i = blockIdx.x * 256 + threadIdx.x;   // 16*16*256*256
    int c = i & 255;
    int l = (i >> 8) & 255;
    int j = (i >> 16) & 15;
    int b = i >> 20;
    int kp = c_IDX[j];
    int ky = kp >> 2, kx = kp & 3;
    int ph = l >> 4,  pw = l & 15;
    u[i] = x[((b * 256 + c) * 64 + ph * 4 + ky) * 64 + pw * 4 + kx];
}

// t = u[:, g*4:(g+1)*4] + acc
__global__ void group_in_kernel(const float* __restrict__ u, const float* __restrict__ acc,
                                float* __restrict__ t, int g) {
    int i = blockIdx.x * 256 + threadIdx.x;   // 16*4*256*256
    int c = i & 255;
    int l = (i >> 8) & 255;
    int p = (i >> 16) & 3;
    int b = i >> 18;
    t[i] = u[((b * 16 + g * 4 + p) * 256 + l) * 256 + c] + acc[i];
}

// y slot g = t; acc += t
__global__ void group_store_kernel(const float* __restrict__ t, float* __restrict__ y,
                                   float* __restrict__ acc, int g) {
    int i = blockIdx.x * 256 + threadIdx.x;
    int c = i & 255;
    int l = (i >> 8) & 255;
    int p = (i >> 16) & 3;
    int b = i >> 18;
    float v = t[i];
    y[((b * 16 + g * 4 + p) * 256 + l) * 256 + c] = v;
    acc[i] += v;
}

// zp[b,h,w,c] = y[b, BACK[kp], l, c]   (fold)
__global__ void fold_kernel(const float* __restrict__ y, float* __restrict__ zp) {
    int i = blockIdx.x * 256 + threadIdx.x;   // 16*64*64*256
    int c  = i & 255;
    int wp = (i >> 8) & 63;
    int hp = (i >> 14) & 63;
    int b  = i >> 20;
    int ky = hp & 3, ph = hp >> 2;
    int kx = wp & 3, pw = wp >> 2;
    int j = c_BACK[ky * 4 + kx];
    int l = ph * 16 + pw;
    zp[i] = y[((b * 16 + j) * 256 + l) * 256 + c];
}

// ---------------- layernorm (one block per row, 256 cols) ----------------
__global__ void ln_kernel(const float* __restrict__ in, const float* __restrict__ gw,
                          const float* __restrict__ bw, float* __restrict__ out) {
    int row = blockIdx.x;
    int tid = threadIdx.x;
    float v = in[row * 256 + tid];
    float s = v, sq = v * v;
    #pragma unroll
    for (int o = 16; o; o >>= 1) {
        s  += __shfl_xor_sync(0xffffffffu, s, o);
        sq += __shfl_xor_sync(0xffffffffu, sq, o);
    }
    __shared__ float ss[8], sqs[8];
    if ((tid & 31) == 0) { ss[tid >> 5] = s; sqs[tid >> 5] = sq; }
    __syncthreads();
    s = 0.f; sq = 0.f;
    #pragma unroll
    for (int k = 0; k < 8; k++) { s += ss[k]; sq += sqs[k]; }
    float mean = s * (1.f / 256.f);
    float var  = sq * (1.f / 256.f) - mean * mean;
    float rstd = rsqrtf(var + EPSF);
    out[row * 256 + tid] = (v - mean) * rstd * gw[tid] + bw[tid];
}

// ---------------- generic SGEMM  C = A@B (+epilogue) ----------------
// 64x64 tile, BK=16, 256 threads, 4x4 per thread. M % 64 == 0, K % 16 == 0, N % 4 == 0.
// epilogue order: resid -> bias -> bn-affine(row) -> silu
__global__ void gemm_kernel(const float* __restrict__ A, const float* __restrict__ B,
                            float* __restrict__ C,
                            const float* __restrict__ bias, const float* __restrict__ resid,
                            const float* __restrict__ bnG, const float* __restrict__ bnB,
                            const float* __restrict__ bnM, const float* __restrict__ bnV,
                            int M, int N, int K, int lda, int ldb, int ldc,
                            int act, long long sA, long long sB, long long sC) {
    __shared__ float As[16][64];
    __shared__ float Bs[16][64];
    int z = blockIdx.z;
    A += z * sA; B += z * sB; C += z * sC;
    const float* R = resid ? resid + z * sC : (const float*)0;
    int bm = blockIdx.y * 64, bn = blockIdx.x * 64;
    int tid = threadIdx.x;
    int ty = tid >> 4, tx = tid & 15;
    int aRow = tid >> 2,  aCol = (tid & 3) * 4;
    int bRow = tid >> 4,  bCol = (tid & 15) * 4;
    float acc[4][4] = {};
    for (int k0 = 0; k0 < K; k0 += 16) {
        float4 av = *(const float4*)(A + (size_t)(bm + aRow) * lda + k0 + aCol);
        As[aCol + 0][aRow] = av.x;
        As[aCol + 1][aRow] = av.y;
        As[aCol + 2][aRow] = av.z;
        As[aCol + 3][aRow] = av.w;
        float4 bv = make_float4(0.f, 0.f, 0.f, 0.f);
        if (bn + bCol < N)
            bv = *(const float4*)(B + (size_t)(k0 + bRow) * ldb + bn + bCol);
        *(float4*)&Bs[bRow][bCol] = bv;
        __syncthreads();
        #pragma unroll
        for (int k = 0; k < 16; k++) {
            float4 a4 = *(const float4*)&As[k][ty * 4];
            float4 b4 = *(const float4*)&Bs[k][tx * 4];
            float ar[4] = {a4.x, a4.y, a4.z, a4.w};
            float br[4] = {b4.x, b4.y, b4.z, b4.w};
            #pragma unroll
            for (int i = 0; i < 4; i++)
                #pragma unroll
                for (int j = 0; j < 4; j++)
                    acc[i][j] += ar[i] * br[j];
        }
        __syncthreads();
    }
    #pragma unroll
    for (int i = 0; i < 4; i++) {
        int row = bm + ty * 4 + i;
        float sc = 1.f, sh = 0.f;
        if (bnG) {
            float s_ = bnG[row] * rsqrtf(bnV[row] + EPSF);
            sc = s_; sh = bnB[row] - bnM[row] * s_;
        }
        #pragma unroll
        for (int j = 0; j < 4; j++) {
            int col = bn + tx * 4 + j;
            if (col < N) {
                float v = acc[i][j];
                if (R)    v += R[(size_t)row * ldc + col];
                if (bias) v += bias[col];
                v = v * sc + sh;
                if (act) v = v / (1.f + __expf(-v));
                C[(size_t)row * ldc + col] = v;
            }
        }
    }
}

// ---------------- attention: block per (b*4+p, head), thread per query ----------------
__global__ void attn_kernel(const float* __restrict__ qkv, float* __restrict__ att) {
    int bp = blockIdx.x;   // 0..63
    int h  = blockIdx.y;   // 0..3
    int n  = threadIdx.x;  // 0..255
    __shared__ float ks[256 * 8];
    __shared__ float vs[256 * 8];
    int row = bp * 256 + n;
    const float* base = qkv + (size_t)row * 96 + h * 8;
    float4 q0 = *(const float4*)(base);
    float4 q1 = *(const float4*)(base + 4);
    *(float4*)&ks[n * 8]     = *(const float4*)(base + 32);
    *(float4*)&ks[n * 8 + 4] = *(const float4*)(base + 36);
    *(float4*)&vs[n * 8]     = *(const float4*)(base + 64);
    *(float4*)&vs[n * 8 + 4] = *(const float4*)(base + 68);
    __syncthreads();
    float q[8] = {q0.x, q0.y, q0.z, q0.w, q1.x, q1.y, q1.z, q1.w};
    float mx = -1e30f, ssum = 0.f;
    float acc[8] = {};
    for (int m = 0; m < 256; m++) {
        float4 ka = *(const float4*)&ks[m * 8];
        float4 kb = *(const float4*)&ks[m * 8 + 4];
        float d = q[0]*ka.x + q[1]*ka.y + q[2]*ka.z + q[3]*ka.w
                + q[4]*kb.x + q[5]*kb.y + q[6]*kb.z + q[7]*kb.w;
        d *= 0.35355339059327373f;
        float w;
        if (d > mx) {
            float corr = __expf(mx - d);
            ssum *= corr;
            #pragma unroll
            for (int j = 0; j < 8; j++) acc[j] *= corr;
            mx = d;
            w = 1.f;
        } else {
            w = __expf(d - mx);
        }
        ssum += w;
        float4 va = *(const float4*)&vs[m * 8];
        float4 vb = *(const float4*)&vs[m * 8 + 4];
        acc[0] += w * va.x; acc[1] += w * va.y; acc[2] += w * va.z; acc[3] += w * va.w;
        acc[4] += w * vb.x; acc[5] += w * vb.y; acc[6] += w * vb.z; acc[7] += w * vb.w;
    }
    float inv = 1.f / ssum;
    float* o = att + (size_t)row * 32 + h * 8;
    *(float4*)(o)     = make_float4(acc[0]*inv, acc[1]*inv, acc[2]*inv, acc[3]*inv);
    *(float4*)(o + 4) = make_float4(acc[4]*inv, acc[5]*inv, acc[6]*inv, acc[7]*inv);
}

// ---------------- FFT stages (64-pt DFT, ortho: 1/8 per 1D transform) ----------------
// stage1: rfft along W:  f1[b,h,w,c] = 1/8 * sum_x zp[b,h,x,c] e^{-2pi i w x/64}
__global__ void fft1_kernel(const float* __restrict__ zp, float2* __restrict__ f1) {
    int w = blockIdx.x, h = blockIdx.y, b = blockIdx.z;
    int c = threadIdx.x;
    __shared__ float2 tw[64];
    if (c < 64) {
        int m = (w * c) & 63;
        float sn, cs; sincosf(m * PI_OVER_32, &sn, &cs);
        tw[c] = make_float2(cs, sn);
    }
    __syncthreads();
    const float* base = zp + ((size_t)(b * 64 + h) * 64) * 256 + c;
    float re = 0.f, im = 0.f;
    for (int x = 0; x < 64; x++) {
        float g = base[x * 256];
        float2 t = tw[x];
        re += g * t.x;
        im -= g * t.y;
    }
    f1[((size_t)(b * 64 + h) * 33 + w) * 256 + c] = make_float2(re * 0.125f, im * 0.125f);
}

// stage2: fft along H:  f2[b,k,w,c] = 1/8 * sum_h f1[b,h,w,c] e^{-2pi i k h/64}
__global__ void fft2_kernel(const float2* __restrict__ f1, float2* __restrict__ f2) {
    int w = blockIdx.x, k = blockIdx.y, b = blockIdx.z;
    int c = threadIdx.x;
    __shared__ float2 tw[64];
    if (c < 64) {
        int m = (k * c) & 63;
        float sn, cs; sincosf(m * PI_OVER_32, &sn, &cs);
        tw[c] = make_float2(cs, sn);
    }
    __syncthreads();
    float re = 0.f, im = 0.f;
    for (int h = 0; h < 64; h++) {
        float2 g = f1[((size_t)(b * 64 + h) * 33 + w) * 256 + c];
        float2 t = tw[h];
        re += g.x * t.x + g.y * t.y;   // (re+i im)(cos - i sin)
        im += g.y * t.x - g.x * t.y;
    }
    f2[((size_t)(b * 64 + k) * 33 + w) * 256 + c] = make_float2(re * 0.125f, im * 0.125f);
}

// stage3: multiply by complex weight, ifft along H:
//   A[b,h,w,c] = 1/8 * sum_k (f2[b,k,w,c] * wc[k,w,c]) e^{+2pi i k h/64}
__global__ void fft3_kernel(const float2* __restrict__ f2, const float2* __restrict__ fw,
                            float2* __restrict__ A) {
    int w = blockIdx.x, h = blockIdx.y, b = blockIdx.z;
    int c = threadIdx.x;
    __shared__ float2 tw[64];
    if (c < 64) {
        int m = (h * c) & 63;
        float sn, cs; sincosf(m * PI_OVER_32, &sn, &cs);
        tw[c] = make_float2(cs, sn);
    }
    __syncthreads();
    float re = 0.f, im = 0.f;
    for (int k = 0; k < 64; k++) {
        float2 g = f2[((size_t)(b * 64 + k) * 33 + w) * 256 + c];
        float2 wc = fw[((size_t)k * 33 + w) * 256 + c];
        float tr = g.x * wc.x - g.y * wc.y;
        float ti = g.x * wc.y + g.y * wc.x;
        float2 t = tw[k];
        re += tr * t.x - ti * t.y;     // (tr+i ti)(cos + i sin)
        im += tr * t.y + ti * t.x;
    }
    A[((size_t)(b * 64 + h) * 33 + w) * 256 + c] = make_float2(re * 0.125f, im * 0.125f);
}

// stage4: irfft along W -> real, channel-major output
//   zf[b,c,h,x] = 1/8 * ( Re A0 + (-1)^x Re A32 + 2 sum_{w=1}^{31} Re(Aw e^{+2pi i w x/64}) )
__global__ void fft4_kernel(const float2* __restrict__ A, float* __restrict__ zf) {
    int h = blockIdx.x, cg = blockIdx.y, b = blockIdx.z;
    int tid = threadIdx.x;
    int cl = tid >> 6;          // 0..3
    int x  = tid & 63;
    int c = cg * 4 + cl;
    const float2* base = A + ((size_t)(b * 64 + h) * 33) * 256 + c;
    float r = base[0].x;
    {
        float a32 = base[32 * 256].x;
        r += (x & 1) ? -a32 : a32;
    }
    for (int w = 1; w < 32; w++) {
        float2 a = base[w * 256];
        int m = (w * x) & 63;
        float sn, cs; sincosf(m * PI_OVER_32, &sn, &cs);
        r += 2.f * (a.x * cs - a.y * sn);
    }
    zf[((size_t)(b * 256 + c) * 64 + h) * 64 + x] = r * 0.125f;
}

// ---------------- conv4: 3x3, 256->256, pad 1, + BN + SiLU ----------------
// grid: x=tile(0..3: 32x32 tiles of 64x64), y=ocg(0..31), z=b. 256 threads, 2x2 px, 8 oc.
__global__ void conv4_kernel(const float* __restrict__ in, const float* __restrict__ w,
                             const float* __restrict__ g4, const float* __restrict__ b4,
                             const float* __restrict__ m4, const float* __restrict__ v4,
                             float* __restrict__ out) {
    __shared__ float wS[8 * 8 * 9];       // [oc][ic][9] for current ic chunk
    __shared__ float inS[8][34][34];
    int tile = blockIdx.x;
    int ty0 = (tile >> 1) * 32, tx0 = (tile & 1) * 32;
    int ocg = blockIdx.y, b = blockIdx.z;
    int tid = threadIdx.x;
    int py = tid >> 4, px = tid & 15;
    int oy = ty0 + py * 2, ox = tx0 + px * 2;
    float acc[8][4] = {};
    for (int ch = 0; ch < 32; ch++) {
        for (int e = tid; e < 576; e += 256) {
            int oc = e / 72; int rem = e % 72; int ic = rem / 9; int kk = rem % 9;
            wS[e] = w[((size_t)(ocg * 8 + oc) * 256 + ch * 8 + ic) * 9 + kk];
        }
        for (int e = tid; e < 8 * 34 * 34; e += 256) {
            int ic = e / 1156; int rem = e % 1156; int r = rem / 34; int cl = rem % 34;
            int gy = ty0 + r - 1, gx = tx0 + cl - 1;
            float v = 0.f;
            if (gy >= 0 && gy < 64 && gx >= 0 && gx < 64)
                v = in[((size_t)(b * 256 + ch * 8 + ic) * 64 + gy) * 64 + gx];
            inS[ic][r][cl] = v;
        }
        __syncthreads();
        #pragma unroll 2
        for (int ic = 0; ic < 8; ic++) {
            float pin[4][4];
            #pragma unroll
            for (int dy = 0; dy < 4; dy++)
                #pragma unroll
                for (int dx = 0; dx < 4; dx++)
                    pin[dy][dx] = inS[ic][py * 2 + dy][px * 2 + dx];
            #pragma unroll
            for (int oc = 0; oc < 8; oc++) {
                const float* ww = &wS[oc * 72 + ic * 9];
                #pragma unroll
                for (int ky = 0; ky < 3; ky++)
                    #pragma unroll
                    for (int kx = 0; kx < 3; kx++) {
                        float wv = ww[ky * 3 + kx];
                        acc[oc][0] += wv * pin[ky    ][kx    ];
                        acc[oc][1] += wv * pin[ky    ][kx + 1];
                        acc[oc][2] += wv * pin[ky + 1][kx    ];
                        acc[oc][3] += wv * pin[ky + 1][kx + 1];
                    }
            }
        }
        __syncthreads();
    }
    #pragma unroll
    for (int oc = 0; oc < 8; oc++) {
        int och = ocg * 8 + oc;
        float s = g4[och] * rsqrtf(v4[och] + EPSF);
        float t = b4[och] - m4[och] * s;
        #pragma unroll
        for (int dy = 0; dy < 2; dy++)
            #pragma unroll
            for (int dx = 0; dx < 2; dx++) {
                float v = acc[oc][dy * 2 + dx] * s + t;
                v = v / (1.f + __expf(-v));
                out[((size_t)(b * 256 + och) * 64 + oy + dy) * 64 + ox + dx] = v;
            }
    }
}

// ---------------- host launch ----------------
extern "C" void kernel_launch(void* const* d_in, const int* in_sizes, int n_in,
                              void* d_out, int out_size) {
    const float* x      = (const float*)d_in[0];
    const float* ln1_g  = (const float*)d_in[1];
    const float* ln1_b  = (const float*)d_in[2];
    const float* wqkv   = (const float*)d_in[3];
    const float* wout   = (const float*)d_in[4];
    const float* bout   = (const float*)d_in[5];
    const float* ln2_g  = (const float*)d_in[6];
    const float* ln2_b  = (const float*)d_in[7];
    const float* w1     = (const float*)d_in[8];
    const float* b1     = (const float*)d_in[9];
    const float* w2     = (const float*)d_in[10];
    const float* b2     = (const float*)d_in[11];
    const float* fft_w  = (const float*)d_in[12];
    const float* conv3w = (const float*)d_in[13];
    const float* bn3_g  = (const float*)d_in[14];
    const float* bn3_b  = (const float*)d_in[15];
    const float* bn3_m  = (const float*)d_in[16];
    const float* bn3_v  = (const float*)d_in[17];
    const float* conv4w = (const float*)d_in[18];
    const float* bn4_g  = (const float*)d_in[19];
    const float* bn4_b  = (const float*)d_in[20];
    const float* bn4_m  = (const float*)d_in[21];
    const float* bn4_v  = (const float*)d_in[22];
    float* outp = (float*)d_out;

    float *u, *y, *ac, *t, *lnb, *qk, *at, *mlp, *zp, *zf, *c3;
    float2 *f1, *f2;
    cudaGetSymbolAddress((void**)&u,   g_u);
    cudaGetSymbolAddress((void**)&y,   g_y);
    cudaGetSymbolAddress((void**)&ac,  g_acc);
    cudaGetSymbolAddress((void**)&t,   g_t);
    cudaGetSymbolAddress((void**)&lnb, g_ln);
    cudaGetSymbolAddress((void**)&qk,  g_qkv);
    cudaGetSymbolAddress((void**)&at,  g_att);
    cudaGetSymbolAddress((void**)&mlp, g_mlp);
    cudaGetSymbolAddress((void**)&zp,  g_zp);
    cudaGetSymbolAddress((void**)&f1,  g_f1);
    cudaGetSymbolAddress((void**)&f2,  g_f2);
    cudaGetSymbolAddress((void**)&zf,  g_zf);
    cudaGetSymbolAddress((void**)&c3,  g_c3);

    const float* NUL = (const float*)0;

    zero_kernel<<<16384, 256>>>(ac);
    unfold_kernel<<<65536, 256>>>(x, u);

    for (int g = 0; g < 4; g++) {
        group_in_kernel<<<16384, 256>>>(u, ac, t, g);
        for (int i = 0; i < 2; i++) {
            // --- attention block ---
            ln_kernel<<<16384, 256>>>(t, ln1_g + i * 256, ln1_b + i * 256, lnb);
            gemm_kernel<<<dim3(2, 256, 1), 256>>>(lnb, wqkv + i * 256 * 96, qk,
                NUL, NUL, NUL, NUL, NUL, NUL,
                16384, 96, 256, 256, 96, 96, 0, 0, 0, 0);
            attn_kernel<<<dim3(64, 4), 256>>>(qk, at);
            gemm_kernel<<<dim3(4, 256, 1), 256>>>(at, wout + i * 32 * 256, t,
                bout + i * 256, t, NUL, NUL, NUL, NUL,
                16384, 256, 32, 32, 256, 256, 0, 0, 0, 0);
            // --- MLP block ---
            ln_kernel<<<16384, 256>>>(t, ln2_g + i * 256, ln2_b + i * 256, lnb);
            gemm_kernel<<<dim3(8, 256, 1), 256>>>(lnb, w1 + i * 256 * 512, mlp,
                b1 + i * 512, NUL, NUL, NUL, NUL, NUL,
                16384, 512, 256, 256, 512, 512, 1, 0, 0, 0);
            gemm_kernel<<<dim3(4, 256, 1), 256>>>(mlp, w2 + i * 512 * 256, t,
                b2 + i * 256, t, NUL, NUL, NUL, NUL,
                16384, 256, 512, 512, 256, 256, 0, 0, 0, 0);
        }
        group_store_kernel<<<16384, 256>>>(t, y, ac, g);
    }

    fold_kernel<<<65536, 256>>>(y, zp);

    fft1_kernel<<<dim3(33, 64, 16), 256>>>(zp, f1);
    fft2_kernel<<<dim3(33, 64, 16), 256>>>(f1, f2);
    fft3_kernel<<<dim3(33, 64, 16), 256>>>(f2, (const float2*)fft_w, f1);
    fft4_kernel<<<dim3(64, 64, 16), 256>>>(f1, zf);

    // conv3 (1x1, 512->256) as two GEMM passes over concat([z, x]) + BN + SiLU
    gemm_kernel<<<dim3(64, 4, 16), 256>>>(conv3w, zf, c3,
        NUL, NUL, NUL, NUL, NUL, NUL,
        256, 4096, 256, 512, 4096, 4096, 0, 0, 256 * 4096, 256 * 4096);
    gemm_kernel<<<dim3(64, 4, 16), 256>>>(conv3w + 256, x, c3,
        NUL, c3, bn3_g, bn3_b, bn3_m, bn3_v,
        256, 4096, 256, 512, 4096, 4096, 1, 0, 256 * 4096, 256 * 4096);

    conv4_kernel<<<dim3(4, 32, 16), 256>>>(c3, conv4w, bn4_g, bn4_b, bn4_m, bn4_v, outp);
}

// round 5
// speedup vs baseline: 1.1279x; 1.1279x over previous
#include <cuda_runtime.h>
#include <mma.h>
#include <math.h>

using namespace nvcuda;

#define EPSF 1e-5f
#define PI_OVER_32 0.09817477042468103f

// ---------------- constant permutations ----------------
__constant__ int c_IDX[16]  = {0,7,10,13,1,4,11,14,2,5,8,15,3,6,9,12};
__constant__ int c_BACK[16] = {0,4,8,12,5,9,13,1,10,14,2,6,15,3,7,11};

// ---------------- device scratch (no allocs allowed) ----------------
__device__ float  g_u  [16*16*256*256];   // unfolded+IDX-permuted  [b,16,L,d]
__device__ float  g_y  [16*16*256*256];   // concat(x1..x4)         [b,16,L,d]
__device__ float  g_acc[16*4*256*256];    // running sum x1+..+xk
__device__ float  g_t  [16*4*256*256];    // transformer state
__device__ float  g_ln [16*4*256*256];    // LN output
__device__ float  g_qkv[16*4*256*128];    // qkv, ld=128 (cols 96..127 pad)
__device__ float  g_att[16*4*256*32];
__device__ float  g_mlp[16*4*256*512];
__device__ float  g_zp [16*64*64*256];    // folded image [b,h,w,c] (c fastest)
__device__ float2 g_f1 [16*64*33*256];
__device__ float2 g_f2 [16*64*33*256];
__device__ float  g_zf [16*256*64*64];    // filtered image, channel-major
__device__ float  g_c3 [16*256*64*64];    // conv3+bn+silu output
__device__ float  g_col[16u*2304u*4096u]; // im2col buffer for conv4

// ---------------- tiny utility kernels ----------------
__global__ void zero_kernel(float* __restrict__ p) {
    p[(size_t)blockIdx.x * 256 + threadIdx.x] = 0.f;
}

// unfold as 32x32 smem transpose: x[b,c,s] -> u[b,j,l,c]
__global__ void unfold_kernel(const float* __restrict__ x, float* __restrict__ u) {
    __shared__ float tile[32][33];
    int b  = blockIdx.z;
    int c0 = blockIdx.y * 32;
    int s0 = blockIdx.x * 32;
    int tx = threadIdx.x & 31, ty = threadIdx.x >> 5;   // 256 threads
    #pragma unroll
    for (int cc = 0; cc < 4; cc++)
        tile[ty + cc * 8][tx] =
            x[(size_t)(b * 256 + c0 + ty + cc * 8) * 4096 + s0 + tx];
    __syncthreads();
    #pragma unroll
    for (int cc = 0; cc < 4; cc++) {
        int s = s0 + ty + cc * 8;
        int h = s >> 6, w = s & 63;
        int kp = (h & 3) * 4 + (w & 3);
        int j = c_BACK[kp];                   // inverse of IDX == BACK
        int l = (h >> 2) * 16 + (w >> 2);
        u[((size_t)(b * 16 + j) * 256 + l) * 256 + c0 + tx] = tile[tx][ty + cc * 8];
    }
}

__device__ __forceinline__ float4 f4add(float4 a, float4 b) {
    return make_float4(a.x + b.x, a.y + b.y, a.z + b.z, a.w + b.w);
}

// t = u[:, g*4:(g+1)*4] + acc       (float4 over c)
__global__ void group_in_kernel(const float4* __restrict__ u, const float4* __restrict__ acc,
                                float4* __restrict__ t, int g) {
    int i = blockIdx.x * 256 + threadIdx.x;   // 16*4*256*64 = 1,048,576 float4
    int c4 = i & 63;
    int l = (i >> 6) & 255;
    int p = (i >> 14) & 3;
    int b = i >> 16;
    t[i] = f4add(u[((size_t)(b * 16 + g * 4 + p) * 256 + l) * 64 + c4], acc[i]);
}

// y slot g = t; acc += t
__global__ void group_store_kernel(const float4* __restrict__ t, float4* __restrict__ y,
                                   float4* __restrict__ acc, int g) {
    int i = blockIdx.x * 256 + threadIdx.x;
    int c4 = i & 63;
    int l = (i >> 6) & 255;
    int p = (i >> 14) & 3;
    int b = i >> 16;
    float4 v = t[i];
    y[((size_t)(b * 16 + g * 4 + p) * 256 + l) * 64 + c4] = v;
    acc[i] = f4add(acc[i], v);
}

// zp[b,h,w,c] = y[b, BACK[kp], l, c]   (fold), float4 over c
__global__ void fold_kernel(const float4* __restrict__ y, float4* __restrict__ zp) {
    int i = blockIdx.x * 256 + threadIdx.x;   // 16*64*64*64 = 4,194,304 float4
    int c4 = i & 63;
    int wp = (i >> 6) & 63;
    int hp = (i >> 12) & 63;
    int b  = i >> 18;
    int ky = hp & 3, ph = hp >> 2;
    int kx = wp & 3, pw = wp >> 2;
    int j = c_BACK[ky * 4 + kx];
    int l = ph * 16 + pw;
    zp[i] = y[((size_t)(b * 16 + j) * 256 + l) * 64 + c4];
}

// ---------------- layernorm: 4 rows per block, float4 ----------------
__global__ void ln_kernel(const float* __restrict__ in, const float* __restrict__ gw,
                          const float* __restrict__ bw, float* __restrict__ out) {
    int tid = threadIdx.x;
    int r = tid >> 6;                 // 0..3
    int t = tid & 63;
    size_t row = (size_t)blockIdx.x * 4 + r;
    float4 v = *(const float4*)(in + row * 256 + t * 4);
    float s  = v.x + v.y + v.z + v.w;
    float sq = v.x * v.x + v.y * v.y + v.z * v.z + v.w * v.w;
    #pragma unroll
    for (int o = 16; o; o >>= 1) {
        s  += __shfl_xor_sync(0xffffffffu, s, o);
        sq += __shfl_xor_sync(0xffffffffu, sq, o);
    }
    __shared__ float ss[8], sqs[8];
    int warp = tid >> 5;
    if ((tid & 31) == 0) { ss[warp] = s; sqs[warp] = sq; }
    __syncthreads();
    s  = ss[r * 2] + ss[r * 2 + 1];
    sq = sqs[r * 2] + sqs[r * 2 + 1];
    float mean = s * (1.f / 256.f);
    float var  = sq * (1.f / 256.f) - mean * mean;
    float rstd = rsqrtf(var + EPSF);
    float4 g4 = *(const float4*)(gw + t * 4);
    float4 b4 = *(const float4*)(bw + t * 4);
    float4 o4;
    o4.x = (v.x - mean) * rstd * g4.x + b4.x;
    o4.y = (v.y - mean) * rstd * g4.y + b4.y;
    o4.z = (v.z - mean) * rstd * g4.z + b4.z;
    o4.w = (v.w - mean) * rstd * g4.w + b4.w;
    *(float4*)(out + row * 256 + t * 4) = o4;
}

// ---------------- tf32 tensor-core GEMM  C = A@B (+epilogue) ----------------
// BM=128, BN=64, BK=16, 256 threads = 8 warps (4x2), warp tile 32x32 (2x2 wmma 16x16x8).
// Requires M%128==0, K%16==0, N%4==0, all pointers 16B aligned.
// epilogue: resid -> bias -> bn-affine(row) -> silu
#define BM 128
#define BN 64
#define BK 16
__global__ void gemm_tf32_kernel(const float* __restrict__ A, const float* __restrict__ B,
                                 float* __restrict__ C,
                                 const float* __restrict__ bias, const float* __restrict__ resid,
                                 const float* __restrict__ bnG, const float* __restrict__ bnB,
                                 const float* __restrict__ bnM, const float* __restrict__ bnV,
                                 int M, int N, int K, int lda, int ldb, int ldc,
                                 int act, long long sA, long long sB, long long sC) {
    __shared__ float As[BM][BK + 4];      // [m][k], ld=20
    __shared__ float Bs[BK][BN + 4];      // [k][n], ld=68
    __shared__ float epi[8][16][20];      // per-warp 16x16 staging
    int z = blockIdx.z;
    A += z * sA; B += z * sB; C += z * sC;
    const float* R = resid ? resid + z * sC : (const float*)0;
    int bm = blockIdx.y * BM, bn = blockIdx.x * BN;
    int tid = threadIdx.x, warp = tid >> 5, lane = tid & 31;
    int wr = warp >> 1, wc = warp & 1;

    wmma::fragment<wmma::accumulator, 16, 16, 8, float> acc[2][2];
    #pragma unroll
    for (int r = 0; r < 2; r++)
        #pragma unroll
        for (int c = 0; c < 2; c++)
            wmma::fill_fragment(acc[r][c], 0.f);

    int aRow = tid >> 2, aCol = (tid & 3) * 4;     // A: rows 0..63 (+64 second), 4 cols
    int bRow = tid >> 4, bCol = (tid & 15) * 4;    // B: 16 rows x 64 cols

    float4 pa0 = *(const float4*)(A + (size_t)(bm + aRow) * lda + aCol);
    float4 pa1 = *(const float4*)(A + (size_t)(bm + aRow + 64) * lda + aCol);
    float4 pb = make_float4(0.f, 0.f, 0.f, 0.f);
    if (bn + bCol < N) pb = *(const float4*)(B + (size_t)bRow * ldb + bn + bCol);

    for (int k0 = 0; k0 < K; k0 += BK) {
        *(float4*)&As[aRow][aCol]      = pa0;
        *(float4*)&As[aRow + 64][aCol] = pa1;
        *(float4*)&Bs[bRow][bCol]      = pb;
        __syncthreads();
        int kn = k0 + BK;
        if (kn < K) {
            pa0 = *(const float4*)(A + (size_t)(bm + aRow) * lda + kn + aCol);
            pa1 = *(const float4*)(A + (size_t)(bm + aRow + 64) * lda + kn + aCol);
            pb = make_float4(0.f, 0.f, 0.f, 0.f);
            if (bn + bCol < N) pb = *(const float4*)(B + (size_t)(kn + bRow) * ldb + bn + bCol);
        }
        #pragma unroll
        for (int ks = 0; ks < BK; ks += 8) {
            wmma::fragment<wmma::matrix_a, 16, 16, 8, wmma::precision::tf32, wmma::row_major> af[2];
            wmma::fragment<wmma::matrix_b, 16, 16, 8, wmma::precision::tf32, wmma::row_major> bf[2];
            #pragma unroll
            for (int r = 0; r < 2; r++) {
                wmma::load_matrix_sync(af[r], &As[wr * 32 + r * 16][ks], BK + 4);
                #pragma unroll
                for (int e = 0; e < af[r].num_elements; e++)
                    af[r].x[e] = wmma::__float_to_tf32(af[r].x[e]);
            }
            #pragma unroll
            for (int c = 0; c < 2; c++) {
                wmma::load_matrix_sync(bf[c], &Bs[ks][wc * 32 + c * 16], BN + 4);
                #pragma unroll
                for (int e = 0; e < bf[c].num_elements; e++)
                    bf[c].x[e] = wmma::__float_to_tf32(bf[c].x[e]);
            }
            #pragma unroll
            for (int r = 0; r < 2; r++)
                #pragma unroll
                for (int c = 0; c < 2; c++)
                    wmma::mma_sync(acc[r][c], af[r], bf[c], acc[r][c]);
        }
        __syncthreads();
    }

    // epilogue
    #pragma unroll
    for (int r = 0; r < 2; r++)
        #pragma unroll
        for (int c = 0; c < 2; c++) {
            wmma::store_matrix_sync(&epi[warp][0][0], acc[r][c], 20, wmma::mem_row_major);
            __syncwarp();
            int rowBase = bm + wr * 32 + r * 16;
            int colBase = bn + wc * 32 + c * 16;
            #pragma unroll
            for (int k = 0; k < 8; k++) {
                int idx = k * 32 + lane;
                int rr = idx >> 4, cc = idx & 15;
                int row = rowBase + rr, col = colBase + cc;
                float v = epi[warp][rr][cc];
                if (R)    v += R[(size_t)row * ldc + col];
                if (bias && col < N) v += bias[col];
                if (bnG) {
                    float s_ = bnG[row] * rsqrtf(bnV[row] + EPSF);
                    v = v * s_ + (bnB[row] - bnM[row] * s_);
                }
                if (act) v = v / (1.f + __expf(-v));
                C[(size_t)row * ldc + col] = v;
            }
            __syncwarp();
        }
}

// ---------------- attention: block per (b*4+p, head), thread per query ----------------
__global__ void attn_kernel(const float* __restrict__ qkv, float* __restrict__ att) {
    int bp = blockIdx.x;   // 0..63
    int h  = blockIdx.y;   // 0..3
    int n  = threadIdx.x;  // 0..255
    __shared__ float ks[256 * 8];
    __shared__ float vs[256 * 8];
    int row = bp * 256 + n;
    const float* base = qkv + (size_t)row * 128 + h * 8;   // ld=128
    float4 q0 = *(const float4*)(base);
    float4 q1 = *(const float4*)(base + 4);
    *(float4*)&ks[n * 8]     = *(const float4*)(base + 32);
    *(float4*)&ks[n * 8 + 4] = *(const float4*)(base + 36);
    *(float4*)&vs[n * 8]     = *(const float4*)(base + 64);
    *(float4*)&vs[n * 8 + 4] = *(const float4*)(base + 68);
    __syncthreads();
    float q[8] = {q0.x, q0.y, q0.z, q0.w, q1.x, q1.y, q1.z, q1.w};
    float mx = -1e30f, ssum = 0.f;
    float acc[8] = {};
    for (int m = 0; m < 256; m++) {
        float4 ka = *(const float4*)&ks[m * 8];
        float4 kb = *(const float4*)&ks[m * 8 + 4];
        float d = q[0]*ka.x + q[1]*ka.y + q[2]*ka.z + q[3]*ka.w
                + q[4]*kb.x + q[5]*kb.y + q[6]*kb.z + q[7]*kb.w;
        d *= 0.35355339059327373f;
        float w;
        if (d > mx) {
            float corr = __expf(mx - d);
            ssum *= corr;
            #pragma unroll
            for (int j = 0; j < 8; j++) acc[j] *= corr;
            mx = d;
            w = 1.f;
        } else {
            w = __expf(d - mx);
        }
        ssum += w;
        float4 va = *(const float4*)&vs[m * 8];
        float4 vb = *(const float4*)&vs[m * 8 + 4];
        acc[0] += w * va.x; acc[1] += w * va.y; acc[2] += w * va.z; acc[3] += w * va.w;
        acc[4] += w * vb.x; acc[5] += w * vb.y; acc[6] += w * vb.z; acc[7] += w * vb.w;
    }
    float inv = 1.f / ssum;
    float* o = att + (size_t)row * 32 + h * 8;
    *(float4*)(o)     = make_float4(acc[0]*inv, acc[1]*inv, acc[2]*inv, acc[3]*inv);
    *(float4*)(o + 4) = make_float4(acc[4]*inv, acc[5]*inv, acc[6]*inv, acc[7]*inv);
}

// ---------------- FFT stages (64-pt DFT, ortho: 1/8 per 1D transform) ----------------
__global__ void fft1_kernel(const float* __restrict__ zp, float2* __restrict__ f1) {
    int w = blockIdx.x, h = blockIdx.y, b = blockIdx.z;
    int c = threadIdx.x;
    __shared__ float2 tw[64];
    if (c < 64) {
        int m = (w * c) & 63;
        float sn, cs; sincosf(m * PI_OVER_32, &sn, &cs);
        tw[c] = make_float2(cs, sn);
    }
    __syncthreads();
    const float* base = zp + ((size_t)(b * 64 + h) * 64) * 256 + c;
    float re = 0.f, im = 0.f;
    for (int x = 0; x < 64; x++) {
        float g = base[x * 256];
        float2 t = tw[x];
        re += g * t.x;
        im -= g * t.y;
    }
    f1[((size_t)(b * 64 + h) * 33 + w) * 256 + c] = make_float2(re * 0.125f, im * 0.125f);
}

__global__ void fft2_kernel(const float2* __restrict__ f1, float2* __restrict__ f2) {
    int w = blockIdx.x, k = blockIdx.y, b = blockIdx.z;
    int c = threadIdx.x;
    __shared__ float2 tw[64];
    if (c < 64) {
        int m = (k * c) & 63;
        float sn, cs; sincosf(m * PI_OVER_32, &sn, &cs);
        tw[c] = make_float2(cs, sn);
    }
    __syncthreads();
    float re = 0.f, im = 0.f;
    for (int h = 0; h < 64; h++) {
        float2 g = f1[((size_t)(b * 64 + h) * 33 + w) * 256 + c];
        float2 t = tw[h];
        re += g.x * t.x + g.y * t.y;
        im += g.y * t.x - g.x * t.y;
    }
    f2[((size_t)(b * 64 + k) * 33 + w) * 256 + c] = make_float2(re * 0.125f, im * 0.125f);
}

__global__ void fft3_kernel(const float2* __restrict__ f2, const float2* __restrict__ fw,
                            float2* __restrict__ A) {
    int w = blockIdx.x, h = blockIdx.y, b = blockIdx.z;
    int c = threadIdx.x;
    __shared__ float2 tw[64];
    if (c < 64) {
        int m = (h * c) & 63;
        float sn, cs; sincosf(m * PI_OVER_32, &sn, &cs);
        tw[c] = make_float2(cs, sn);
    }
    __syncthreads();
    float re = 0.f, im = 0.f;
    for (int k = 0; k < 64; k++) {
        float2 g = f2[((size_t)(b * 64 + k) * 33 + w) * 256 + c];
        float2 wc = fw[((size_t)k * 33 + w) * 256 + c];
        float tr = g.x * wc.x - g.y * wc.y;
        float ti = g.x * wc.y + g.y * wc.x;
        float2 t = tw[k];
        re += tr * t.x - ti * t.y;
        im += tr * t.y + ti * t.x;
    }
    A[((size_t)(b * 64 + h) * 33 + w) * 256 + c] = make_float2(re * 0.125f, im * 0.125f);
}

__global__ void fft4_kernel(const float2* __restrict__ A, float* __restrict__ zf) {
    int h = blockIdx.x, cg = blockIdx.y, b = blockIdx.z;
    int tid = threadIdx.x;
    __shared__ float2 tw[64];
    if (tid < 64) {
        float sn, cs; sincosf(tid * PI_OVER_32, &sn, &cs);
        tw[tid] = make_float2(cs, sn);
    }
    __syncthreads();
    int cl = tid >> 6;          // 0..3
    int x  = tid & 63;
    int c = cg * 4 + cl;
    const float2* base = A + ((size_t)(b * 64 + h) * 33) * 256 + c;
    float r = base[0].x;
    {
        float a32 = base[32 * 256].x;
        r += (x & 1) ? -a32 : a32;
    }
    for (int w = 1; w < 32; w++) {
        float2 a = base[w * 256];
        float2 t = tw[(w * x) & 63];
        r += 2.f * (a.x * t.x - a.y * t.y);
    }
    zf[((size_t)(b * 256 + c) * 64 + h) * 64 + x] = r * 0.125f;
}

// ---------------- im2col for conv4: col[b][ic*9+kk][p] ----------------
__global__ void im2col_kernel(const float* __restrict__ in, float* __restrict__ col) {
    size_t i = (size_t)blockIdx.x * 256 + threadIdx.x;  // 16*2304*4096 elems
    int p = (int)(i & 4095);
    size_t t = i >> 12;
    int kk = (int)(t % 9);
    int t2 = (int)(t / 9);          // b*256 + ic
    int ic = t2 & 255, b = t2 >> 8;
    int y = p >> 6, x = p & 63;
    int gy = y + kk / 3 - 1, gx = x + kk % 3 - 1;
    float v = 0.f;
    if ((unsigned)gy < 64u && (unsigned)gx < 64u)
        v = in[((size_t)(b * 256 + ic) * 64 + gy) * 64 + gx];
    col[i] = v;
}

// ---------------- host launch ----------------
extern "C" void kernel_launch(void* const* d_in, const int* in_sizes, int n_in,
                              void* d_out, int out_size) {
    const float* x      = (const float*)d_in[0];
    const float* ln1_g  = (const float*)d_in[1];
    const float* ln1_b  = (const float*)d_in[2];
    const float* wqkv   = (const float*)d_in[3];
    const float* wout   = (const float*)d_in[4];
    const float* bout   = (const float*)d_in[5];
    const float* ln2_g  = (const float*)d_in[6];
    const float* ln2_b  = (const float*)d_in[7];
    const float* w1     = (const float*)d_in[8];
    const float* b1     = (const float*)d_in[9];
    const float* w2     = (const float*)d_in[10];
    const float* b2     = (const float*)d_in[11];
    const float* fft_w  = (const float*)d_in[12];
    const float* conv3w = (const float*)d_in[13];
    const float* bn3_g  = (const float*)d_in[14];
    const float* bn3_b  = (const float*)d_in[15];
    const float* bn3_m  = (const float*)d_in[16];
    const float* bn3_v  = (const float*)d_in[17];
    const float* conv4w = (const float*)d_in[18];
    const float* bn4_g  = (const float*)d_in[19];
    const float* bn4_b  = (const float*)d_in[20];
    const float* bn4_m  = (const float*)d_in[21];
    const float* bn4_v  = (const float*)d_in[22];
    float* outp = (float*)d_out;

    float *u, *y, *ac, *t, *lnb, *qk, *at, *mlp, *zp, *zf, *c3, *col;
    float2 *f1, *f2;
    cudaGetSymbolAddress((void**)&u,   g_u);
    cudaGetSymbolAddress((void**)&y,   g_y);
    cudaGetSymbolAddress((void**)&ac,  g_acc);
    cudaGetSymbolAddress((void**)&t,   g_t);
    cudaGetSymbolAddress((void**)&lnb, g_ln);
    cudaGetSymbolAddress((void**)&qk,  g_qkv);
    cudaGetSymbolAddress((void**)&at,  g_att);
    cudaGetSymbolAddress((void**)&mlp, g_mlp);
    cudaGetSymbolAddress((void**)&zp,  g_zp);
    cudaGetSymbolAddress((void**)&f1,  g_f1);
    cudaGetSymbolAddress((void**)&f2,  g_f2);
    cudaGetSymbolAddress((void**)&zf,  g_zf);
    cudaGetSymbolAddress((void**)&c3,  g_c3);
    cudaGetSymbolAddress((void**)&col, g_col);

    const float* NUL = (const float*)0;

    zero_kernel<<<16384, 256>>>(ac);
    unfold_kernel<<<dim3(128, 8, 16), 256>>>(x, u);

    for (int g = 0; g < 4; g++) {
        group_in_kernel<<<4096, 256>>>((const float4*)u, (const float4*)ac, (float4*)t, g);
        for (int i = 0; i < 2; i++) {
            // --- attention block ---
            ln_kernel<<<4096, 256>>>(t, ln1_g + i * 256, ln1_b + i * 256, lnb);
            gemm_tf32_kernel<<<dim3(2, 128, 1), 256>>>(lnb, wqkv + i * 256 * 96, qk,
                NUL, NUL, NUL, NUL, NUL, NUL,
                16384, 96, 256, 256, 96, 128, 0, 0, 0, 0);
            attn_kernel<<<dim3(64, 4), 256>>>(qk, at);
            gemm_tf32_kernel<<<dim3(4, 128, 1), 256>>>(at, wout + i * 32 * 256, t,
                bout + i * 256, t, NUL, NUL, NUL, NUL,
                16384, 256, 32, 32, 256, 256, 0, 0, 0, 0);
            // --- MLP block ---
            ln_kernel<<<4096, 256>>>(t, ln2_g + i * 256, ln2_b + i * 256, lnb);
            gemm_tf32_kernel<<<dim3(8, 128, 1), 256>>>(lnb, w1 + i * 256 * 512, mlp,
                b1 + i * 512, NUL, NUL, NUL, NUL, NUL,
                16384, 512, 256, 256, 512, 512, 1, 0, 0, 0);
            gemm_tf32_kernel<<<dim3(4, 128, 1), 256>>>(mlp, w2 + i * 512 * 256, t,
                b2 + i * 256, t, NUL, NUL, NUL, NUL,
                16384, 256, 512, 512, 256, 256, 0, 0, 0, 0);
        }
        group_store_kernel<<<4096, 256>>>((const float4*)t, (float4*)y, (float4*)ac, g);
    }

    fold_kernel<<<16384, 256>>>((const float4*)y, (float4*)zp);

    fft1_kernel<<<dim3(33, 64, 16), 256>>>(zp, f1);
    fft2_kernel<<<dim3(33, 64, 16), 256>>>(f1, f2);
    fft3_kernel<<<dim3(33, 64, 16), 256>>>(f2, (const float2*)fft_w, f1);
    fft4_kernel<<<dim3(64, 64, 16), 256>>>(f1, zf);

    // conv3 (1x1, 512->256) as two GEMM passes over concat([z, x]) + BN + SiLU
    gemm_tf32_kernel<<<dim3(64, 2, 16), 256>>>(conv3w, zf, c3,
        NUL, NUL, NUL, NUL, NUL, NUL,
        256, 4096, 256, 512, 4096, 4096, 0, 0, 256 * 4096, 256 * 4096);
    gemm_tf32_kernel<<<dim3(64, 2, 16), 256>>>(conv3w + 256, x, c3,
        NUL, c3, bn3_g, bn3_b, bn3_m, bn3_v,
        256, 4096, 256, 512, 4096, 4096, 1, 0, 256 * 4096, 256 * 4096);

    // conv4 (3x3, 256->256) = im2col + GEMM + BN + SiLU
    im2col_kernel<<<589824, 256>>>(c3, col);
    gemm_tf32_kernel<<<dim3(64, 2, 16), 256>>>(conv4w, col, outp,
        NUL, NUL, bn4_g, bn4_b, bn4_m, bn4_v,
        256, 4096, 2304, 2304, 4096, 4096, 1, 0, 2304LL * 4096LL, 256 * 4096);
}

// round 6
// speedup vs baseline: 1.2394x; 1.0989x over previous
#include <cuda_runtime.h>
#include <mma.h>
#include <math.h>

using namespace nvcuda;

#define EPSF 1e-5f
#define PI_OVER_32 0.09817477042468103f

// ---------------- constant permutations ----------------
__constant__ int c_IDX[16]  = {0,7,10,13,1,4,11,14,2,5,8,15,3,6,9,12};
__constant__ int c_BACK[16] = {0,4,8,12,5,9,13,1,10,14,2,6,15,3,7,11};

// ---------------- device scratch (no allocs allowed) ----------------
__device__ float  g_u  [16*16*256*256];   // unfolded+IDX-permuted  [b,16,L,d]
__device__ float  g_y  [16*16*256*256];   // concat(x1..x4)         [b,16,L,d]
__device__ float  g_acc[16*4*256*256];    // running sum x1+..+xk
__device__ float  g_t  [16*4*256*256];    // transformer state
__device__ float  g_ln [16*4*256*256];    // LN output
__device__ float  g_qkv[16*4*256*128];    // qkv, ld=128 (cols 96..127 pad)
__device__ float  g_att[16*4*256*32];
__device__ float  g_mlp[16*4*256*512];
__device__ float  g_zp [16*64*64*256];    // folded image [b,h,w,c] (c fastest)
__device__ float2 g_f1 [16*64*33*256];    // rfft along W
__device__ float2 g_f2 [16*64*33*256];    // after fwd-H + weight + inv-H
__device__ float  g_zf [16*256*64*64];    // filtered image, channel-major
__device__ float  g_c3 [16*256*64*64];    // conv3+bn+silu output

// ---------------- tiny utility kernels ----------------
__global__ void zero_kernel(float* __restrict__ p) {
    p[(size_t)blockIdx.x * 256 + threadIdx.x] = 0.f;
}

// unfold as 32x32 smem transpose: x[b,c,s] -> u[b,j,l,c]
__global__ void unfold_kernel(const float* __restrict__ x, float* __restrict__ u) {
    __shared__ float tile[32][33];
    int b  = blockIdx.z;
    int c0 = blockIdx.y * 32;
    int s0 = blockIdx.x * 32;
    int tx = threadIdx.x & 31, ty = threadIdx.x >> 5;   // 256 threads
    #pragma unroll
    for (int cc = 0; cc < 4; cc++)
        tile[ty + cc * 8][tx] =
            x[(size_t)(b * 256 + c0 + ty + cc * 8) * 4096 + s0 + tx];
    __syncthreads();
    #pragma unroll
    for (int cc = 0; cc < 4; cc++) {
        int s = s0 + ty + cc * 8;
        int h = s >> 6, w = s & 63;
        int kp = (h & 3) * 4 + (w & 3);
        int j = c_BACK[kp];                   // inverse of IDX == BACK
        int l = (h >> 2) * 16 + (w >> 2);
        u[((size_t)(b * 16 + j) * 256 + l) * 256 + c0 + tx] = tile[tx][ty + cc * 8];
    }
}

__device__ __forceinline__ float4 f4add(float4 a, float4 b) {
    return make_float4(a.x + b.x, a.y + b.y, a.z + b.z, a.w + b.w);
}

// t = u[:, g*4:(g+1)*4] + acc       (float4 over c)
__global__ void group_in_kernel(const float4* __restrict__ u, const float4* __restrict__ acc,
                                float4* __restrict__ t, int g) {
    int i = blockIdx.x * 256 + threadIdx.x;   // 16*4*256*64 float4
    int c4 = i & 63;
    int l = (i >> 6) & 255;
    int p = (i >> 14) & 3;
    int b = i >> 16;
    t[i] = f4add(u[((size_t)(b * 16 + g * 4 + p) * 256 + l) * 64 + c4], acc[i]);
}

// y slot g = t; acc += t
__global__ void group_store_kernel(const float4* __restrict__ t, float4* __restrict__ y,
                                   float4* __restrict__ acc, int g) {
    int i = blockIdx.x * 256 + threadIdx.x;
    int c4 = i & 63;
    int l = (i >> 6) & 255;
    int p = (i >> 14) & 3;
    int b = i >> 16;
    float4 v = t[i];
    y[((size_t)(b * 16 + g * 4 + p) * 256 + l) * 64 + c4] = v;
    acc[i] = f4add(acc[i], v);
}

// zp[b,h,w,c] = y[b, BACK[kp], l, c]   (fold), float4 over c
__global__ void fold_kernel(const float4* __restrict__ y, float4* __restrict__ zp) {
    int i = blockIdx.x * 256 + threadIdx.x;   // 16*64*64*64 float4
    int c4 = i & 63;
    int wp = (i >> 6) & 63;
    int hp = (i >> 12) & 63;
    int b  = i >> 18;
    int ky = hp & 3, ph = hp >> 2;
    int kx = wp & 3, pw = wp >> 2;
    int j = c_BACK[ky * 4 + kx];
    int l = ph * 16 + pw;
    zp[i] = y[((size_t)(b * 16 + j) * 256 + l) * 64 + c4];
}

// ---------------- layernorm: 4 rows per block, float4 ----------------
__global__ void ln_kernel(const float* __restrict__ in, const float* __restrict__ gw,
                          const float* __restrict__ bw, float* __restrict__ out) {
    int tid = threadIdx.x;
    int r = tid >> 6;                 // 0..3
    int t = tid & 63;
    size_t row = (size_t)blockIdx.x * 4 + r;
    float4 v = *(const float4*)(in + row * 256 + t * 4);
    float s  = v.x + v.y + v.z + v.w;
    float sq = v.x * v.x + v.y * v.y + v.z * v.z + v.w * v.w;
    #pragma unroll
    for (int o = 16; o; o >>= 1) {
        s  += __shfl_xor_sync(0xffffffffu, s, o);
        sq += __shfl_xor_sync(0xffffffffu, sq, o);
    }
    __shared__ float ss[8], sqs[8];
    int warp = tid >> 5;
    if ((tid & 31) == 0) { ss[warp] = s; sqs[warp] = sq; }
    __syncthreads();
    s  = ss[r * 2] + ss[r * 2 + 1];
    sq = sqs[r * 2] + sqs[r * 2 + 1];
    float mean = s * (1.f / 256.f);
    float var  = sq * (1.f / 256.f) - mean * mean;
    float rstd = rsqrtf(var + EPSF);
    float4 g4 = *(const float4*)(gw + t * 4);
    float4 b4 = *(const float4*)(bw + t * 4);
    float4 o4;
    o4.x = (v.x - mean) * rstd * g4.x + b4.x;
    o4.y = (v.y - mean) * rstd * g4.y + b4.y;
    o4.z = (v.z - mean) * rstd * g4.z + b4.z;
    o4.w = (v.w - mean) * rstd * g4.w + b4.w;
    *(float4*)(out + row * 256 + t * 4) = o4;
}

// ---------------- tf32 tensor-core GEMM, ping-pong smem ----------------
// BM=128, BN=64, BK=16, 256 threads = 8 warps (4x2), warp tile 32x32.
#define BM 128
#define BN 64
#define BK 16
__global__ void gemm_tf32_kernel(const float* __restrict__ A, const float* __restrict__ B,
                                 float* __restrict__ C,
                                 const float* __restrict__ bias, const float* __restrict__ resid,
                                 const float* __restrict__ bnG, const float* __restrict__ bnB,
                                 const float* __restrict__ bnM, const float* __restrict__ bnV,
                                 int M, int N, int K, int lda, int ldb, int ldc,
                                 int act, long long sA, long long sB, long long sC) {
    __shared__ float As[2][BM][BK + 4];
    __shared__ float Bs[2][BK][BN + 4];
    __shared__ float epi[8][16][20];
    int z = blockIdx.z;
    A += z * sA; B += z * sB; C += z * sC;
    const float* R = resid ? resid + z * sC : (const float*)0;
    int bm = blockIdx.y * BM, bn = blockIdx.x * BN;
    int tid = threadIdx.x, warp = tid >> 5, lane = tid & 31;
    int wr = warp >> 1, wc = warp & 1;

    wmma::fragment<wmma::accumulator, 16, 16, 8, float> acc[2][2];
    #pragma unroll
    for (int r = 0; r < 2; r++)
        #pragma unroll
        for (int c = 0; c < 2; c++)
            wmma::fill_fragment(acc[r][c], 0.f);

    int aRow = tid >> 2, aCol = (tid & 3) * 4;
    int bRow = tid >> 4, bCol = (tid & 15) * 4;

    float4 pa0 = *(const float4*)(A + (size_t)(bm + aRow) * lda + aCol);
    float4 pa1 = *(const float4*)(A + (size_t)(bm + aRow + 64) * lda + aCol);
    float4 pb = make_float4(0.f, 0.f, 0.f, 0.f);
    if (bn + bCol < N) pb = *(const float4*)(B + (size_t)bRow * ldb + bn + bCol);
    *(float4*)&As[0][aRow][aCol]      = pa0;
    *(float4*)&As[0][aRow + 64][aCol] = pa1;
    *(float4*)&Bs[0][bRow][bCol]      = pb;
    __syncthreads();

    int cur = 0;
    for (int k0 = 0; k0 < K; k0 += BK) {
        int kn = k0 + BK;
        if (kn < K) {
            pa0 = *(const float4*)(A + (size_t)(bm + aRow) * lda + kn + aCol);
            pa1 = *(const float4*)(A + (size_t)(bm + aRow + 64) * lda + kn + aCol);
            pb = make_float4(0.f, 0.f, 0.f, 0.f);
            if (bn + bCol < N) pb = *(const float4*)(B + (size_t)(kn + bRow) * ldb + bn + bCol);
        }
        #pragma unroll
        for (int ks = 0; ks < BK; ks += 8) {
            wmma::fragment<wmma::matrix_a, 16, 16, 8, wmma::precision::tf32, wmma::row_major> af[2];
            wmma::fragment<wmma::matrix_b, 16, 16, 8, wmma::precision::tf32, wmma::row_major> bf[2];
            #pragma unroll
            for (int r = 0; r < 2; r++) {
                wmma::load_matrix_sync(af[r], &As[cur][wr * 32 + r * 16][ks], BK + 4);
                #pragma unroll
                for (int e = 0; e < af[r].num_elements; e++)
                    af[r].x[e] = wmma::__float_to_tf32(af[r].x[e]);
            }
            #pragma unroll
            for (int c = 0; c < 2; c++) {
                wmma::load_matrix_sync(bf[c], &Bs[cur][ks][wc * 32 + c * 16], BN + 4);
                #pragma unroll
                for (int e = 0; e < bf[c].num_elements; e++)
                    bf[c].x[e] = wmma::__float_to_tf32(bf[c].x[e]);
            }
            #pragma unroll
            for (int r = 0; r < 2; r++)
                #pragma unroll
                for (int c = 0; c < 2; c++)
                    wmma::mma_sync(acc[r][c], af[r], bf[c], acc[r][c]);
        }
        if (kn < K) {
            *(float4*)&As[cur ^ 1][aRow][aCol]      = pa0;
            *(float4*)&As[cur ^ 1][aRow + 64][aCol] = pa1;
            *(float4*)&Bs[cur ^ 1][bRow][bCol]      = pb;
        }
        __syncthreads();
        cur ^= 1;
    }

    // epilogue
    #pragma unroll
    for (int r = 0; r < 2; r++)
        #pragma unroll
        for (int c = 0; c < 2; c++) {
            wmma::store_matrix_sync(&epi[warp][0][0], acc[r][c], 20, wmma::mem_row_major);
            __syncwarp();
            int rowBase = bm + wr * 32 + r * 16;
            int colBase = bn + wc * 32 + c * 16;
            #pragma unroll
            for (int k = 0; k < 8; k++) {
                int idx = k * 32 + lane;
                int rr = idx >> 4, cc = idx & 15;
                int row = rowBase + rr, col = colBase + cc;
                float v = epi[warp][rr][cc];
                if (R)    v += R[(size_t)row * ldc + col];
                if (bias && col < N) v += bias[col];
                if (bnG) {
                    float s_ = bnG[row] * rsqrtf(bnV[row] + EPSF);
                    v = v * s_ + (bnB[row] - bnM[row] * s_);
                }
                if (act) v = v / (1.f + __expf(-v));
                C[(size_t)row * ldc + col] = v;
            }
            __syncwarp();
        }
}

// ---------------- conv4 implicit GEMM: 3x3 256->256 + BN + SiLU ----------------
// M=256 (oc), N=4096 (p), K=2304 (ic*9+kk). B built on the fly from image.
__global__ void conv4_gemm_kernel(const float* __restrict__ W, const float* __restrict__ img,
                                  float* __restrict__ C,
                                  const float* __restrict__ bnG, const float* __restrict__ bnB,
                                  const float* __restrict__ bnM, const float* __restrict__ bnV) {
    __shared__ float As[2][BM][BK + 4];
    __shared__ float Bs[2][BK][BN + 4];
    __shared__ float epi[8][16][20];
    const int K = 2304;
    int z = blockIdx.z;
    img += (size_t)z * 256 * 4096;
    C   += (size_t)z * 256 * 4096;
    int bm = blockIdx.y * BM, bn = blockIdx.x * BN;
    int tid = threadIdx.x, warp = tid >> 5, lane = tid & 31;
    int wr = warp >> 1, wc = warp & 1;

    wmma::fragment<wmma::accumulator, 16, 16, 8, float> acc[2][2];
    #pragma unroll
    for (int r = 0; r < 2; r++)
        #pragma unroll
        for (int c = 0; c < 2; c++)
            wmma::fill_fragment(acc[r][c], 0.f);

    int aRow = tid >> 2, aCol = (tid & 3) * 4;
    int bRow = tid >> 4, bCol = (tid & 15) * 4;
    int n = bn + bCol;
    int y = n >> 6, xx = n & 63;

    float pb[4];
    float4 pa0, pa1;
    {   // initial loads (k = bRow)
        pa0 = *(const float4*)(W + (size_t)(bm + aRow) * 2304 + aCol);
        pa1 = *(const float4*)(W + (size_t)(bm + aRow + 64) * 2304 + aCol);
        int k = bRow;
        int ic = k / 9, kk = k - ic * 9;
        int ky = kk / 3, kx = kk - ky * 3;
        int gy = y + ky - 1;
        const float* bp = img + ((size_t)ic * 64 + gy) * 64;
        bool rok = (unsigned)gy < 64u;
        #pragma unroll
        for (int e = 0; e < 4; e++) {
            int gx = xx + e + kx - 1;
            pb[e] = (rok && (unsigned)gx < 64u) ? bp[gx] : 0.f;
        }
    }
    *(float4*)&As[0][aRow][aCol]      = pa0;
    *(float4*)&As[0][aRow + 64][aCol] = pa1;
    Bs[0][bRow][bCol + 0] = pb[0];
    Bs[0][bRow][bCol + 1] = pb[1];
    Bs[0][bRow][bCol + 2] = pb[2];
    Bs[0][bRow][bCol + 3] = pb[3];
    __syncthreads();

    int cur = 0;
    for (int k0 = 0; k0 < K; k0 += BK) {
        int kn = k0 + BK;
        if (kn < K) {
            pa0 = *(const float4*)(W + (size_t)(bm + aRow) * 2304 + kn + aCol);
            pa1 = *(const float4*)(W + (size_t)(bm + aRow + 64) * 2304 + kn + aCol);
            int k = kn + bRow;
            int ic = k / 9, kk = k - ic * 9;
            int ky = kk / 3, kx = kk - ky * 3;
            int gy = y + ky - 1;
            const float* bp = img + ((size_t)ic * 64 + gy) * 64;
            bool rok = (unsigned)gy < 64u;
            #pragma unroll
            for (int e = 0; e < 4; e++) {
                int gx = xx + e + kx - 1;
                pb[e] = (rok && (unsigned)gx < 64u) ? bp[gx] : 0.f;
            }
        }
        #pragma unroll
        for (int ks = 0; ks < BK; ks += 8) {
            wmma::fragment<wmma::matrix_a, 16, 16, 8, wmma::precision::tf32, wmma::row_major> af[2];
            wmma::fragment<wmma::matrix_b, 16, 16, 8, wmma::precision::tf32, wmma::row_major> bf[2];
            #pragma unroll
            for (int r = 0; r < 2; r++) {
                wmma::load_matrix_sync(af[r], &As[cur][wr * 32 + r * 16][ks], BK + 4);
                #pragma unroll
                for (int e = 0; e < af[r].num_elements; e++)
                    af[r].x[e] = wmma::__float_to_tf32(af[r].x[e]);
            }
            #pragma unroll
            for (int c = 0; c < 2; c++) {
                wmma::load_matrix_sync(bf[c], &Bs[cur][ks][wc * 32 + c * 16], BN + 4);
                #pragma unroll
                for (int e = 0; e < bf[c].num_elements; e++)
                    bf[c].x[e] = wmma::__float_to_tf32(bf[c].x[e]);
            }
            #pragma unroll
            for (int r = 0; r < 2; r++)
                #pragma unroll
                for (int c = 0; c < 2; c++)
                    wmma::mma_sync(acc[r][c], af[r], bf[c], acc[r][c]);
        }
        if (kn < K) {
            *(float4*)&As[cur ^ 1][aRow][aCol]      = pa0;
            *(float4*)&As[cur ^ 1][aRow + 64][aCol] = pa1;
            Bs[cur ^ 1][bRow][bCol + 0] = pb[0];
            Bs[cur ^ 1][bRow][bCol + 1] = pb[1];
            Bs[cur ^ 1][bRow][bCol + 2] = pb[2];
            Bs[cur ^ 1][bRow][bCol + 3] = pb[3];
        }
        __syncthreads();
        cur ^= 1;
    }

    #pragma unroll
    for (int r = 0; r < 2; r++)
        #pragma unroll
        for (int c = 0; c < 2; c++) {
            wmma::store_matrix_sync(&epi[warp][0][0], acc[r][c], 20, wmma::mem_row_major);
            __syncwarp();
            int rowBase = bm + wr * 32 + r * 16;
            int colBase = bn + wc * 32 + c * 16;
            #pragma unroll
            for (int k = 0; k < 8; k++) {
                int idx = k * 32 + lane;
                int rr = idx >> 4, cc = idx & 15;
                int row = rowBase + rr, col = colBase + cc;
                float v = epi[warp][rr][cc];
                float s_ = bnG[row] * rsqrtf(bnV[row] + EPSF);
                v = v * s_ + (bnB[row] - bnM[row] * s_);
                v = v / (1.f + __expf(-v));
                C[(size_t)row * 4096 + col] = v;
            }
            __syncwarp();
        }
}

// ---------------- attention: block per (b*4+p, head), thread per query ----------------
__global__ void attn_kernel(const float* __restrict__ qkv, float* __restrict__ att) {
    int bp = blockIdx.x;
    int h  = blockIdx.y;
    int n  = threadIdx.x;
    __shared__ float ks[256 * 8];
    __shared__ float vs[256 * 8];
    int row = bp * 256 + n;
    const float* base = qkv + (size_t)row * 128 + h * 8;
    float4 q0 = *(const float4*)(base);
    float4 q1 = *(const float4*)(base + 4);
    *(float4*)&ks[n * 8]     = *(const float4*)(base + 32);
    *(float4*)&ks[n * 8 + 4] = *(const float4*)(base + 36);
    *(float4*)&vs[n * 8]     = *(const float4*)(base + 64);
    *(float4*)&vs[n * 8 + 4] = *(const float4*)(base + 68);
    __syncthreads();
    float q[8] = {q0.x, q0.y, q0.z, q0.w, q1.x, q1.y, q1.z, q1.w};
    float mx = -1e30f, ssum = 0.f;
    float acc[8] = {};
    for (int m = 0; m < 256; m++) {
        float4 ka = *(const float4*)&ks[m * 8];
        float4 kb = *(const float4*)&ks[m * 8 + 4];
        float d = q[0]*ka.x + q[1]*ka.y + q[2]*ka.z + q[3]*ka.w
                + q[4]*kb.x + q[5]*kb.y + q[6]*kb.z + q[7]*kb.w;
        d *= 0.35355339059327373f;
        float w;
        if (d > mx) {
            float corr = __expf(mx - d);
            ssum *= corr;
            #pragma unroll
            for (int j = 0; j < 8; j++) acc[j] *= corr;
            mx = d;
            w = 1.f;
        } else {
            w = __expf(d - mx);
        }
        ssum += w;
        float4 va = *(const float4*)&vs[m * 8];
        float4 vb = *(const float4*)&vs[m * 8 + 4];
        acc[0] += w * va.x; acc[1] += w * va.y; acc[2] += w * va.z; acc[3] += w * va.w;
        acc[4] += w * vb.x; acc[5] += w * vb.y; acc[6] += w * vb.z; acc[7] += w * vb.w;
    }
    float inv = 1.f / ssum;
    float* o = att + (size_t)row * 32 + h * 8;
    *(float4*)(o)     = make_float4(acc[0]*inv, acc[1]*inv, acc[2]*inv, acc[3]*inv);
    *(float4*)(o + 4) = make_float4(acc[4]*inv, acc[5]*inv, acc[6]*inv, acc[7]*inv);
}

// ---------------- FFT stage 1: rfft along W, smem-tiled ----------------
// block = (chalf, h, b); threads 256; c-tile = 128.
__global__ void fft1_kernel(const float* __restrict__ zp, float2* __restrict__ f1) {
    __shared__ float sX[64][128];
    __shared__ float2 tw[64];
    int c0 = blockIdx.x * 128;
    int h = blockIdx.y, b = blockIdx.z;
    int tid = threadIdx.x;
    if (tid < 64) {
        float sn, cs; sincosf(tid * PI_OVER_32, &sn, &cs);
        tw[tid] = make_float2(cs, sn);
    }
    const float* src = zp + ((size_t)(b * 64 + h) * 64) * 256 + c0;
    #pragma unroll
    for (int i = 0; i < 8; i++) {
        int idx = tid + i * 256;          // float4 index within 64x32
        int x = idx >> 5, cc = (idx & 31) * 4;
        *(float4*)&sX[x][cc] = *(const float4*)(src + (size_t)x * 256 + cc);
    }
    __syncthreads();
    int c = tid & 127, wg = tid >> 7;     // wg 0: w=0,2,..,32 (17); wg 1: w=1,3,..,31 (16)
    int nw = 17 - wg;
    float re[17], im[17];
    #pragma unroll
    for (int j = 0; j < 17; j++) { re[j] = 0.f; im[j] = 0.f; }
    for (int x = 0; x < 64; x++) {
        float g = sX[x][c];
        int m = (wg * x) & 63;
        int step = (2 * x) & 63;
        #pragma unroll
        for (int j = 0; j < 17; j++) {
            if (j < nw) {
                float2 t = tw[m];
                re[j] += g * t.x;
                im[j] -= g * t.y;
                m = (m + step) & 63;
            }
        }
    }
    float2* dst = f1 + ((size_t)(b * 64 + h) * 33) * 256 + c0 + c;
    #pragma unroll
    for (int j = 0; j < 17; j++) {
        if (j < nw) {
            int w = wg + 2 * j;
            dst[(size_t)w * 256] = make_float2(re[j] * 0.125f, im[j] * 0.125f);
        }
    }
}

// ---------------- FFT stages 2+3 fused: fwd-DFT over H, weight, inv-DFT over H ----
// block = (w, ctile(32), b); threads 256.
__global__ void fft23_kernel(const float2* __restrict__ f1, const float2* __restrict__ fw,
                             float2* __restrict__ out) {
    __shared__ float2 sA[64][32];
    __shared__ float2 sB[64][32];
    __shared__ float2 tw[64];
    int w = blockIdx.x;
    int c0 = blockIdx.y * 32;
    int b = blockIdx.z;
    int tid = threadIdx.x;
    if (tid < 64) {
        float sn, cs; sincosf(tid * PI_OVER_32, &sn, &cs);
        tw[tid] = make_float2(cs, sn);
    }
    #pragma unroll
    for (int i = 0; i < 8; i++) {
        int idx = tid + i * 256;
        int hh = idx >> 5, cc = idx & 31;
        sA[hh][cc] = f1[((size_t)(b * 64 + hh) * 33 + w) * 256 + c0 + cc];
    }
    __syncthreads();

    int c = tid & 31;
    int kb = tid >> 5;            // 8 k per thread: k = kb*8 + j
    {
        float re[8] = {}, im[8] = {};
        for (int hh = 0; hh < 64; hh++) {
            float2 g = sA[hh][c];
            int m = ((kb * 8) * hh) & 63;
            #pragma unroll
            for (int j = 0; j < 8; j++) {
                float2 t = tw[m];
                re[j] += g.x * t.x + g.y * t.y;
                im[j] += g.y * t.x - g.x * t.y;
                m = (m + hh) & 63;
            }
        }
        #pragma unroll
        for (int j = 0; j < 8; j++) {
            int k = kb * 8 + j;
            float2 wc = fw[((size_t)k * 33 + w) * 256 + c0 + c];
            float rr = re[j] * 0.125f, ii = im[j] * 0.125f;
            sB[k][c] = make_float2(rr * wc.x - ii * wc.y, rr * wc.y + ii * wc.x);
        }
    }
    __syncthreads();

    int hb = tid >> 5;            // 8 h per thread: h = hb*8 + j
    {
        float re[8] = {}, im[8] = {};
        for (int k = 0; k < 64; k++) {
            float2 g = sB[k][c];
            int m = (k * (hb * 8)) & 63;
            #pragma unroll
            for (int j = 0; j < 8; j++) {
                float2 t = tw[m];
                re[j] += g.x * t.x - g.y * t.y;
                im[j] += g.x * t.y + g.y * t.x;
                m = (m + k) & 63;
            }
        }
        #pragma unroll
        for (int j = 0; j < 8; j++) {
            int hh = hb * 8 + j;
            out[((size_t)(b * 64 + hh) * 33 + w) * 256 + c0 + c] =
                make_float2(re[j] * 0.125f, im[j] * 0.125f);
        }
    }
}

// ---------------- FFT stage 4: irfft along W -> real channel-major ----------------
// block = (cq, h, b); threads 256; c-tile = 64.
__global__ void fft4_kernel(const float2* __restrict__ A, float* __restrict__ zf) {
    __shared__ float2 sA[33][64];
    __shared__ float2 tw[64];
    int c0 = blockIdx.x * 64;
    int h = blockIdx.y, b = blockIdx.z;
    int tid = threadIdx.x;
    if (tid < 64) {
        float sn, cs; sincosf(tid * PI_OVER_32, &sn, &cs);
        tw[tid] = make_float2(cs, sn);
    }
    const float2* src = A + ((size_t)(b * 64 + h) * 33) * 256 + c0;
    for (int idx = tid; idx < 33 * 64; idx += 256) {
        int w = idx >> 6, cc = idx & 63;
        sA[w][cc] = src[(size_t)w * 256 + cc];
    }
    __syncthreads();
    int c = tid >> 2;             // 0..63
    int x0 = (tid & 3) * 16;      // 16 consecutive x per thread
    float r[16];
    {
        float2 a0 = sA[0][c], a32 = sA[32][c];
        #pragma unroll
        for (int j = 0; j < 16; j++)
            r[j] = a0.x + (((x0 + j) & 1) ? -a32.x : a32.x);
    }
    for (int w = 1; w < 32; w++) {
        float2 a = sA[w][c];
        int m = (w * x0) & 63;
        #pragma unroll
        for (int j = 0; j < 16; j++) {
            float2 t = tw[m];
            r[j] += 2.f * (a.x * t.x - a.y * t.y);
            m = (m + w) & 63;
        }
    }
    float* dst = zf + ((size_t)(b * 256 + c0 + c) * 64 + h) * 64 + x0;
    #pragma unroll
    for (int q = 0; q < 4; q++) {
        float4 v = make_float4(r[q*4] * 0.125f, r[q*4+1] * 0.125f,
                               r[q*4+2] * 0.125f, r[q*4+3] * 0.125f);
        *(float4*)(dst + q * 4) = v;
    }
}

// ---------------- host launch ----------------
extern "C" void kernel_launch(void* const* d_in, const int* in_sizes, int n_in,
                              void* d_out, int out_size) {
    const float* x      = (const float*)d_in[0];
    const float* ln1_g  = (const float*)d_in[1];
    const float* ln1_b  = (const float*)d_in[2];
    const float* wqkv   = (const float*)d_in[3];
    const float* wout   = (const float*)d_in[4];
    const float* bout   = (const float*)d_in[5];
    const float* ln2_g  = (const float*)d_in[6];
    const float* ln2_b  = (const float*)d_in[7];
    const float* w1     = (const float*)d_in[8];
    const float* b1     = (const float*)d_in[9];
    const float* w2     = (const float*)d_in[10];
    const float* b2     = (const float*)d_in[11];
    const float* fft_w  = (const float*)d_in[12];
    const float* conv3w = (const float*)d_in[13];
    const float* bn3_g  = (const float*)d_in[14];
    const float* bn3_b  = (const float*)d_in[15];
    const float* bn3_m  = (const float*)d_in[16];
    const float* bn3_v  = (const float*)d_in[17];
    const float* conv4w = (const float*)d_in[18];
    const float* bn4_g  = (const float*)d_in[19];
    const float* bn4_b  = (const float*)d_in[20];
    const float* bn4_m  = (const float*)d_in[21];
    const float* bn4_v  = (const float*)d_in[22];
    float* outp = (float*)d_out;

    float *u, *y, *ac, *t, *lnb, *qk, *at, *mlp, *zp, *zf, *c3;
    float2 *f1, *f2;
    cudaGetSymbolAddress((void**)&u,   g_u);
    cudaGetSymbolAddress((void**)&y,   g_y);
    cudaGetSymbolAddress((void**)&ac,  g_acc);
    cudaGetSymbolAddress((void**)&t,   g_t);
    cudaGetSymbolAddress((void**)&lnb, g_ln);
    cudaGetSymbolAddress((void**)&qk,  g_qkv);
    cudaGetSymbolAddress((void**)&at,  g_att);
    cudaGetSymbolAddress((void**)&mlp, g_mlp);
    cudaGetSymbolAddress((void**)&zp,  g_zp);
    cudaGetSymbolAddress((void**)&f1,  g_f1);
    cudaGetSymbolAddress((void**)&f2,  g_f2);
    cudaGetSymbolAddress((void**)&zf,  g_zf);
    cudaGetSymbolAddress((void**)&c3,  g_c3);

    const float* NUL = (const float*)0;

    zero_kernel<<<16384, 256>>>(ac);
    unfold_kernel<<<dim3(128, 8, 16), 256>>>(x, u);

    for (int g = 0; g < 4; g++) {
        group_in_kernel<<<4096, 256>>>((const float4*)u, (const float4*)ac, (float4*)t, g);
        for (int i = 0; i < 2; i++) {
            // --- attention block ---
            ln_kernel<<<4096, 256>>>(t, ln1_g + i * 256, ln1_b + i * 256, lnb);
            gemm_tf32_kernel<<<dim3(2, 128, 1), 256>>>(lnb, wqkv + i * 256 * 96, qk,
                NUL, NUL, NUL, NUL, NUL, NUL,
                16384, 96, 256, 256, 96, 128, 0, 0, 0, 0);
            attn_kernel<<<dim3(64, 4), 256>>>(qk, at);
            gemm_tf32_kernel<<<dim3(4, 128, 1), 256>>>(at, wout + i * 32 * 256, t,
                bout + i * 256, t, NUL, NUL, NUL, NUL,
                16384, 256, 32, 32, 256, 256, 0, 0, 0, 0);
            // --- MLP block ---
            ln_kernel<<<4096, 256>>>(t, ln2_g + i * 256, ln2_b + i * 256, lnb);
            gemm_tf32_kernel<<<dim3(8, 128, 1), 256>>>(lnb, w1 + i * 256 * 512, mlp,
                b1 + i * 512, NUL, NUL, NUL, NUL, NUL,
                16384, 512, 256, 256, 512, 512, 1, 0, 0, 0);
            gemm_tf32_kernel<<<dim3(4, 128, 1), 256>>>(mlp, w2 + i * 512 * 256, t,
                b2 + i * 256, t, NUL, NUL, NUL, NUL,
                16384, 256, 512, 512, 256, 256, 0, 0, 0, 0);
        }
        group_store_kernel<<<4096, 256>>>((const float4*)t, (float4*)y, (float4*)ac, g);
    }

    fold_kernel<<<16384, 256>>>((const float4*)y, (float4*)zp);

    fft1_kernel<<<dim3(2, 64, 16), 256>>>(zp, f1);
    fft23_kernel<<<dim3(33, 8, 16), 256>>>(f1, (const float2*)fft_w, f2);
    fft4_kernel<<<dim3(4, 64, 16), 256>>>(f2, zf);

    // conv3 (1x1, 512->256) as two GEMM passes over concat([z, x]) + BN + SiLU
    gemm_tf32_kernel<<<dim3(64, 2, 16), 256>>>(conv3w, zf, c3,
        NUL, NUL, NUL, NUL, NUL, NUL,
        256, 4096, 256, 512, 4096, 4096, 0, 0, 256 * 4096, 256 * 4096);
    gemm_tf32_kernel<<<dim3(64, 2, 16), 256>>>(conv3w + 256, x, c3,
        NUL, c3, bn3_g, bn3_b, bn3_m, bn3_v,
        256, 4096, 256, 512, 4096, 4096, 1, 0, 256 * 4096, 256 * 4096);

    // conv4 (3x3, 256->256) implicit GEMM + BN + SiLU
    conv4_gemm_kernel<<<dim3(64, 2, 16), 256>>>(conv4w, c3, outp,
                                                bn4_g, bn4_b, bn4_m, bn4_v);
}

// round 7
// speedup vs baseline: 1.4781x; 1.1926x over previous
#include <cuda_runtime.h>
#include <mma.h>
#include <math.h>

using namespace nvcuda;

#define EPSF 1e-5f
#define PI_OVER_32 0.09817477042468103f

// ---------------- constant permutations ----------------
__constant__ int c_IDX[16]  = {0,7,10,13,1,4,11,14,2,5,8,15,3,6,9,12};
__constant__ int c_BACK[16] = {0,4,8,12,5,9,13,1,10,14,2,6,15,3,7,11};

// ---------------- device scratch (no allocs allowed) ----------------
__device__ float  g_u  [16*16*256*256];
__device__ float  g_y  [16*16*256*256];
__device__ float  g_acc[16*4*256*256];
__device__ float  g_t  [16*4*256*256];
__device__ float  g_ln [16*4*256*256];
__device__ float  g_qkv[16*4*256*128];    // ld=128 (cols 96..127 pad)
__device__ float  g_att[16*4*256*32];
__device__ float  g_mlp[16*4*256*512];
__device__ float  g_zp [16*64*64*256];
__device__ float2 g_f1 [16*64*33*256];
__device__ float2 g_f2 [16*64*33*256];
__device__ float  g_zf [16*256*64*64];
__device__ float  g_c3 [16*256*64*64];

// ---------------- tiny utility kernels ----------------
__global__ void zero_kernel(float* __restrict__ p) {
    p[(size_t)blockIdx.x * 256 + threadIdx.x] = 0.f;
}

__global__ void unfold_kernel(const float* __restrict__ x, float* __restrict__ u) {
    __shared__ float tile[32][33];
    int b  = blockIdx.z;
    int c0 = blockIdx.y * 32;
    int s0 = blockIdx.x * 32;
    int tx = threadIdx.x & 31, ty = threadIdx.x >> 5;
    #pragma unroll
    for (int cc = 0; cc < 4; cc++)
        tile[ty + cc * 8][tx] =
            x[(size_t)(b * 256 + c0 + ty + cc * 8) * 4096 + s0 + tx];
    __syncthreads();
    #pragma unroll
    for (int cc = 0; cc < 4; cc++) {
        int s = s0 + ty + cc * 8;
        int h = s >> 6, w = s & 63;
        int kp = (h & 3) * 4 + (w & 3);
        int j = c_BACK[kp];
        int l = (h >> 2) * 16 + (w >> 2);
        u[((size_t)(b * 16 + j) * 256 + l) * 256 + c0 + tx] = tile[tx][ty + cc * 8];
    }
}

__device__ __forceinline__ float4 f4add(float4 a, float4 b) {
    return make_float4(a.x + b.x, a.y + b.y, a.z + b.z, a.w + b.w);
}

__global__ void group_in_kernel(const float4* __restrict__ u, const float4* __restrict__ acc,
                                float4* __restrict__ t, int g) {
    int i = blockIdx.x * 256 + threadIdx.x;
    int c4 = i & 63;
    int l = (i >> 6) & 255;
    int p = (i >> 14) & 3;
    int b = i >> 16;
    t[i] = f4add(u[((size_t)(b * 16 + g * 4 + p) * 256 + l) * 64 + c4], acc[i]);
}

__global__ void group_store_kernel(const float4* __restrict__ t, float4* __restrict__ y,
                                   float4* __restrict__ acc, int g) {
    int i = blockIdx.x * 256 + threadIdx.x;
    int c4 = i & 63;
    int l = (i >> 6) & 255;
    int p = (i >> 14) & 3;
    int b = i >> 16;
    float4 v = t[i];
    y[((size_t)(b * 16 + g * 4 + p) * 256 + l) * 64 + c4] = v;
    acc[i] = f4add(acc[i], v);
}

__global__ void fold_kernel(const float4* __restrict__ y, float4* __restrict__ zp) {
    int i = blockIdx.x * 256 + threadIdx.x;
    int c4 = i & 63;
    int wp = (i >> 6) & 63;
    int hp = (i >> 12) & 63;
    int b  = i >> 18;
    int ky = hp & 3, ph = hp >> 2;
    int kx = wp & 3, pw = wp >> 2;
    int j = c_BACK[ky * 4 + kx];
    int l = ph * 16 + pw;
    zp[i] = y[((size_t)(b * 16 + j) * 256 + l) * 64 + c4];
}

// ---------------- layernorm: 4 rows per block, float4 ----------------
__global__ void ln_kernel(const float* __restrict__ in, const float* __restrict__ gw,
                          const float* __restrict__ bw, float* __restrict__ out) {
    int tid = threadIdx.x;
    int r = tid >> 6;
    int t = tid & 63;
    size_t row = (size_t)blockIdx.x * 4 + r;
    float4 v = *(const float4*)(in + row * 256 + t * 4);
    float s  = v.x + v.y + v.z + v.w;
    float sq = v.x * v.x + v.y * v.y + v.z * v.z + v.w * v.w;
    #pragma unroll
    for (int o = 16; o; o >>= 1) {
        s  += __shfl_xor_sync(0xffffffffu, s, o);
        sq += __shfl_xor_sync(0xffffffffu, sq, o);
    }
    __shared__ float ss[8], sqs[8];
    int warp = tid >> 5;
    if ((tid & 31) == 0) { ss[warp] = s; sqs[warp] = sq; }
    __syncthreads();
    s  = ss[r * 2] + ss[r * 2 + 1];
    sq = sqs[r * 2] + sqs[r * 2 + 1];
    float mean = s * (1.f / 256.f);
    float var  = sq * (1.f / 256.f) - mean * mean;
    float rstd = rsqrtf(var + EPSF);
    float4 g4 = *(const float4*)(gw + t * 4);
    float4 b4 = *(const float4*)(bw + t * 4);
    float4 o4;
    o4.x = (v.x - mean) * rstd * g4.x + b4.x;
    o4.y = (v.y - mean) * rstd * g4.y + b4.y;
    o4.z = (v.z - mean) * rstd * g4.z + b4.z;
    o4.w = (v.w - mean) * rstd * g4.w + b4.w;
    *(float4*)(out + row * 256 + t * 4) = o4;
}

// ---------------- tf32 GEMM: BM=128, BN=128, BK=16, warp tile 32x64 ----------------
// 256 threads = 8 warps (4x2). tf32-converted at smem store. Dual-source B (ksplit).
#define BM 128
#define BNN 128
#define BK 16

__device__ __forceinline__ float4 to_tf32_4(float4 v) {
    v.x = wmma::__float_to_tf32(v.x);
    v.y = wmma::__float_to_tf32(v.y);
    v.z = wmma::__float_to_tf32(v.z);
    v.w = wmma::__float_to_tf32(v.w);
    return v;
}

__global__ void __launch_bounds__(256)
gemm128_kernel(const float* __restrict__ A, const float* __restrict__ B,
               const float* __restrict__ B2, int ksplit,
               float* __restrict__ C,
               const float* __restrict__ bias, const float* __restrict__ resid,
               const float* __restrict__ bnG, const float* __restrict__ bnB,
               const float* __restrict__ bnM, const float* __restrict__ bnV,
               int M, int N, int K, int lda, int ldb, int ldc,
               int act, long long sA, long long sB, long long sC) {
    __shared__ float As[2][BM][BK + 4];
    __shared__ float Bs[2][BK][BNN + 4];
    __shared__ float epi[8][16][20];
    int z = blockIdx.z;
    A += z * sA; B += z * sB; if (B2) B2 += z * sB;
    C += z * sC;
    const float* R = resid ? resid + z * sC : (const float*)0;
    int bm = blockIdx.y * BM, bn = blockIdx.x * BNN;
    int tid = threadIdx.x, warp = tid >> 5, lane = tid & 31;
    int wr = warp >> 1, wc = warp & 1;

    wmma::fragment<wmma::accumulator, 16, 16, 8, float> acc[2][4];
    #pragma unroll
    for (int r = 0; r < 2; r++)
        #pragma unroll
        for (int c = 0; c < 4; c++)
            wmma::fill_fragment(acc[r][c], 0.f);

    int aRow = tid >> 2, aCol = (tid & 3) * 4;
    int bRow = tid >> 4, bCol = (tid & 15) * 4;
    int cB0 = bn + bCol, cB1 = cB0 + 64;

    float4 pa0, pa1, pb0, pb1;
    const float4 f4z = make_float4(0.f, 0.f, 0.f, 0.f);
    {
        pa0 = *(const float4*)(A + (size_t)(bm + aRow) * lda + aCol);
        pa1 = *(const float4*)(A + (size_t)(bm + aRow + 64) * lda + aCol);
        const float* q = (bRow < ksplit) ? B + (size_t)bRow * ldb
                                         : B2 + (size_t)(bRow - ksplit) * ldb;
        pb0 = (cB0 < N) ? *(const float4*)(q + cB0) : f4z;
        pb1 = (cB1 < N) ? *(const float4*)(q + cB1) : f4z;
    }
    *(float4*)&As[0][aRow][aCol]      = to_tf32_4(pa0);
    *(float4*)&As[0][aRow + 64][aCol] = to_tf32_4(pa1);
    *(float4*)&Bs[0][bRow][bCol]      = to_tf32_4(pb0);
    *(float4*)&Bs[0][bRow][bCol + 64] = to_tf32_4(pb1);
    __syncthreads();

    int cur = 0;
    for (int k0 = 0; k0 < K; k0 += BK) {
        int kn = k0 + BK;
        if (kn < K) {
            pa0 = *(const float4*)(A + (size_t)(bm + aRow) * lda + kn + aCol);
            pa1 = *(const float4*)(A + (size_t)(bm + aRow + 64) * lda + kn + aCol);
            int k = kn + bRow;
            const float* q = (k < ksplit) ? B + (size_t)k * ldb
                                          : B2 + (size_t)(k - ksplit) * ldb;
            pb0 = (cB0 < N) ? *(const float4*)(q + cB0) : f4z;
            pb1 = (cB1 < N) ? *(const float4*)(q + cB1) : f4z;
        }
        #pragma unroll
        for (int ks = 0; ks < BK; ks += 8) {
            wmma::fragment<wmma::matrix_a, 16, 16, 8, wmma::precision::tf32, wmma::row_major> af[2];
            wmma::fragment<wmma::matrix_b, 16, 16, 8, wmma::precision::tf32, wmma::row_major> bf[4];
            #pragma unroll
            for (int r = 0; r < 2; r++)
                wmma::load_matrix_sync(af[r], &As[cur][wr * 32 + r * 16][ks], BK + 4);
            #pragma unroll
            for (int c = 0; c < 4; c++)
                wmma::load_matrix_sync(bf[c], &Bs[cur][ks][wc * 64 + c * 16], BNN + 4);
            #pragma unroll
            for (int r = 0; r < 2; r++)
                #pragma unroll
                for (int c = 0; c < 4; c++)
                    wmma::mma_sync(acc[r][c], af[r], bf[c], acc[r][c]);
        }
        if (kn < K) {
            *(float4*)&As[cur ^ 1][aRow][aCol]      = to_tf32_4(pa0);
            *(float4*)&As[cur ^ 1][aRow + 64][aCol] = to_tf32_4(pa1);
            *(float4*)&Bs[cur ^ 1][bRow][bCol]      = to_tf32_4(pb0);
            *(float4*)&Bs[cur ^ 1][bRow][bCol + 64] = to_tf32_4(pb1);
        }
        __syncthreads();
        cur ^= 1;
    }

    // epilogue: resid -> bias -> bn-affine(row) -> silu
    #pragma unroll
    for (int r = 0; r < 2; r++)
        #pragma unroll
        for (int c = 0; c < 4; c++) {
            wmma::store_matrix_sync(&epi[warp][0][0], acc[r][c], 20, wmma::mem_row_major);
            __syncwarp();
            int rowBase = bm + wr * 32 + r * 16;
            int colBase = bn + wc * 64 + c * 16;
            #pragma unroll
            for (int k = 0; k < 8; k++) {
                int idx = k * 32 + lane;
                int rr = idx >> 4, cc = idx & 15;
                int row = rowBase + rr, col = colBase + cc;
                float v = epi[warp][rr][cc];
                if (R)    v += R[(size_t)row * ldc + col];
                if (bias && col < N) v += bias[col];
                if (bnG) {
                    float s_ = bnG[row] * rsqrtf(bnV[row] + EPSF);
                    v = v * s_ + (bnB[row] - bnM[row] * s_);
                }
                if (act) v = v / (1.f + __expf(-v));
                C[(size_t)row * ldc + col] = v;
            }
            __syncwarp();
        }
}

// ---------------- conv4 implicit GEMM, BN=128 ----------------
__global__ void __launch_bounds__(256)
conv4_gemm_kernel(const float* __restrict__ W, const float* __restrict__ img,
                  float* __restrict__ C,
                  const float* __restrict__ bnG, const float* __restrict__ bnB,
                  const float* __restrict__ bnM, const float* __restrict__ bnV) {
    __shared__ float As[2][BM][BK + 4];
    __shared__ float Bs[2][BK][BNN + 4];
    __shared__ float epi[8][16][20];
    const int K = 2304;
    int z = blockIdx.z;
    img += (size_t)z * 256 * 4096;
    C   += (size_t)z * 256 * 4096;
    int bm = blockIdx.y * BM, bn = blockIdx.x * BNN;
    int tid = threadIdx.x, warp = tid >> 5, lane = tid & 31;
    int wr = warp >> 1, wc = warp & 1;

    wmma::fragment<wmma::accumulator, 16, 16, 8, float> acc[2][4];
    #pragma unroll
    for (int r = 0; r < 2; r++)
        #pragma unroll
        for (int c = 0; c < 4; c++)
            wmma::fill_fragment(acc[r][c], 0.f);

    int aRow = tid >> 2, aCol = (tid & 3) * 4;
    int bRow = tid >> 4, bCol = (tid & 15) * 4;
    int n0 = bn + bCol, n1 = n0 + 64;
    int y0 = n0 >> 6, x0 = n0 & 63;
    int y1 = n1 >> 6, x1 = n1 & 63;

    float4 pa0, pa1;
    float pb0[4], pb1[4];

    auto loadB = [&](int k) {
        int ic = k / 9, kk = k - ic * 9;
        int ky = kk / 3, kx = kk - ky * 3;
        const float* base = img + (size_t)ic * 4096;
        int gy0 = y0 + ky - 1, gy1 = y1 + ky - 1;
        bool r0 = (unsigned)gy0 < 64u, r1 = (unsigned)gy1 < 64u;
        const float* p0 = base + gy0 * 64;
        const float* p1 = base + gy1 * 64;
        #pragma unroll
        for (int e = 0; e < 4; e++) {
            int gx0 = x0 + e + kx - 1;
            int gx1 = x1 + e + kx - 1;
            pb0[e] = (r0 && (unsigned)gx0 < 64u) ? p0[gx0] : 0.f;
            pb1[e] = (r1 && (unsigned)gx1 < 64u) ? p1[gx1] : 0.f;
        }
    };

    pa0 = *(const float4*)(W + (size_t)(bm + aRow) * 2304 + aCol);
    pa1 = *(const float4*)(W + (size_t)(bm + aRow + 64) * 2304 + aCol);
    loadB(bRow);
    *(float4*)&As[0][aRow][aCol]      = to_tf32_4(pa0);
    *(float4*)&As[0][aRow + 64][aCol] = to_tf32_4(pa1);
    #pragma unroll
    for (int e = 0; e < 4; e++) {
        Bs[0][bRow][bCol + e]      = wmma::__float_to_tf32(pb0[e]);
        Bs[0][bRow][bCol + 64 + e] = wmma::__float_to_tf32(pb1[e]);
    }
    __syncthreads();

    int cur = 0;
    for (int k0 = 0; k0 < K; k0 += BK) {
        int kn = k0 + BK;
        if (kn < K) {
            pa0 = *(const float4*)(W + (size_t)(bm + aRow) * 2304 + kn + aCol);
            pa1 = *(const float4*)(W + (size_t)(bm + aRow + 64) * 2304 + kn + aCol);
            loadB(kn + bRow);
        }
        #pragma unroll
        for (int ks = 0; ks < BK; ks += 8) {
            wmma::fragment<wmma::matrix_a, 16, 16, 8, wmma::precision::tf32, wmma::row_major> af[2];
            wmma::fragment<wmma::matrix_b, 16, 16, 8, wmma::precision::tf32, wmma::row_major> bf[4];
            #pragma unroll
            for (int r = 0; r < 2; r++)
                wmma::load_matrix_sync(af[r], &As[cur][wr * 32 + r * 16][ks], BK + 4);
            #pragma unroll
            for (int c = 0; c < 4; c++)
                wmma::load_matrix_sync(bf[c], &Bs[cur][ks][wc * 64 + c * 16], BNN + 4);
            #pragma unroll
            for (int r = 0; r < 2; r++)
                #pragma unroll
                for (int c = 0; c < 4; c++)
                    wmma::mma_sync(acc[r][c], af[r], bf[c], acc[r][c]);
        }
        if (kn < K) {
            *(float4*)&As[cur ^ 1][aRow][aCol]      = to_tf32_4(pa0);
            *(float4*)&As[cur ^ 1][aRow + 64][aCol] = to_tf32_4(pa1);
            #pragma unroll
            for (int e = 0; e < 4; e++) {
                Bs[cur ^ 1][bRow][bCol + e]      = wmma::__float_to_tf32(pb0[e]);
                Bs[cur ^ 1][bRow][bCol + 64 + e] = wmma::__float_to_tf32(pb1[e]);
            }
        }
        __syncthreads();
        cur ^= 1;
    }

    #pragma unroll
    for (int r = 0; r < 2; r++)
        #pragma unroll
        for (int c = 0; c < 4; c++) {
            wmma::store_matrix_sync(&epi[warp][0][0], acc[r][c], 20, wmma::mem_row_major);
            __syncwarp();
            int rowBase = bm + wr * 32 + r * 16;
            int colBase = bn + wc * 64 + c * 16;
            #pragma unroll
            for (int k = 0; k < 8; k++) {
                int idx = k * 32 + lane;
                int rr = idx >> 4, cc = idx & 15;
                int row = rowBase + rr, col = colBase + cc;
                float v = epi[warp][rr][cc];
                float s_ = bnG[row] * rsqrtf(bnV[row] + EPSF);
                v = v * s_ + (bnB[row] - bnM[row] * s_);
                v = v / (1.f + __expf(-v));
                C[(size_t)row * 4096 + col] = v;
            }
            __syncwarp();
        }
}

// ---------------- attention ----------------
__global__ void attn_kernel(const float* __restrict__ qkv, float* __restrict__ att) {
    int bp = blockIdx.x;
    int h  = blockIdx.y;
    int n  = threadIdx.x;
    __shared__ float ks[256 * 8];
    __shared__ float vs[256 * 8];
    int row = bp * 256 + n;
    const float* base = qkv + (size_t)row * 128 + h * 8;
    float4 q0 = *(const float4*)(base);
    float4 q1 = *(const float4*)(base + 4);
    *(float4*)&ks[n * 8]     = *(const float4*)(base + 32);
    *(float4*)&ks[n * 8 + 4] = *(const float4*)(base + 36);
    *(float4*)&vs[n * 8]     = *(const float4*)(base + 64);
    *(float4*)&vs[n * 8 + 4] = *(const float4*)(base + 68);
    __syncthreads();
    float q[8] = {q0.x, q0.y, q0.z, q0.w, q1.x, q1.y, q1.z, q1.w};
    float mx = -1e30f, ssum = 0.f;
    float acc[8] = {};
    for (int m = 0; m < 256; m++) {
        float4 ka = *(const float4*)&ks[m * 8];
        float4 kb = *(const float4*)&ks[m * 8 + 4];
        float d = q[0]*ka.x + q[1]*ka.y + q[2]*ka.z + q[3]*ka.w
                + q[4]*kb.x + q[5]*kb.y + q[6]*kb.z + q[7]*kb.w;
        d *= 0.35355339059327373f;
        float w;
        if (d > mx) {
            float corr = __expf(mx - d);
            ssum *= corr;
            #pragma unroll
            for (int j = 0; j < 8; j++) acc[j] *= corr;
            mx = d;
            w = 1.f;
        } else {
            w = __expf(d - mx);
        }
        ssum += w;
        float4 va = *(const float4*)&vs[m * 8];
        float4 vb = *(const float4*)&vs[m * 8 + 4];
        acc[0] += w * va.x; acc[1] += w * va.y; acc[2] += w * va.z; acc[3] += w * va.w;
        acc[4] += w * vb.x; acc[5] += w * vb.y; acc[6] += w * vb.z; acc[7] += w * vb.w;
    }
    float inv = 1.f / ssum;
    float* o = att + (size_t)row * 32 + h * 8;
    *(float4*)(o)     = make_float4(acc[0]*inv, acc[1]*inv, acc[2]*inv, acc[3]*inv);
    *(float4*)(o + 4) = make_float4(acc[4]*inv, acc[5]*inv, acc[6]*inv, acc[7]*inv);
}

// ---------------- FFT stage 1: rfft along W ----------------
__global__ void fft1_kernel(const float* __restrict__ zp, float2* __restrict__ f1) {
    __shared__ float sX[64][128];
    __shared__ float2 tw[64];
    int c0 = blockIdx.x * 128;
    int h = blockIdx.y, b = blockIdx.z;
    int tid = threadIdx.x;
    if (tid < 64) {
        float sn, cs; sincosf(tid * PI_OVER_32, &sn, &cs);
        tw[tid] = make_float2(cs, sn);
    }
    const float* src = zp + ((size_t)(b * 64 + h) * 64) * 256 + c0;
    #pragma unroll
    for (int i = 0; i < 8; i++) {
        int idx = tid + i * 256;
        int x = idx >> 5, cc = (idx & 31) * 4;
        *(float4*)&sX[x][cc] = *(const float4*)(src + (size_t)x * 256 + cc);
    }
    __syncthreads();
    int c = tid & 127, wg = tid >> 7;
    int nw = 17 - wg;
    float re[17], im[17];
    #pragma unroll
    for (int j = 0; j < 17; j++) { re[j] = 0.f; im[j] = 0.f; }
    for (int x = 0; x < 64; x++) {
        float g = sX[x][c];
        int m = (wg * x) & 63;
        int step = (2 * x) & 63;
        #pragma unroll
        for (int j = 0; j < 17; j++) {
            if (j < nw) {
                float2 t = tw[m];
                re[j] += g * t.x;
                im[j] -= g * t.y;
                m = (m + step) & 63;
            }
        }
    }
    float2* dst = f1 + ((size_t)(b * 64 + h) * 33) * 256 + c0 + c;
    #pragma unroll
    for (int j = 0; j < 17; j++) {
        if (j < nw) {
            int w = wg + 2 * j;
            dst[(size_t)w * 256] = make_float2(re[j] * 0.125f, im[j] * 0.125f);
        }
    }
}

// ---------------- FFT stages 2+3 fused ----------------
__global__ void fft23_kernel(const float2* __restrict__ f1, const float2* __restrict__ fw,
                             float2* __restrict__ out) {
    __shared__ float2 sA[64][32];
    __shared__ float2 sB[64][32];
    __shared__ float2 tw[64];
    int w = blockIdx.x;
    int c0 = blockIdx.y * 32;
    int b = blockIdx.z;
    int tid = threadIdx.x;
    if (tid < 64) {
        float sn, cs; sincosf(tid * PI_OVER_32, &sn, &cs);
        tw[tid] = make_float2(cs, sn);
    }
    #pragma unroll
    for (int i = 0; i < 8; i++) {
        int idx = tid + i * 256;
        int hh = idx >> 5, cc = idx & 31;
        sA[hh][cc] = f1[((size_t)(b * 64 + hh) * 33 + w) * 256 + c0 + cc];
    }
    __syncthreads();

    int c = tid & 31;
    int kb = tid >> 5;
    {
        float re[8] = {}, im[8] = {};
        for (int hh = 0; hh < 64; hh++) {
            float2 g = sA[hh][c];
            int m = ((kb * 8) * hh) & 63;
            #pragma unroll
            for (int j = 0; j < 8; j++) {
                float2 t = tw[m];
                re[j] += g.x * t.x + g.y * t.y;
                im[j] += g.y * t.x - g.x * t.y;
                m = (m + hh) & 63;
            }
        }
        #pragma unroll
        for (int j = 0; j < 8; j++) {
            int k = kb * 8 + j;
            float2 wc = fw[((size_t)k * 33 + w) * 256 + c0 + c];
            float rr = re[j] * 0.125f, ii = im[j] * 0.125f;
            sB[k][c] = make_float2(rr * wc.x - ii * wc.y, rr * wc.y + ii * wc.x);
        }
    }
    __syncthreads();

    int hb = tid >> 5;
    {
        float re[8] = {}, im[8] = {};
        for (int k = 0; k < 64; k++) {
            float2 g = sB[k][c];
            int m = (k * (hb * 8)) & 63;
            #pragma unroll
            for (int j = 0; j < 8; j++) {
                float2 t = tw[m];
                re[j] += g.x * t.x - g.y * t.y;
                im[j] += g.x * t.y + g.y * t.x;
                m = (m + k) & 63;
            }
        }
        #pragma unroll
        for (int j = 0; j < 8; j++) {
            int hh = hb * 8 + j;
            out[((size_t)(b * 64 + hh) * 33 + w) * 256 + c0 + c] =
                make_float2(re[j] * 0.125f, im[j] * 0.125f);
        }
    }
}

// ---------------- FFT stage 4: irfft along W ----------------
__global__ void fft4_kernel(const float2* __restrict__ A, float* __restrict__ zf) {
    __shared__ float2 sA[33][64];
    __shared__ float2 tw[64];
    int c0 = blockIdx.x * 64;
    int h = blockIdx.y, b = blockIdx.z;
    int tid = threadIdx.x;
    if (tid < 64) {
        float sn, cs; sincosf(tid * PI_OVER_32, &sn, &cs);
        tw[tid] = make_float2(cs, sn);
    }
    const float2* src = A + ((size_t)(b * 64 + h) * 33) * 256 + c0;
    for (int idx = tid; idx < 33 * 64; idx += 256) {
        int w = idx >> 6, cc = idx & 63;
        sA[w][cc] = src[(size_t)w * 256 + cc];
    }
    __syncthreads();
    int c = tid >> 2;
    int x0 = (tid & 3) * 16;
    float r[16];
    {
        float2 a0 = sA[0][c], a32 = sA[32][c];
        #pragma unroll
        for (int j = 0; j < 16; j++)
            r[j] = a0.x + (((x0 + j) & 1) ? -a32.x : a32.x);
    }
    for (int w = 1; w < 32; w++) {
        float2 a = sA[w][c];
        int m = (w * x0) & 63;
        #pragma unroll
        for (int j = 0; j < 16; j++) {
            float2 t = tw[m];
            r[j] += 2.f * (a.x * t.x - a.y * t.y);
            m = (m + w) & 63;
        }
    }
    float* dst = zf + ((size_t)(b * 256 + c0 + c) * 64 + h) * 64 + x0;
    #pragma unroll
    for (int q = 0; q < 4; q++) {
        float4 v = make_float4(r[q*4] * 0.125f, r[q*4+1] * 0.125f,
                               r[q*4+2] * 0.125f, r[q*4+3] * 0.125f);
        *(float4*)(dst + q * 4) = v;
    }
}

// ---------------- host launch ----------------
extern "C" void kernel_launch(void* const* d_in, const int* in_sizes, int n_in,
                              void* d_out, int out_size) {
    const float* x      = (const float*)d_in[0];
    const float* ln1_g  = (const float*)d_in[1];
    const float* ln1_b  = (const float*)d_in[2];
    const float* wqkv   = (const float*)d_in[3];
    const float* wout   = (const float*)d_in[4];
    const float* bout   = (const float*)d_in[5];
    const float* ln2_g  = (const float*)d_in[6];
    const float* ln2_b  = (const float*)d_in[7];
    const float* w1     = (const float*)d_in[8];
    const float* b1     = (const float*)d_in[9];
    const float* w2     = (const float*)d_in[10];
    const float* b2     = (const float*)d_in[11];
    const float* fft_w  = (const float*)d_in[12];
    const float* conv3w = (const float*)d_in[13];
    const float* bn3_g  = (const float*)d_in[14];
    const float* bn3_b  = (const float*)d_in[15];
    const float* bn3_m  = (const float*)d_in[16];
    const float* bn3_v  = (const float*)d_in[17];
    const float* conv4w = (const float*)d_in[18];
    const float* bn4_g  = (const float*)d_in[19];
    const float* bn4_b  = (const float*)d_in[20];
    const float* bn4_m  = (const float*)d_in[21];
    const float* bn4_v  = (const float*)d_in[22];
    float* outp = (float*)d_out;

    float *u, *y, *ac, *t, *lnb, *qk, *at, *mlp, *zp, *zf, *c3;
    float2 *f1, *f2;
    cudaGetSymbolAddress((void**)&u,   g_u);
    cudaGetSymbolAddress((void**)&y,   g_y);
    cudaGetSymbolAddress((void**)&ac,  g_acc);
    cudaGetSymbolAddress((void**)&t,   g_t);
    cudaGetSymbolAddress((void**)&lnb, g_ln);
    cudaGetSymbolAddress((void**)&qk,  g_qkv);
    cudaGetSymbolAddress((void**)&at,  g_att);
    cudaGetSymbolAddress((void**)&mlp, g_mlp);
    cudaGetSymbolAddress((void**)&zp,  g_zp);
    cudaGetSymbolAddress((void**)&f1,  g_f1);
    cudaGetSymbolAddress((void**)&f2,  g_f2);
    cudaGetSymbolAddress((void**)&zf,  g_zf);
    cudaGetSymbolAddress((void**)&c3,  g_c3);

    const float* NUL = (const float*)0;

    zero_kernel<<<16384, 256>>>(ac);
    unfold_kernel<<<dim3(128, 8, 16), 256>>>(x, u);

    for (int g = 0; g < 4; g++) {
        group_in_kernel<<<4096, 256>>>((const float4*)u, (const float4*)ac, (float4*)t, g);
        for (int i = 0; i < 2; i++) {
            // --- attention block ---
            ln_kernel<<<4096, 256>>>(t, ln1_g + i * 256, ln1_b + i * 256, lnb);
            gemm128_kernel<<<dim3(1, 128, 1), 256>>>(lnb, wqkv + i * 256 * 96,
                wqkv + i * 256 * 96, 1 << 30, qk,
                NUL, NUL, NUL, NUL, NUL, NUL,
                16384, 96, 256, 256, 96, 128, 0, 0, 0, 0);
            attn_kernel<<<dim3(64, 4), 256>>>(qk, at);
            gemm128_kernel<<<dim3(2, 128, 1), 256>>>(at, wout + i * 32 * 256,
                wout + i * 32 * 256, 1 << 30, t,
                bout + i * 256, t, NUL, NUL, NUL, NUL,
                16384, 256, 32, 32, 256, 256, 0, 0, 0, 0);
            // --- MLP block ---
            ln_kernel<<<4096, 256>>>(t, ln2_g + i * 256, ln2_b + i * 256, lnb);
            gemm128_kernel<<<dim3(4, 128, 1), 256>>>(lnb, w1 + i * 256 * 512,
                w1 + i * 256 * 512, 1 << 30, mlp,
                b1 + i * 512, NUL, NUL, NUL, NUL, NUL,
                16384, 512, 256, 256, 512, 512, 1, 0, 0, 0);
            gemm128_kernel<<<dim3(2, 128, 1), 256>>>(mlp, w2 + i * 512 * 256,
                w2 + i * 512 * 256, 1 << 30, t,
                b2 + i * 256, t, NUL, NUL, NUL, NUL,
                16384, 256, 512, 512, 256, 256, 0, 0, 0, 0);
        }
        group_store_kernel<<<4096, 256>>>((const float4*)t, (float4*)y, (float4*)ac, g);
    }

    fold_kernel<<<16384, 256>>>((const float4*)y, (float4*)zp);

    fft1_kernel<<<dim3(2, 64, 16), 256>>>(zp, f1);
    fft23_kernel<<<dim3(33, 8, 16), 256>>>(f1, (const float2*)fft_w, f2);
    fft4_kernel<<<dim3(4, 64, 16), 256>>>(f2, zf);

    // conv3 (1x1, 512->256): single GEMM, B = [zf ; x] via dual-source, + BN + SiLU
    gemm128_kernel<<<dim3(32, 2, 16), 256>>>(conv3w, zf, x, 256, c3,
        NUL, NUL, bn3_g, bn3_b, bn3_m, bn3_v,
        256, 4096, 512, 512, 4096, 4096, 1, 0, 1048576LL, 1048576LL);

    // conv4 (3x3, 256->256) implicit GEMM + BN + SiLU
    conv4_gemm_kernel<<<dim3(32, 2, 16), 256>>>(conv4w, c3, outp,
                                                bn4_g, bn4_b, bn4_m, bn4_v);
}

// round 8
// speedup vs baseline: 1.7101x; 1.1569x over previous
#include <cuda_runtime.h>
#include <mma.h>
#include <math.h>

using namespace nvcuda;

#define EPSF 1e-5f
#define PI_OVER_32 0.09817477042468103f

// ---------------- constant permutations ----------------
__constant__ int c_IDX[16]  = {0,7,10,13,1,4,11,14,2,5,8,15,3,6,9,12};
__constant__ int c_BACK[16] = {0,4,8,12,5,9,13,1,10,14,2,6,15,3,7,11};

// ---------------- device scratch (no allocs allowed) ----------------
__device__ float  g_u  [16*16*256*256];
__device__ float  g_y  [16*16*256*256];
__device__ float  g_acc[16*4*256*256];
__device__ float  g_t  [16*4*256*256];
__device__ float  g_ln [16*4*256*256];
__device__ float  g_qkv[16*4*256*128];    // ld=128 (cols 96..127 pad)
__device__ float  g_att[16*4*256*32];
__device__ float  g_mlp[16*4*256*512];
__device__ float  g_zp [16*64*64*256];
__device__ float2 g_f1 [16*64*33*256];
__device__ float2 g_f2 [16*64*33*256];
__device__ float  g_zf [16*256*64*64];
__device__ float  g_c3 [16*256*64*64];

// ---------------- tiny utility kernels ----------------
__global__ void zero_kernel(float* __restrict__ p) {
    p[(size_t)blockIdx.x * 256 + threadIdx.x] = 0.f;
}

__global__ void unfold_kernel(const float* __restrict__ x, float* __restrict__ u) {
    __shared__ float tile[32][33];
    int b  = blockIdx.z;
    int c0 = blockIdx.y * 32;
    int s0 = blockIdx.x * 32;
    int tx = threadIdx.x & 31, ty = threadIdx.x >> 5;
    #pragma unroll
    for (int cc = 0; cc < 4; cc++)
        tile[ty + cc * 8][tx] =
            x[(size_t)(b * 256 + c0 + ty + cc * 8) * 4096 + s0 + tx];
    __syncthreads();
    #pragma unroll
    for (int cc = 0; cc < 4; cc++) {
        int s = s0 + ty + cc * 8;
        int h = s >> 6, w = s & 63;
        int kp = (h & 3) * 4 + (w & 3);
        int j = c_BACK[kp];
        int l = (h >> 2) * 16 + (w >> 2);
        u[((size_t)(b * 16 + j) * 256 + l) * 256 + c0 + tx] = tile[tx][ty + cc * 8];
    }
}

__device__ __forceinline__ float4 f4add(float4 a, float4 b) {
    return make_float4(a.x + b.x, a.y + b.y, a.z + b.z, a.w + b.w);
}

__global__ void group_in_kernel(const float4* __restrict__ u, const float4* __restrict__ acc,
                                float4* __restrict__ t, int g) {
    int i = blockIdx.x * 256 + threadIdx.x;
    int c4 = i & 63;
    int l = (i >> 6) & 255;
    int p = (i >> 14) & 3;
    int b = i >> 16;
    t[i] = f4add(u[((size_t)(b * 16 + g * 4 + p) * 256 + l) * 64 + c4], acc[i]);
}

__global__ void group_store_kernel(const float4* __restrict__ t, float4* __restrict__ y,
                                   float4* __restrict__ acc, int g) {
    int i = blockIdx.x * 256 + threadIdx.x;
    int c4 = i & 63;
    int l = (i >> 6) & 255;
    int p = (i >> 14) & 3;
    int b = i >> 16;
    float4 v = t[i];
    y[((size_t)(b * 16 + g * 4 + p) * 256 + l) * 64 + c4] = v;
    acc[i] = f4add(acc[i], v);
}

__global__ void fold_kernel(const float4* __restrict__ y, float4* __restrict__ zp) {
    int i = blockIdx.x * 256 + threadIdx.x;
    int c4 = i & 63;
    int wp = (i >> 6) & 63;
    int hp = (i >> 12) & 63;
    int b  = i >> 18;
    int ky = hp & 3, ph = hp >> 2;
    int kx = wp & 3, pw = wp >> 2;
    int j = c_BACK[ky * 4 + kx];
    int l = ph * 16 + pw;
    zp[i] = y[((size_t)(b * 16 + j) * 256 + l) * 64 + c4];
}

// ---------------- layernorm: 4 rows per block, float4 ----------------
__global__ void ln_kernel(const float* __restrict__ in, const float* __restrict__ gw,
                          const float* __restrict__ bw, float* __restrict__ out) {
    int tid = threadIdx.x;
    int r = tid >> 6;
    int t = tid & 63;
    size_t row = (size_t)blockIdx.x * 4 + r;
    float4 v = *(const float4*)(in + row * 256 + t * 4);
    float s  = v.x + v.y + v.z + v.w;
    float sq = v.x * v.x + v.y * v.y + v.z * v.z + v.w * v.w;
    #pragma unroll
    for (int o = 16; o; o >>= 1) {
        s  += __shfl_xor_sync(0xffffffffu, s, o);
        sq += __shfl_xor_sync(0xffffffffu, sq, o);
    }
    __shared__ float ss[8], sqs[8];
    int warp = tid >> 5;
    if ((tid & 31) == 0) { ss[warp] = s; sqs[warp] = sq; }
    __syncthreads();
    s  = ss[r * 2] + ss[r * 2 + 1];
    sq = sqs[r * 2] + sqs[r * 2 + 1];
    float mean = s * (1.f / 256.f);
    float var  = sq * (1.f / 256.f) - mean * mean;
    float rstd = rsqrtf(var + EPSF);
    float4 g4 = *(const float4*)(gw + t * 4);
    float4 b4 = *(const float4*)(bw + t * 4);
    float4 o4;
    o4.x = (v.x - mean) * rstd * g4.x + b4.x;
    o4.y = (v.y - mean) * rstd * g4.y + b4.y;
    o4.z = (v.z - mean) * rstd * g4.z + b4.z;
    o4.w = (v.w - mean) * rstd * g4.w + b4.w;
    *(float4*)(out + row * 256 + t * 4) = o4;
}

// ---------------- tf32 GEMM: BM=128, BN=128, BK=16, 4 warps, warp tile 64x64 ----------
#define BM 128
#define BNN 128
#define BK 16

__device__ __forceinline__ float4 to_tf32_4(float4 v) {
    v.x = wmma::__float_to_tf32(v.x);
    v.y = wmma::__float_to_tf32(v.y);
    v.z = wmma::__float_to_tf32(v.z);
    v.w = wmma::__float_to_tf32(v.w);
    return v;
}

__global__ void __launch_bounds__(128)
gemm128_kernel(const float* __restrict__ A, const float* __restrict__ B,
               const float* __restrict__ B2, int ksplit,
               float* __restrict__ C,
               const float* __restrict__ bias, const float* __restrict__ resid,
               const float* __restrict__ bnG, const float* __restrict__ bnB,
               const float* __restrict__ bnM, const float* __restrict__ bnV,
               int M, int N, int K, int lda, int ldb, int ldc,
               int act, long long sA, long long sB, long long sC) {
    __shared__ float As[2][BM][BK + 4];
    __shared__ float Bs[2][BK][BNN + 4];
    __shared__ float epi[4][16][20];
    int z = blockIdx.z;
    A += z * sA; B += z * sB; if (B2) B2 += z * sB;
    C += z * sC;
    const float* R = resid ? resid + z * sC : (const float*)0;
    int bm = blockIdx.y * BM, bn = blockIdx.x * BNN;
    int tid = threadIdx.x, warp = tid >> 5, lane = tid & 31;
    int wr = warp >> 1, wc = warp & 1;

    wmma::fragment<wmma::accumulator, 16, 16, 8, float> acc[4][4];
    #pragma unroll
    for (int r = 0; r < 4; r++)
        #pragma unroll
        for (int c = 0; c < 4; c++)
            wmma::fill_fragment(acc[r][c], 0.f);

    // A: 128x16, thread covers rows (tid>>2)+32i, col (tid&3)*4
    // B: 16x128, thread covers rows (tid>>5)+4i,  col (tid&31)*4
    int aRow0 = tid >> 2, aCol = (tid & 3) * 4;
    int bRow0 = tid >> 5, bCol = (tid & 31) * 4;
    int cB = bn + bCol;
    bool bOK = (cB < N);

    float4 pa[4], pb[4];
    const float4 f4z = make_float4(0.f, 0.f, 0.f, 0.f);

    #pragma unroll
    for (int i = 0; i < 4; i++)
        pa[i] = *(const float4*)(A + (size_t)(bm + aRow0 + 32 * i) * lda + aCol);
    #pragma unroll
    for (int i = 0; i < 4; i++) {
        int k = bRow0 + 4 * i;
        const float* q = (k < ksplit) ? B + (size_t)k * ldb
                                      : B2 + (size_t)(k - ksplit) * ldb;
        pb[i] = bOK ? *(const float4*)(q + cB) : f4z;
    }
    #pragma unroll
    for (int i = 0; i < 4; i++) {
        *(float4*)&As[0][aRow0 + 32 * i][aCol] = to_tf32_4(pa[i]);
        *(float4*)&Bs[0][bRow0 + 4 * i][bCol]  = to_tf32_4(pb[i]);
    }
    __syncthreads();

    int cur = 0;
    for (int k0 = 0; k0 < K; k0 += BK) {
        int kn = k0 + BK;
        if (kn < K) {
            #pragma unroll
            for (int i = 0; i < 4; i++)
                pa[i] = *(const float4*)(A + (size_t)(bm + aRow0 + 32 * i) * lda + kn + aCol);
            #pragma unroll
            for (int i = 0; i < 4; i++) {
                int k = kn + bRow0 + 4 * i;
                const float* q = (k < ksplit) ? B + (size_t)k * ldb
                                              : B2 + (size_t)(k - ksplit) * ldb;
                pb[i] = bOK ? *(const float4*)(q + cB) : f4z;
            }
        }
        #pragma unroll
        for (int ks = 0; ks < BK; ks += 8) {
            wmma::fragment<wmma::matrix_a, 16, 16, 8, wmma::precision::tf32, wmma::row_major> af[4];
            wmma::fragment<wmma::matrix_b, 16, 16, 8, wmma::precision::tf32, wmma::row_major> bf[4];
            #pragma unroll
            for (int r = 0; r < 4; r++)
                wmma::load_matrix_sync(af[r], &As[cur][wr * 64 + r * 16][ks], BK + 4);
            #pragma unroll
            for (int c = 0; c < 4; c++)
                wmma::load_matrix_sync(bf[c], &Bs[cur][ks][wc * 64 + c * 16], BNN + 4);
            #pragma unroll
            for (int r = 0; r < 4; r++)
                #pragma unroll
                for (int c = 0; c < 4; c++)
                    wmma::mma_sync(acc[r][c], af[r], bf[c], acc[r][c]);
        }
        if (kn < K) {
            #pragma unroll
            for (int i = 0; i < 4; i++) {
                *(float4*)&As[cur ^ 1][aRow0 + 32 * i][aCol] = to_tf32_4(pa[i]);
                *(float4*)&Bs[cur ^ 1][bRow0 + 4 * i][bCol]  = to_tf32_4(pb[i]);
            }
        }
        __syncthreads();
        cur ^= 1;
    }

    // epilogue: resid -> bias -> bn-affine(row) -> silu
    #pragma unroll
    for (int r = 0; r < 4; r++)
        #pragma unroll
        for (int c = 0; c < 4; c++) {
            wmma::store_matrix_sync(&epi[warp][0][0], acc[r][c], 20, wmma::mem_row_major);
            __syncwarp();
            int rowBase = bm + wr * 64 + r * 16;
            int colBase = bn + wc * 64 + c * 16;
            #pragma unroll
            for (int k = 0; k < 8; k++) {
                int idx = k * 32 + lane;
                int rr = idx >> 4, cc = idx & 15;
                int row = rowBase + rr, col = colBase + cc;
                float v = epi[warp][rr][cc];
                if (R)    v += R[(size_t)row * ldc + col];
                if (bias && col < N) v += bias[col];
                if (bnG) {
                    float s_ = bnG[row] * rsqrtf(bnV[row] + EPSF);
                    v = v * s_ + (bnB[row] - bnM[row] * s_);
                }
                if (act) v = v / (1.f + __expf(-v));
                C[(size_t)row * ldc + col] = v;
            }
            __syncwarp();
        }
}

// ---------------- conv4 implicit GEMM, 4 warps, warp tile 64x64 ----------------
__global__ void __launch_bounds__(128)
conv4_gemm_kernel(const float* __restrict__ W, const float* __restrict__ img,
                  float* __restrict__ C,
                  const float* __restrict__ bnG, const float* __restrict__ bnB,
                  const float* __restrict__ bnM, const float* __restrict__ bnV) {
    __shared__ float As[2][BM][BK + 4];
    __shared__ float Bs[2][BK][BNN + 4];
    __shared__ float epi[4][16][20];
    const int K = 2304;
    int z = blockIdx.z;
    img += (size_t)z * 256 * 4096;
    C   += (size_t)z * 256 * 4096;
    int bm = blockIdx.y * BM, bn = blockIdx.x * BNN;
    int tid = threadIdx.x, warp = tid >> 5, lane = tid & 31;
    int wr = warp >> 1, wc = warp & 1;

    wmma::fragment<wmma::accumulator, 16, 16, 8, float> acc[4][4];
    #pragma unroll
    for (int r = 0; r < 4; r++)
        #pragma unroll
        for (int c = 0; c < 4; c++)
            wmma::fill_fragment(acc[r][c], 0.f);

    int aRow0 = tid >> 2, aCol = (tid & 3) * 4;
    int bRow0 = tid >> 5, bCol = (tid & 31) * 4;
    int n = bn + bCol;
    int y0 = n >> 6, x0 = n & 63;

    float4 pa[4];
    float pbv[4][4];

    auto loadB = [&](int kbase) {
        #pragma unroll
        for (int i = 0; i < 4; i++) {
            int k = kbase + bRow0 + 4 * i;
            int ic = k / 9, kk = k - ic * 9;
            int ky = kk / 3, kx = kk - ky * 3;
            int gy = y0 + ky - 1;
            const float* p = img + ((size_t)ic * 64 + gy) * 64;
            bool rok = (unsigned)gy < 64u;
            #pragma unroll
            for (int e = 0; e < 4; e++) {
                int gx = x0 + e + kx - 1;
                pbv[i][e] = (rok && (unsigned)gx < 64u) ? p[gx] : 0.f;
            }
        }
    };

    #pragma unroll
    for (int i = 0; i < 4; i++)
        pa[i] = *(const float4*)(W + (size_t)(bm + aRow0 + 32 * i) * 2304 + aCol);
    loadB(0);
    #pragma unroll
    for (int i = 0; i < 4; i++) {
        *(float4*)&As[0][aRow0 + 32 * i][aCol] = to_tf32_4(pa[i]);
        #pragma unroll
        for (int e = 0; e < 4; e++)
            Bs[0][bRow0 + 4 * i][bCol + e] = wmma::__float_to_tf32(pbv[i][e]);
    }
    __syncthreads();

    int cur = 0;
    for (int k0 = 0; k0 < K; k0 += BK) {
        int kn = k0 + BK;
        if (kn < K) {
            #pragma unroll
            for (int i = 0; i < 4; i++)
                pa[i] = *(const float4*)(W + (size_t)(bm + aRow0 + 32 * i) * 2304 + kn + aCol);
            loadB(kn);
        }
        #pragma unroll
        for (int ks = 0; ks < BK; ks += 8) {
            wmma::fragment<wmma::matrix_a, 16, 16, 8, wmma::precision::tf32, wmma::row_major> af[4];
            wmma::fragment<wmma::matrix_b, 16, 16, 8, wmma::precision::tf32, wmma::row_major> bf[4];
            #pragma unroll
            for (int r = 0; r < 4; r++)
                wmma::load_matrix_sync(af[r], &As[cur][wr * 64 + r * 16][ks], BK + 4);
            #pragma unroll
            for (int c = 0; c < 4; c++)
                wmma::load_matrix_sync(bf[c], &Bs[cur][ks][wc * 64 + c * 16], BNN + 4);
            #pragma unroll
            for (int r = 0; r < 4; r++)
                #pragma unroll
                for (int c = 0; c < 4; c++)
                    wmma::mma_sync(acc[r][c], af[r], bf[c], acc[r][c]);
        }
        if (kn < K) {
            #pragma unroll
            for (int i = 0; i < 4; i++) {
                *(float4*)&As[cur ^ 1][aRow0 + 32 * i][aCol] = to_tf32_4(pa[i]);
                #pragma unroll
                for (int e = 0; e < 4; e++)
                    Bs[cur ^ 1][bRow0 + 4 * i][bCol + e] = wmma::__float_to_tf32(pbv[i][e]);
            }
        }
        __syncthreads();
        cur ^= 1;
    }

    #pragma unroll
    for (int r = 0; r < 4; r++)
        #pragma unroll
        for (int c = 0; c < 4; c++) {
            wmma::store_matrix_sync(&epi[warp][0][0], acc[r][c], 20, wmma::mem_row_major);
            __syncwarp();
            int rowBase = bm + wr * 64 + r * 16;
            int colBase = bn + wc * 64 + c * 16;
            #pragma unroll
            for (int k = 0; k < 8; k++) {
                int idx = k * 32 + lane;
                int rr = idx >> 4, cc = idx & 15;
                int row = rowBase + rr, col = colBase + cc;
                float v = epi[warp][rr][cc];
                float s_ = bnG[row] * rsqrtf(bnV[row] + EPSF);
                v = v * s_ + (bnB[row] - bnM[row] * s_);
                v = v / (1.f + __expf(-v));
                C[(size_t)row * 4096 + col] = v;
            }
            __syncwarp();
        }
}

// ---------------- attention ----------------
__global__ void attn_kernel(const float* __restrict__ qkv, float* __restrict__ att) {
    int bp = blockIdx.x;
    int h  = blockIdx.y;
    int n  = threadIdx.x;
    __shared__ float ks[256 * 8];
    __shared__ float vs[256 * 8];
    int row = bp * 256 + n;
    const float* base = qkv + (size_t)row * 128 + h * 8;
    float4 q0 = *(const float4*)(base);
    float4 q1 = *(const float4*)(base + 4);
    *(float4*)&ks[n * 8]     = *(const float4*)(base + 32);
    *(float4*)&ks[n * 8 + 4] = *(const float4*)(base + 36);
    *(float4*)&vs[n * 8]     = *(const float4*)(base + 64);
    *(float4*)&vs[n * 8 + 4] = *(const float4*)(base + 68);
    __syncthreads();
    float q[8] = {q0.x, q0.y, q0.z, q0.w, q1.x, q1.y, q1.z, q1.w};
    float mx = -1e30f, ssum = 0.f;
    float acc[8] = {};
    for (int m = 0; m < 256; m++) {
        float4 ka = *(const float4*)&ks[m * 8];
        float4 kb = *(const float4*)&ks[m * 8 + 4];
        float d = q[0]*ka.x + q[1]*ka.y + q[2]*ka.z + q[3]*ka.w
                + q[4]*kb.x + q[5]*kb.y + q[6]*kb.z + q[7]*kb.w;
        d *= 0.35355339059327373f;
        float w;
        if (d > mx) {
            float corr = __expf(mx - d);
            ssum *= corr;
            #pragma unroll
            for (int j = 0; j < 8; j++) acc[j] *= corr;
            mx = d;
            w = 1.f;
        } else {
            w = __expf(d - mx);
        }
        ssum += w;
        float4 va = *(const float4*)&vs[m * 8];
        float4 vb = *(const float4*)&vs[m * 8 + 4];
        acc[0] += w * va.x; acc[1] += w * va.y; acc[2] += w * va.z; acc[3] += w * va.w;
        acc[4] += w * vb.x; acc[5] += w * vb.y; acc[6] += w * vb.z; acc[7] += w * vb.w;
    }
    float inv = 1.f / ssum;
    float* o = att + (size_t)row * 32 + h * 8;
    *(float4*)(o)     = make_float4(acc[0]*inv, acc[1]*inv, acc[2]*inv, acc[3]*inv);
    *(float4*)(o + 4) = make_float4(acc[4]*inv, acc[5]*inv, acc[6]*inv, acc[7]*inv);
}

// ---------------- FFT stage 1: rfft along W ----------------
__global__ void fft1_kernel(const float* __restrict__ zp, float2* __restrict__ f1) {
    __shared__ float sX[64][128];
    __shared__ float2 tw[64];
    int c0 = blockIdx.x * 128;
    int h = blockIdx.y, b = blockIdx.z;
    int tid = threadIdx.x;
    if (tid < 64) {
        float sn, cs; sincosf(tid * PI_OVER_32, &sn, &cs);
        tw[tid] = make_float2(cs, sn);
    }
    const float* src = zp + ((size_t)(b * 64 + h) * 64) * 256 + c0;
    #pragma unroll
    for (int i = 0; i < 8; i++) {
        int idx = tid + i * 256;
        int x = idx >> 5, cc = (idx & 31) * 4;
        *(float4*)&sX[x][cc] = *(const float4*)(src + (size_t)x * 256 + cc);
    }
    __syncthreads();
    int c = tid & 127, wg = tid >> 7;
    int nw = 17 - wg;
    float re[17], im[17];
    #pragma unroll
    for (int j = 0; j < 17; j++) { re[j] = 0.f; im[j] = 0.f; }
    for (int x = 0; x < 64; x++) {
        float g = sX[x][c];
        int m = (wg * x) & 63;
        int step = (2 * x) & 63;
        #pragma unroll
        for (int j = 0; j < 17; j++) {
            if (j < nw) {
                float2 t = tw[m];
                re[j] += g * t.x;
                im[j] -= g * t.y;
                m = (m + step) & 63;
            }
        }
    }
    float2* dst = f1 + ((size_t)(b * 64 + h) * 33) * 256 + c0 + c;
    #pragma unroll
    for (int j = 0; j < 17; j++) {
        if (j < nw) {
            int w = wg + 2 * j;
            dst[(size_t)w * 256] = make_float2(re[j] * 0.125f, im[j] * 0.125f);
        }
    }
}

// ---------------- FFT stages 2+3 fused ----------------
__global__ void fft23_kernel(const float2* __restrict__ f1, const float2* __restrict__ fw,
                             float2* __restrict__ out) {
    __shared__ float2 sA[64][32];
    __shared__ float2 sB[64][32];
    __shared__ float2 tw[64];
    int w = blockIdx.x;
    int c0 = blockIdx.y * 32;
    int b = blockIdx.z;
    int tid = threadIdx.x;
    if (tid < 64) {
        float sn, cs; sincosf(tid * PI_OVER_32, &sn, &cs);
        tw[tid] = make_float2(cs, sn);
    }
    #pragma unroll
    for (int i = 0; i < 8; i++) {
        int idx = tid + i * 256;
        int hh = idx >> 5, cc = idx & 31;
        sA[hh][cc] = f1[((size_t)(b * 64 + hh) * 33 + w) * 256 + c0 + cc];
    }
    __syncthreads();

    int c = tid & 31;
    int kb = tid >> 5;
    {
        float re[8] = {}, im[8] = {};
        for (int hh = 0; hh < 64; hh++) {
            float2 g = sA[hh][c];
            int m = ((kb * 8) * hh) & 63;
            #pragma unroll
            for (int j = 0; j < 8; j++) {
                float2 t = tw[m];
                re[j] += g.x * t.x + g.y * t.y;
                im[j] += g.y * t.x - g.x * t.y;
                m = (m + hh) & 63;
            }
        }
        #pragma unroll
        for (int j = 0; j < 8; j++) {
            int k = kb * 8 + j;
            float2 wc = fw[((size_t)k * 33 + w) * 256 + c0 + c];
            float rr = re[j] * 0.125f, ii = im[j] * 0.125f;
            sB[k][c] = make_float2(rr * wc.x - ii * wc.y, rr * wc.y + ii * wc.x);
        }
    }
    __syncthreads();

    int hb = tid >> 5;
    {
        float re[8] = {}, im[8] = {};
        for (int k = 0; k < 64; k++) {
            float2 g = sB[k][c];
            int m = (k * (hb * 8)) & 63;
            #pragma unroll
            for (int j = 0; j < 8; j++) {
                float2 t = tw[m];
                re[j] += g.x * t.x - g.y * t.y;
                im[j] += g.x * t.y + g.y * t.x;
                m = (m + k) & 63;
            }
        }
        #pragma unroll
        for (int j = 0; j < 8; j++) {
            int hh = hb * 8 + j;
            out[((size_t)(b * 64 + hh) * 33 + w) * 256 + c0 + c] =
                make_float2(re[j] * 0.125f, im[j] * 0.125f);
        }
    }
}

// ---------------- FFT stage 4: irfft along W ----------------
__global__ void fft4_kernel(const float2* __restrict__ A, float* __restrict__ zf) {
    __shared__ float2 sA[33][64];
    __shared__ float2 tw[64];
    int c0 = blockIdx.x * 64;
    int h = blockIdx.y, b = blockIdx.z;
    int tid = threadIdx.x;
    if (tid < 64) {
        float sn, cs; sincosf(tid * PI_OVER_32, &sn, &cs);
        tw[tid] = make_float2(cs, sn);
    }
    const float2* src = A + ((size_t)(b * 64 + h) * 33) * 256 + c0;
    for (int idx = tid; idx < 33 * 64; idx += 256) {
        int w = idx >> 6, cc = idx & 63;
        sA[w][cc] = src[(size_t)w * 256 + cc];
    }
    __syncthreads();
    int c = tid >> 2;
    int x0 = (tid & 3) * 16;
    float r[16];
    {
        float2 a0 = sA[0][c], a32 = sA[32][c];
        #pragma unroll
        for (int j = 0; j < 16; j++)
            r[j] = a0.x + (((x0 + j) & 1) ? -a32.x : a32.x);
    }
    for (int w = 1; w < 32; w++) {
        float2 a = sA[w][c];
        int m = (w * x0) & 63;
        #pragma unroll
        for (int j = 0; j < 16; j++) {
            float2 t = tw[m];
            r[j] += 2.f * (a.x * t.x - a.y * t.y);
            m = (m + w) & 63;
        }
    }
    float* dst = zf + ((size_t)(b * 256 + c0 + c) * 64 + h) * 64 + x0;
    #pragma unroll
    for (int q = 0; q < 4; q++) {
        float4 v = make_float4(r[q*4] * 0.125f, r[q*4+1] * 0.125f,
                               r[q*4+2] * 0.125f, r[q*4+3] * 0.125f);
        *(float4*)(dst + q * 4) = v;
    }
}

// ---------------- host launch ----------------
extern "C" void kernel_launch(void* const* d_in, const int* in_sizes, int n_in,
                              void* d_out, int out_size) {
    const float* x      = (const float*)d_in[0];
    const float* ln1_g  = (const float*)d_in[1];
    const float* ln1_b  = (const float*)d_in[2];
    const float* wqkv   = (const float*)d_in[3];
    const float* wout   = (const float*)d_in[4];
    const float* bout   = (const float*)d_in[5];
    const float* ln2_g  = (const float*)d_in[6];
    const float* ln2_b  = (const float*)d_in[7];
    const float* w1     = (const float*)d_in[8];
    const float* b1     = (const float*)d_in[9];
    const float* w2     = (const float*)d_in[10];
    const float* b2     = (const float*)d_in[11];
    const float* fft_w  = (const float*)d_in[12];
    const float* conv3w = (const float*)d_in[13];
    const float* bn3_g  = (const float*)d_in[14];
    const float* bn3_b  = (const float*)d_in[15];
    const float* bn3_m  = (const float*)d_in[16];
    const float* bn3_v  = (const float*)d_in[17];
    const float* conv4w = (const float*)d_in[18];
    const float* bn4_g  = (const float*)d_in[19];
    const float* bn4_b  = (const float*)d_in[20];
    const float* bn4_m  = (const float*)d_in[21];
    const float* bn4_v  = (const float*)d_in[22];
    float* outp = (float*)d_out;

    float *u, *y, *ac, *t, *lnb, *qk, *at, *mlp, *zp, *zf, *c3;
    float2 *f1, *f2;
    cudaGetSymbolAddress((void**)&u,   g_u);
    cudaGetSymbolAddress((void**)&y,   g_y);
    cudaGetSymbolAddress((void**)&ac,  g_acc);
    cudaGetSymbolAddress((void**)&t,   g_t);
    cudaGetSymbolAddress((void**)&lnb, g_ln);
    cudaGetSymbolAddress((void**)&qk,  g_qkv);
    cudaGetSymbolAddress((void**)&at,  g_att);
    cudaGetSymbolAddress((void**)&mlp, g_mlp);
    cudaGetSymbolAddress((void**)&zp,  g_zp);
    cudaGetSymbolAddress((void**)&f1,  g_f1);
    cudaGetSymbolAddress((void**)&f2,  g_f2);
    cudaGetSymbolAddress((void**)&zf,  g_zf);
    cudaGetSymbolAddress((void**)&c3,  g_c3);

    const float* NUL = (const float*)0;

    zero_kernel<<<16384, 256>>>(ac);
    unfold_kernel<<<dim3(128, 8, 16), 256>>>(x, u);

    for (int g = 0; g < 4; g++) {
        group_in_kernel<<<4096, 256>>>((const float4*)u, (const float4*)ac, (float4*)t, g);
        for (int i = 0; i < 2; i++) {
            // --- attention block ---
            ln_kernel<<<4096, 256>>>(t, ln1_g + i * 256, ln1_b + i * 256, lnb);
            gemm128_kernel<<<dim3(1, 128, 1), 128>>>(lnb, wqkv + i * 256 * 96,
                wqkv + i * 256 * 96, 1 << 30, qk,
                NUL, NUL, NUL, NUL, NUL, NUL,
                16384, 96, 256, 256, 96, 128, 0, 0, 0, 0);
            attn_kernel<<<dim3(64, 4), 256>>>(qk, at);
            gemm128_kernel<<<dim3(2, 128, 1), 128>>>(at, wout + i * 32 * 256,
                wout + i * 32 * 256, 1 << 30, t,
                bout + i * 256, t, NUL, NUL, NUL, NUL,
                16384, 256, 32, 32, 256, 256, 0, 0, 0, 0);
            // --- MLP block ---
            ln_kernel<<<4096, 256>>>(t, ln2_g + i * 256, ln2_b + i * 256, lnb);
            gemm128_kernel<<<dim3(4, 128, 1), 128>>>(lnb, w1 + i * 256 * 512,
                w1 + i * 256 * 512, 1 << 30, mlp,
                b1 + i * 512, NUL, NUL, NUL, NUL, NUL,
                16384, 512, 256, 256, 512, 512, 1, 0, 0, 0);
            gemm128_kernel<<<dim3(2, 128, 1), 128>>>(mlp, w2 + i * 512 * 256,
                w2 + i * 512 * 256, 1 << 30, t,
                b2 + i * 256, t, NUL, NUL, NUL, NUL,
                16384, 256, 512, 512, 256, 256, 0, 0, 0, 0);
        }
        group_store_kernel<<<4096, 256>>>((const float4*)t, (float4*)y, (float4*)ac, g);
    }

    fold_kernel<<<16384, 256>>>((const float4*)y, (float4*)zp);

    fft1_kernel<<<dim3(2, 64, 16), 256>>>(zp, f1);
    fft23_kernel<<<dim3(33, 8, 16), 256>>>(f1, (const float2*)fft_w, f2);
    fft4_kernel<<<dim3(4, 64, 16), 256>>>(f2, zf);

    // conv3 (1x1, 512->256): single GEMM, B = [zf ; x] via dual-source, + BN + SiLU
    gemm128_kernel<<<dim3(32, 2, 16), 128>>>(conv3w, zf, x, 256, c3,
        NUL, NUL, bn3_g, bn3_b, bn3_m, bn3_v,
        256, 4096, 512, 512, 4096, 4096, 1, 0, 1048576LL, 1048576LL);

    // conv4 (3x3, 256->256) implicit GEMM + BN + SiLU
    conv4_gemm_kernel<<<dim3(32, 2, 16), 128>>>(conv4w, c3, outp,
                                                bn4_g, bn4_b, bn4_m, bn4_v);
}

// round 9
// speedup vs baseline: 2.2173x; 1.2966x over previous
#include <cuda_runtime.h>
#include <mma.h>
#include <math.h>

#define EPSF 1e-5f
#define PI_OVER_32 0.09817477042468103f

// ---------------- constant permutations ----------------
__constant__ int c_IDX[16]  = {0,7,10,13,1,4,11,14,2,5,8,15,3,6,9,12};
__constant__ int c_BACK[16] = {0,4,8,12,5,9,13,1,10,14,2,6,15,3,7,11};

// ---------------- device scratch (no allocs allowed) ----------------
__device__ float  g_u  [16*16*256*256];
__device__ float  g_y  [16*16*256*256];
__device__ float  g_acc[16*4*256*256];
__device__ float  g_t  [16*4*256*256];
__device__ float  g_ln [16*4*256*256];
__device__ float  g_qkv[16*4*256*128];    // ld=128 (cols 96..127 pad)
__device__ float  g_att[16*4*256*32];
__device__ float  g_mlp[16*4*256*512];
__device__ float  g_zp [16*64*64*256];
__device__ float2 g_f1 [16*64*33*256];
__device__ float2 g_f2 [16*64*33*256];
__device__ float  g_zf [16*256*64*64];
__device__ float  g_c3 [16*256*64*64];

__device__ __forceinline__ float to_tf32(float x) {
    return nvcuda::wmma::__float_to_tf32(x);
}

__device__ __forceinline__ void mma8(float* d, const unsigned* a, unsigned b0, unsigned b1) {
    asm volatile(
        "mma.sync.aligned.m16n8k8.row.col.f32.tf32.tf32.f32 "
        "{%0,%1,%2,%3}, {%4,%5,%6,%7}, {%8,%9}, {%0,%1,%2,%3};"
        : "+f"(d[0]), "+f"(d[1]), "+f"(d[2]), "+f"(d[3])
        : "r"(a[0]), "r"(a[1]), "r"(a[2]), "r"(a[3]), "r"(b0), "r"(b1));
}

// ---------------- tiny utility kernels ----------------
__global__ void zero_kernel(float* __restrict__ p) {
    p[(size_t)blockIdx.x * 256 + threadIdx.x] = 0.f;
}

__global__ void unfold_kernel(const float* __restrict__ x, float* __restrict__ u) {
    __shared__ float tile[32][33];
    int b  = blockIdx.z;
    int c0 = blockIdx.y * 32;
    int s0 = blockIdx.x * 32;
    int tx = threadIdx.x & 31, ty = threadIdx.x >> 5;
    #pragma unroll
    for (int cc = 0; cc < 4; cc++)
        tile[ty + cc * 8][tx] =
            x[(size_t)(b * 256 + c0 + ty + cc * 8) * 4096 + s0 + tx];
    __syncthreads();
    #pragma unroll
    for (int cc = 0; cc < 4; cc++) {
        int s = s0 + ty + cc * 8;
        int h = s >> 6, w = s & 63;
        int kp = (h & 3) * 4 + (w & 3);
        int j = c_BACK[kp];
        int l = (h >> 2) * 16 + (w >> 2);
        u[((size_t)(b * 16 + j) * 256 + l) * 256 + c0 + tx] = tile[tx][ty + cc * 8];
    }
}

__device__ __forceinline__ float4 f4add(float4 a, float4 b) {
    return make_float4(a.x + b.x, a.y + b.y, a.z + b.z, a.w + b.w);
}

__global__ void group_in_kernel(const float4* __restrict__ u, const float4* __restrict__ acc,
                                float4* __restrict__ t, int g) {
    int i = blockIdx.x * 256 + threadIdx.x;
    int c4 = i & 63;
    int l = (i >> 6) & 255;
    int p = (i >> 14) & 3;
    int b = i >> 16;
    t[i] = f4add(u[((size_t)(b * 16 + g * 4 + p) * 256 + l) * 64 + c4], acc[i]);
}

__global__ void group_store_kernel(const float4* __restrict__ t, float4* __restrict__ y,
                                   float4* __restrict__ acc, int g) {
    int i = blockIdx.x * 256 + threadIdx.x;
    int c4 = i & 63;
    int l = (i >> 6) & 255;
    int p = (i >> 14) & 3;
    int b = i >> 16;
    float4 v = t[i];
    y[((size_t)(b * 16 + g * 4 + p) * 256 + l) * 64 + c4] = v;
    acc[i] = f4add(acc[i], v);
}

__global__ void fold_kernel(const float4* __restrict__ y, float4* __restrict__ zp) {
    int i = blockIdx.x * 256 + threadIdx.x;
    int c4 = i & 63;
    int wp = (i >> 6) & 63;
    int hp = (i >> 12) & 63;
    int b  = i >> 18;
    int ky = hp & 3, ph = hp >> 2;
    int kx = wp & 3, pw = wp >> 2;
    int j = c_BACK[ky * 4 + kx];
    int l = ph * 16 + pw;
    zp[i] = y[((size_t)(b * 16 + j) * 256 + l) * 64 + c4];
}

// ---------------- layernorm: 4 rows per block, float4 ----------------
__global__ void ln_kernel(const float* __restrict__ in, const float* __restrict__ gw,
                          const float* __restrict__ bw, float* __restrict__ out) {
    int tid = threadIdx.x;
    int r = tid >> 6;
    int t = tid & 63;
    size_t row = (size_t)blockIdx.x * 4 + r;
    float4 v = *(const float4*)(in + row * 256 + t * 4);
    float s  = v.x + v.y + v.z + v.w;
    float sq = v.x * v.x + v.y * v.y + v.z * v.z + v.w * v.w;
    #pragma unroll
    for (int o = 16; o; o >>= 1) {
        s  += __shfl_xor_sync(0xffffffffu, s, o);
        sq += __shfl_xor_sync(0xffffffffu, sq, o);
    }
    __shared__ float ss[8], sqs[8];
    int warp = tid >> 5;
    if ((tid & 31) == 0) { ss[warp] = s; sqs[warp] = sq; }
    __syncthreads();
    s  = ss[r * 2] + ss[r * 2 + 1];
    sq = sqs[r * 2] + sqs[r * 2 + 1];
    float mean = s * (1.f / 256.f);
    float var  = sq * (1.f / 256.f) - mean * mean;
    float rstd = rsqrtf(var + EPSF);
    float4 g4 = *(const float4*)(gw + t * 4);
    float4 b4 = *(const float4*)(bw + t * 4);
    float4 o4;
    o4.x = (v.x - mean) * rstd * g4.x + b4.x;
    o4.y = (v.y - mean) * rstd * g4.y + b4.y;
    o4.z = (v.z - mean) * rstd * g4.z + b4.z;
    o4.w = (v.w - mean) * rstd * g4.w + b4.w;
    *(float4*)(out + row * 256 + t * 4) = o4;
}

// ============ raw-mma tf32 GEMM: BM=128, BN=128, BK=16, 4 warps, 64x64 warp tile ======
// A smem: k-permuted per 8-slice (k' = (k&3)*2 + (k>>2)) -> A frag = 2x LDS.64
// B smem: k-major (natural)                              -> B frag = 2x LDS.32
// Epilogue: direct register->global float2 stores (no staging).
#define BM 128
#define BNN 128
#define BK 16
#define ALD 18
#define BLD 132

__global__ void __launch_bounds__(128)
gemm128_kernel(const float* __restrict__ A, const float* __restrict__ B,
               const float* __restrict__ B2, int ksplit,
               float* __restrict__ C,
               const float* __restrict__ bias, const float* __restrict__ resid,
               const float* __restrict__ bnG, const float* __restrict__ bnB,
               const float* __restrict__ bnM, const float* __restrict__ bnV,
               int M, int N, int K, int lda, int ldb, int ldc,
               int act, long long sA, long long sB, long long sC) {
    __shared__ float As[2][BM][ALD];
    __shared__ float Bs[2][BK][BLD];
    int z = blockIdx.z;
    A += z * sA; B += z * sB; if (B2) B2 += z * sB;
    C += z * sC;
    const float* R = resid ? resid + z * sC : (const float*)0;
    int bm = blockIdx.y * BM, bn = blockIdx.x * BNN;
    int tid = threadIdx.x, warp = tid >> 5, lane = tid & 31;
    int wr = warp >> 1, wc = warp & 1;
    int lg = lane >> 2, lq = lane & 3;   // group / quad

    float acc[4][8][4];
    #pragma unroll
    for (int r = 0; r < 4; r++)
        #pragma unroll
        for (int c = 0; c < 8; c++)
            #pragma unroll
            for (int e = 0; e < 4; e++)
                acc[r][c][e] = 0.f;

    int aRow0 = tid >> 2, aCol = (tid & 3) * 4;
    int aDst = ((aCol >> 3) * 8) + ((aCol >> 2) & 1);   // permuted base
    int bRow0 = tid >> 5, bCol = (tid & 31) * 4;
    int cB = bn + bCol;
    bool bOK = (cB < N);

    float4 pa[4], pb[4];
    const float4 f4z = make_float4(0.f, 0.f, 0.f, 0.f);

    #pragma unroll
    for (int i = 0; i < 4; i++)
        pa[i] = *(const float4*)(A + (size_t)(bm + aRow0 + 32 * i) * lda + aCol);
    #pragma unroll
    for (int i = 0; i < 4; i++) {
        int k = bRow0 + 4 * i;
        const float* q = (k < ksplit) ? B + (size_t)k * ldb
                                      : B2 + (size_t)(k - ksplit) * ldb;
        pb[i] = bOK ? *(const float4*)(q + cB) : f4z;
    }
    #pragma unroll
    for (int i = 0; i < 4; i++) {
        float* d = &As[0][aRow0 + 32 * i][aDst];
        d[0] = to_tf32(pa[i].x); d[2] = to_tf32(pa[i].y);
        d[4] = to_tf32(pa[i].z); d[6] = to_tf32(pa[i].w);
        float4 t4 = pb[i];
        t4.x = to_tf32(t4.x); t4.y = to_tf32(t4.y);
        t4.z = to_tf32(t4.z); t4.w = to_tf32(t4.w);
        *(float4*)&Bs[0][bRow0 + 4 * i][bCol] = t4;
    }
    __syncthreads();

    int cur = 0;
    for (int k0 = 0; k0 < K; k0 += BK) {
        int kn = k0 + BK;
        if (kn < K) {
            #pragma unroll
            for (int i = 0; i < 4; i++)
                pa[i] = *(const float4*)(A + (size_t)(bm + aRow0 + 32 * i) * lda + kn + aCol);
            #pragma unroll
            for (int i = 0; i < 4; i++) {
                int k = kn + bRow0 + 4 * i;
                const float* q = (k < ksplit) ? B + (size_t)k * ldb
                                              : B2 + (size_t)(k - ksplit) * ldb;
                pb[i] = bOK ? *(const float4*)(q + cB) : f4z;
            }
        }
        #pragma unroll
        for (int s = 0; s < 2; s++) {
            unsigned a[4][4];
            #pragma unroll
            for (int r = 0; r < 4; r++) {
                const float* ap = &As[cur][wr * 64 + r * 16 + lg][s * 8 + 2 * lq];
                float2 lo = *(const float2*)ap;
                float2 hi = *(const float2*)(ap + 8 * ALD);
                a[r][0] = __float_as_uint(lo.x); a[r][1] = __float_as_uint(hi.x);
                a[r][2] = __float_as_uint(lo.y); a[r][3] = __float_as_uint(hi.y);
            }
            #pragma unroll
            for (int c = 0; c < 8; c++) {
                int nn = wc * 64 + c * 8 + lg;
                unsigned b0 = __float_as_uint(Bs[cur][s * 8 + lq][nn]);
                unsigned b1 = __float_as_uint(Bs[cur][s * 8 + lq + 4][nn]);
                #pragma unroll
                for (int r = 0; r < 4; r++)
                    mma8(acc[r][c], a[r], b0, b1);
            }
        }
        if (kn < K) {
            #pragma unroll
            for (int i = 0; i < 4; i++) {
                float* d = &As[cur ^ 1][aRow0 + 32 * i][aDst];
                d[0] = to_tf32(pa[i].x); d[2] = to_tf32(pa[i].y);
                d[4] = to_tf32(pa[i].z); d[6] = to_tf32(pa[i].w);
                float4 t4 = pb[i];
                t4.x = to_tf32(t4.x); t4.y = to_tf32(t4.y);
                t4.z = to_tf32(t4.z); t4.w = to_tf32(t4.w);
                *(float4*)&Bs[cur ^ 1][bRow0 + 4 * i][bCol] = t4;
            }
        }
        __syncthreads();
        cur ^= 1;
    }

    // direct epilogue: resid -> bias -> bn-affine(row) -> silu
    #pragma unroll
    for (int r = 0; r < 4; r++) {
        #pragma unroll
        for (int half = 0; half < 2; half++) {
            int row = bm + wr * 64 + r * 16 + lg + half * 8;
            float sc = 1.f, sh = 0.f;
            if (bnG) {
                float s_ = bnG[row] * rsqrtf(bnV[row] + EPSF);
                sc = s_; sh = bnB[row] - bnM[row] * s_;
            }
            #pragma unroll
            for (int c = 0; c < 8; c++) {
                int col = bn + wc * 64 + c * 8 + 2 * lq;
                if (col < N) {
                    float v0 = acc[r][c][half * 2];
                    float v1 = acc[r][c][half * 2 + 1];
                    if (R) {
                        float2 rv = *(const float2*)(R + (size_t)row * ldc + col);
                        v0 += rv.x; v1 += rv.y;
                    }
                    if (bias) {
                        float2 bv = *(const float2*)(bias + col);
                        v0 += bv.x; v1 += bv.y;
                    }
                    v0 = v0 * sc + sh;
                    v1 = v1 * sc + sh;
                    if (act) {
                        v0 = v0 / (1.f + __expf(-v0));
                        v1 = v1 / (1.f + __expf(-v1));
                    }
                    *(float2*)(C + (size_t)row * ldc + col) = make_float2(v0, v1);
                }
            }
        }
    }
}

// ---------------- conv4 implicit GEMM, raw mma ----------------
__global__ void __launch_bounds__(128)
conv4_gemm_kernel(const float* __restrict__ W, const float* __restrict__ img,
                  float* __restrict__ C,
                  const float* __restrict__ bnG, const float* __restrict__ bnB,
                  const float* __restrict__ bnM, const float* __restrict__ bnV) {
    __shared__ float As[2][BM][ALD];
    __shared__ float Bs[2][BK][BLD];
    const int K = 2304;
    int z = blockIdx.z;
    img += (size_t)z * 256 * 4096;
    C   += (size_t)z * 256 * 4096;
    int bm = blockIdx.y * BM, bn = blockIdx.x * BNN;
    int tid = threadIdx.x, warp = tid >> 5, lane = tid & 31;
    int wr = warp >> 1, wc = warp & 1;
    int lg = lane >> 2, lq = lane & 3;

    float acc[4][8][4];
    #pragma unroll
    for (int r = 0; r < 4; r++)
        #pragma unroll
        for (int c = 0; c < 8; c++)
            #pragma unroll
            for (int e = 0; e < 4; e++)
                acc[r][c][e] = 0.f;

    int aRow0 = tid >> 2, aCol = (tid & 3) * 4;
    int aDst = ((aCol >> 3) * 8) + ((aCol >> 2) & 1);
    int bRow0 = tid >> 5, bCol = (tid & 31) * 4;
    int n = bn + bCol;
    int y0 = n >> 6, x0 = n & 63;

    float4 pa[4];
    float pbv[4][4];

    auto loadB = [&](int kbase) {
        #pragma unroll
        for (int i = 0; i < 4; i++) {
            int k = kbase + bRow0 + 4 * i;
            int ic = k / 9, kk = k - ic * 9;
            int ky = kk / 3, kx = kk - ky * 3;
            int gy = y0 + ky - 1;
            const float* p = img + ((size_t)ic * 64 + gy) * 64;
            bool rok = (unsigned)gy < 64u;
            #pragma unroll
            for (int e = 0; e < 4; e++) {
                int gx = x0 + e + kx - 1;
                pbv[i][e] = (rok && (unsigned)gx < 64u) ? p[gx] : 0.f;
            }
        }
    };

    #pragma unroll
    for (int i = 0; i < 4; i++)
        pa[i] = *(const float4*)(W + (size_t)(bm + aRow0 + 32 * i) * 2304 + aCol);
    loadB(0);
    #pragma unroll
    for (int i = 0; i < 4; i++) {
        float* d = &As[0][aRow0 + 32 * i][aDst];
        d[0] = to_tf32(pa[i].x); d[2] = to_tf32(pa[i].y);
        d[4] = to_tf32(pa[i].z); d[6] = to_tf32(pa[i].w);
        float* bd = &Bs[0][bRow0 + 4 * i][bCol];
        #pragma unroll
        for (int e = 0; e < 4; e++) bd[e] = to_tf32(pbv[i][e]);
    }
    __syncthreads();

    int cur = 0;
    for (int k0 = 0; k0 < K; k0 += BK) {
        int kn = k0 + BK;
        if (kn < K) {
            #pragma unroll
            for (int i = 0; i < 4; i++)
                pa[i] = *(const float4*)(W + (size_t)(bm + aRow0 + 32 * i) * 2304 + kn + aCol);
            loadB(kn);
        }
        #pragma unroll
        for (int s = 0; s < 2; s++) {
            unsigned a[4][4];
            #pragma unroll
            for (int r = 0; r < 4; r++) {
                const float* ap = &As[cur][wr * 64 + r * 16 + lg][s * 8 + 2 * lq];
                float2 lo = *(const float2*)ap;
                float2 hi = *(const float2*)(ap + 8 * ALD);
                a[r][0] = __float_as_uint(lo.x); a[r][1] = __float_as_uint(hi.x);
                a[r][2] = __float_as_uint(lo.y); a[r][3] = __float_as_uint(hi.y);
            }
            #pragma unroll
            for (int c = 0; c < 8; c++) {
                int nn = wc * 64 + c * 8 + lg;
                unsigned b0 = __float_as_uint(Bs[cur][s * 8 + lq][nn]);
                unsigned b1 = __float_as_uint(Bs[cur][s * 8 + lq + 4][nn]);
                #pragma unroll
                for (int r = 0; r < 4; r++)
                    mma8(acc[r][c], a[r], b0, b1);
            }
        }
        if (kn < K) {
            #pragma unroll
            for (int i = 0; i < 4; i++) {
                float* d = &As[cur ^ 1][aRow0 + 32 * i][aDst];
                d[0] = to_tf32(pa[i].x); d[2] = to_tf32(pa[i].y);
                d[4] = to_tf32(pa[i].z); d[6] = to_tf32(pa[i].w);
                float* bd = &Bs[cur ^ 1][bRow0 + 4 * i][bCol];
                #pragma unroll
                for (int e = 0; e < 4; e++) bd[e] = to_tf32(pbv[i][e]);
            }
        }
        __syncthreads();
        cur ^= 1;
    }

    #pragma unroll
    for (int r = 0; r < 4; r++) {
        #pragma unroll
        for (int half = 0; half < 2; half++) {
            int row = bm + wr * 64 + r * 16 + lg + half * 8;
            float s_ = bnG[row] * rsqrtf(bnV[row] + EPSF);
            float sh = bnB[row] - bnM[row] * s_;
            #pragma unroll
            for (int c = 0; c < 8; c++) {
                int col = bn + wc * 64 + c * 8 + 2 * lq;
                float v0 = acc[r][c][half * 2] * s_ + sh;
                float v1 = acc[r][c][half * 2 + 1] * s_ + sh;
                v0 = v0 / (1.f + __expf(-v0));
                v1 = v1 / (1.f + __expf(-v1));
                *(float2*)(C + (size_t)row * 4096 + col) = make_float2(v0, v1);
            }
        }
    }
}

// ---------------- attention: branch-free softmax (scores are O(0.1)) ----------------
__global__ void attn_kernel(const float* __restrict__ qkv, float* __restrict__ att) {
    int bp = blockIdx.x;
    int h  = blockIdx.y;
    int n  = threadIdx.x;
    __shared__ float ks[256 * 8];
    __shared__ float vs[256 * 8];
    int row = bp * 256 + n;
    const float* base = qkv + (size_t)row * 128 + h * 8;
    float4 q0 = *(const float4*)(base);
    float4 q1 = *(const float4*)(base + 4);
    *(float4*)&ks[n * 8]     = *(const float4*)(base + 32);
    *(float4*)&ks[n * 8 + 4] = *(const float4*)(base + 36);
    *(float4*)&vs[n * 8]     = *(const float4*)(base + 64);
    *(float4*)&vs[n * 8 + 4] = *(const float4*)(base + 68);
    __syncthreads();
    float q[8] = {q0.x, q0.y, q0.z, q0.w, q1.x, q1.y, q1.z, q1.w};
    #pragma unroll
    for (int j = 0; j < 8; j++) q[j] *= 0.35355339059327373f;
    float ssum = 0.f;
    float acc[8] = {};
    for (int m = 0; m < 256; m++) {
        float4 ka = *(const float4*)&ks[m * 8];
        float4 kb = *(const float4*)&ks[m * 8 + 4];
        float d = q[0]*ka.x + q[1]*ka.y + q[2]*ka.z + q[3]*ka.w
                + q[4]*kb.x + q[5]*kb.y + q[6]*kb.z + q[7]*kb.w;
        float w = __expf(d);
        ssum += w;
        float4 va = *(const float4*)&vs[m * 8];
        float4 vb = *(const float4*)&vs[m * 8 + 4];
        acc[0] += w * va.x; acc[1] += w * va.y; acc[2] += w * va.z; acc[3] += w * va.w;
        acc[4] += w * vb.x; acc[5] += w * vb.y; acc[6] += w * vb.z; acc[7] += w * vb.w;
    }
    float inv = 1.f / ssum;
    float* o = att + (size_t)row * 32 + h * 8;
    *(float4*)(o)     = make_float4(acc[0]*inv, acc[1]*inv, acc[2]*inv, acc[3]*inv);
    *(float4*)(o + 4) = make_float4(acc[4]*inv, acc[5]*inv, acc[6]*inv, acc[7]*inv);
}

// ---------------- FFT stage 1: rfft along W ----------------
__global__ void fft1_kernel(const float* __restrict__ zp, float2* __restrict__ f1) {
    __shared__ float sX[64][128];
    __shared__ float2 tw[64];
    int c0 = blockIdx.x * 128;
    int h = blockIdx.y, b = blockIdx.z;
    int tid = threadIdx.x;
    if (tid < 64) {
        float sn, cs; sincosf(tid * PI_OVER_32, &sn, &cs);
        tw[tid] = make_float2(cs, sn);
    }
    const float* src = zp + ((size_t)(b * 64 + h) * 64) * 256 + c0;
    #pragma unroll
    for (int i = 0; i < 8; i++) {
        int idx = tid + i * 256;
        int x = idx >> 5, cc = (idx & 31) * 4;
        *(float4*)&sX[x][cc] = *(const float4*)(src + (size_t)x * 256 + cc);
    }
    __syncthreads();
    int c = tid & 127, wg = tid >> 7;
    int nw = 17 - wg;
    float re[17], im[17];
    #pragma unroll
    for (int j = 0; j < 17; j++) { re[j] = 0.f; im[j] = 0.f; }
    for (int x = 0; x < 64; x++) {
        float g = sX[x][c];
        int m = (wg * x) & 63;
        int step = (2 * x) & 63;
        #pragma unroll
        for (int j = 0; j < 17; j++) {
            if (j < nw) {
                float2 t = tw[m];
                re[j] += g * t.x;
                im[j] -= g * t.y;
                m = (m + step) & 63;
            }
        }
    }
    float2* dst = f1 + ((size_t)(b * 64 + h) * 33) * 256 + c0 + c;
    #pragma unroll
    for (int j = 0; j < 17; j++) {
        if (j < nw) {
            int w = wg + 2 * j;
            dst[(size_t)w * 256] = make_float2(re[j] * 0.125f, im[j] * 0.125f);
        }
    }
}

// ---------------- FFT stages 2+3 fused ----------------
__global__ void fft23_kernel(const float2* __restrict__ f1, const float2* __restrict__ fw,
                             float2* __restrict__ out) {
    __shared__ float2 sA[64][32];
    __shared__ float2 sB[64][32];
    __shared__ float2 tw[64];
    int w = blockIdx.x;
    int c0 = blockIdx.y * 32;
    int b = blockIdx.z;
    int tid = threadIdx.x;
    if (tid < 64) {
        float sn, cs; sincosf(tid * PI_OVER_32, &sn, &cs);
        tw[tid] = make_float2(cs, sn);
    }
    #pragma unroll
    for (int i = 0; i < 8; i++) {
        int idx = tid + i * 256;
        int hh = idx >> 5, cc = idx & 31;
        sA[hh][cc] = f1[((size_t)(b * 64 + hh) * 33 + w) * 256 + c0 + cc];
    }
    __syncthreads();

    int c = tid & 31;
    int kb = tid >> 5;
    {
        float re[8] = {}, im[8] = {};
        for (int hh = 0; hh < 64; hh++) {
            float2 g = sA[hh][c];
            int m = ((kb * 8) * hh) & 63;
            #pragma unroll
            for (int j = 0; j < 8; j++) {
                float2 t = tw[m];
                re[j] += g.x * t.x + g.y * t.y;
                im[j] += g.y * t.x - g.x * t.y;
                m = (m + hh) & 63;
            }
        }
        #pragma unroll
        for (int j = 0; j < 8; j++) {
            int k = kb * 8 + j;
            float2 wc = fw[((size_t)k * 33 + w) * 256 + c0 + c];
            float rr = re[j] * 0.125f, ii = im[j] * 0.125f;
            sB[k][c] = make_float2(rr * wc.x - ii * wc.y, rr * wc.y + ii * wc.x);
        }
    }
    __syncthreads();

    int hb = tid >> 5;
    {
        float re[8] = {}, im[8] = {};
        for (int k = 0; k < 64; k++) {
            float2 g = sB[k][c];
            int m = (k * (hb * 8)) & 63;
            #pragma unroll
            for (int j = 0; j < 8; j++) {
                float2 t = tw[m];
                re[j] += g.x * t.x - g.y * t.y;
                im[j] += g.x * t.y + g.y * t.x;
                m = (m + k) & 63;
            }
        }
        #pragma unroll
        for (int j = 0; j < 8; j++) {
            int hh = hb * 8 + j;
            out[((size_t)(b * 64 + hh) * 33 + w) * 256 + c0 + c] =
                make_float2(re[j] * 0.125f, im[j] * 0.125f);
        }
    }
}

// ---------------- FFT stage 4: irfft along W ----------------
__global__ void fft4_kernel(const float2* __restrict__ A, float* __restrict__ zf) {
    __shared__ float2 sA[33][64];
    __shared__ float2 tw[64];
    int c0 = blockIdx.x * 64;
    int h = blockIdx.y, b = blockIdx.z;
    int tid = threadIdx.x;
    if (tid < 64) {
        float sn, cs; sincosf(tid * PI_OVER_32, &sn, &cs);
        tw[tid] = make_float2(cs, sn);
    }
    const float2* src = A + ((size_t)(b * 64 + h) * 33) * 256 + c0;
    for (int idx = tid; idx < 33 * 64; idx += 256) {
        int w = idx >> 6, cc = idx & 63;
        sA[w][cc] = src[(size_t)w * 256 + cc];
    }
    __syncthreads();
    int c = tid >> 2;
    int x0 = (tid & 3) * 16;
    float r[16];
    {
        float2 a0 = sA[0][c], a32 = sA[32][c];
        #pragma unroll
        for (int j = 0; j < 16; j++)
            r[j] = a0.x + (((x0 + j) & 1) ? -a32.x : a32.x);
    }
    for (int w = 1; w < 32; w++) {
        float2 a = sA[w][c];
        int m = (w * x0) & 63;
        #pragma unroll
        for (int j = 0; j < 16; j++) {
            float2 t = tw[m];
            r[j] += 2.f * (a.x * t.x - a.y * t.y);
            m = (m + w) & 63;
        }
    }
    float* dst = zf + ((size_t)(b * 256 + c0 + c) * 64 + h) * 64 + x0;
    #pragma unroll
    for (int q = 0; q < 4; q++) {
        float4 v = make_float4(r[q*4] * 0.125f, r[q*4+1] * 0.125f,
                               r[q*4+2] * 0.125f, r[q*4+3] * 0.125f);
        *(float4*)(dst + q * 4) = v;
    }
}

// ---------------- host launch ----------------
extern "C" void kernel_launch(void* const* d_in, const int* in_sizes, int n_in,
                              void* d_out, int out_size) {
    const float* x      = (const float*)d_in[0];
    const float* ln1_g  = (const float*)d_in[1];
    const float* ln1_b  = (const float*)d_in[2];
    const float* wqkv   = (const float*)d_in[3];
    const float* wout   = (const float*)d_in[4];
    const float* bout   = (const float*)d_in[5];
    const float* ln2_g  = (const float*)d_in[6];
    const float* ln2_b  = (const float*)d_in[7];
    const float* w1     = (const float*)d_in[8];
    const float* b1     = (const float*)d_in[9];
    const float* w2     = (const float*)d_in[10];
    const float* b2     = (const float*)d_in[11];
    const float* fft_w  = (const float*)d_in[12];
    const float* conv3w = (const float*)d_in[13];
    const float* bn3_g  = (const float*)d_in[14];
    const float* bn3_b  = (const float*)d_in[15];
    const float* bn3_m  = (const float*)d_in[16];
    const float* bn3_v  = (const float*)d_in[17];
    const float* conv4w = (const float*)d_in[18];
    const float* bn4_g  = (const float*)d_in[19];
    const float* bn4_b  = (const float*)d_in[20];
    const float* bn4_m  = (const float*)d_in[21];
    const float* bn4_v  = (const float*)d_in[22];
    float* outp = (float*)d_out;

    float *u, *y, *ac, *t, *lnb, *qk, *at, *mlp, *zp, *zf, *c3;
    float2 *f1, *f2;
    cudaGetSymbolAddress((void**)&u,   g_u);
    cudaGetSymbolAddress((void**)&y,   g_y);
    cudaGetSymbolAddress((void**)&ac,  g_acc);
    cudaGetSymbolAddress((void**)&t,   g_t);
    cudaGetSymbolAddress((void**)&lnb, g_ln);
    cudaGetSymbolAddress((void**)&qk,  g_qkv);
    cudaGetSymbolAddress((void**)&at,  g_att);
    cudaGetSymbolAddress((void**)&mlp, g_mlp);
    cudaGetSymbolAddress((void**)&zp,  g_zp);
    cudaGetSymbolAddress((void**)&f1,  g_f1);
    cudaGetSymbolAddress((void**)&f2,  g_f2);
    cudaGetSymbolAddress((void**)&zf,  g_zf);
    cudaGetSymbolAddress((void**)&c3,  g_c3);

    const float* NUL = (const float*)0;

    zero_kernel<<<16384, 256>>>(ac);
    unfold_kernel<<<dim3(128, 8, 16), 256>>>(x, u);

    for (int g = 0; g < 4; g++) {
        group_in_kernel<<<4096, 256>>>((const float4*)u, (const float4*)ac, (float4*)t, g);
        for (int i = 0; i < 2; i++) {
            // --- attention block ---
            ln_kernel<<<4096, 256>>>(t, ln1_g + i * 256, ln1_b + i * 256, lnb);
            gemm128_kernel<<<dim3(1, 128, 1), 128>>>(lnb, wqkv + i * 256 * 96,
                wqkv + i * 256 * 96, 1 << 30, qk,
                NUL, NUL, NUL, NUL, NUL, NUL,
                16384, 96, 256, 256, 96, 128, 0, 0, 0, 0);
            attn_kernel<<<dim3(64, 4), 256>>>(qk, at);
            gemm128_kernel<<<dim3(2, 128, 1), 128>>>(at, wout + i * 32 * 256,
                wout + i * 32 * 256, 1 << 30, t,
                bout + i * 256, t, NUL, NUL, NUL, NUL,
                16384, 256, 32, 32, 256, 256, 0, 0, 0, 0);
            // --- MLP block ---
            ln_kernel<<<4096, 256>>>(t, ln2_g + i * 256, ln2_b + i * 256, lnb);
            gemm128_kernel<<<dim3(4, 128, 1), 128>>>(lnb, w1 + i * 256 * 512,
                w1 + i * 256 * 512, 1 << 30, mlp,
                b1 + i * 512, NUL, NUL, NUL, NUL, NUL,
                16384, 512, 256, 256, 512, 512, 1, 0, 0, 0);
            gemm128_kernel<<<dim3(2, 128, 1), 128>>>(mlp, w2 + i * 512 * 256,
                w2 + i * 512 * 256, 1 << 30, t,
                b2 + i * 256, t, NUL, NUL, NUL, NUL,
                16384, 256, 512, 512, 256, 256, 0, 0, 0, 0);
        }
        group_store_kernel<<<4096, 256>>>((const float4*)t, (float4*)y, (float4*)ac, g);
    }

    fold_kernel<<<16384, 256>>>((const float4*)y, (float4*)zp);

    fft1_kernel<<<dim3(2, 64, 16), 256>>>(zp, f1);
    fft23_kernel<<<dim3(33, 8, 16), 256>>>(f1, (const float2*)fft_w, f2);
    fft4_kernel<<<dim3(4, 64, 16), 256>>>(f2, zf);

    // conv3 (1x1, 512->256): single GEMM, B = [zf ; x] via dual-source, + BN + SiLU
    gemm128_kernel<<<dim3(32, 2, 16), 128>>>(conv3w, zf, x, 256, c3,
        NUL, NUL, bn3_g, bn3_b, bn3_m, bn3_v,
        256, 4096, 512, 512, 4096, 4096, 1, 0, 1048576LL, 1048576LL);

    // conv4 (3x3, 256->256) implicit GEMM + BN + SiLU
    conv4_gemm_kernel<<<dim3(32, 2, 16), 128>>>(conv4w, c3, outp,
                                                bn4_g, bn4_b, bn4_m, bn4_v);
}

// round 10
// speedup vs baseline: 2.7887x; 1.2577x over previous
#include <cuda_runtime.h>
#include <cuda_fp16.h>
#include <math.h>

#define EPSF 1e-5f
#define PI_OVER_32 0.09817477042468103f

// ---------------- constant permutations ----------------
__constant__ int c_IDX[16]  = {0,7,10,13,1,4,11,14,2,5,8,15,3,6,9,12};
__constant__ int c_BACK[16] = {0,4,8,12,5,9,13,1,10,14,2,6,15,3,7,11};

// ---------------- device scratch (no allocs allowed) ----------------
__device__ float  g_u  [16*16*256*256];
__device__ float  g_y  [16*16*256*256];
__device__ float  g_acc[16*4*256*256];
__device__ float  g_t  [16*4*256*256];
__device__ float  g_ln [16*4*256*256];
__device__ float  g_qkv[16*4*256*128];    // ld=128 (cols 96..127 pad)
__device__ float  g_att[16*4*256*32];
__device__ float  g_mlp[16*4*256*512];
__device__ float  g_zp [16*64*64*256];
__device__ float2 g_f1 [16*64*33*256];
__device__ float2 g_f2 [16*64*33*256];
__device__ float  g_zf [16*256*64*64];
__device__ float  g_c3 [16*256*64*64];

// fp16 m16n8k16 mma, fp32 accumulate
__device__ __forceinline__ void mma16(float* d, const unsigned* a, unsigned b0, unsigned b1) {
    asm volatile(
        "mma.sync.aligned.m16n8k16.row.col.f32.f16.f16.f32 "
        "{%0,%1,%2,%3}, {%4,%5,%6,%7}, {%8,%9}, {%0,%1,%2,%3};"
        : "+f"(d[0]), "+f"(d[1]), "+f"(d[2]), "+f"(d[3])
        : "r"(a[0]), "r"(a[1]), "r"(a[2]), "r"(a[3]), "r"(b0), "r"(b1));
}

// ---------------- tiny utility kernels ----------------
__global__ void unfold_kernel(const float* __restrict__ x, float* __restrict__ u) {
    __shared__ float tile[32][33];
    int b  = blockIdx.z;
    int c0 = blockIdx.y * 32;
    int s0 = blockIdx.x * 32;
    int tx = threadIdx.x & 31, ty = threadIdx.x >> 5;
    #pragma unroll
    for (int cc = 0; cc < 4; cc++)
        tile[ty + cc * 8][tx] =
            x[(size_t)(b * 256 + c0 + ty + cc * 8) * 4096 + s0 + tx];
    __syncthreads();
    #pragma unroll
    for (int cc = 0; cc < 4; cc++) {
        int s = s0 + ty + cc * 8;
        int h = s >> 6, w = s & 63;
        int kp = (h & 3) * 4 + (w & 3);
        int j = c_BACK[kp];
        int l = (h >> 2) * 16 + (w >> 2);
        u[((size_t)(b * 16 + j) * 256 + l) * 256 + c0 + tx] = tile[tx][ty + cc * 8];
    }
}

__device__ __forceinline__ float4 f4add(float4 a, float4 b) {
    return make_float4(a.x + b.x, a.y + b.y, a.z + b.z, a.w + b.w);
}

// t = u slot 0..3 (g=0, acc=0)
__global__ void t_init_kernel(const float4* __restrict__ u, float4* __restrict__ t) {
    int i = blockIdx.x * 256 + threadIdx.x;
    int c4 = i & 63;
    int l = (i >> 6) & 255;
    int p = (i >> 14) & 3;
    int b = i >> 16;
    t[i] = u[((size_t)(b * 16 + p) * 256 + l) * 64 + c4];
}

// y[g]=t; acc = (first?0:acc)+t; t = u[g+1] + acc
__global__ void group_step_kernel(const float4* __restrict__ u, float4* __restrict__ t,
                                  float4* __restrict__ y, float4* __restrict__ acc,
                                  int g, int first) {
    int i = blockIdx.x * 256 + threadIdx.x;
    int c4 = i & 63;
    int l = (i >> 6) & 255;
    int p = (i >> 14) & 3;
    int b = i >> 16;
    float4 v = t[i];
    y[((size_t)(b * 16 + g * 4 + p) * 256 + l) * 64 + c4] = v;
    float4 a = first ? v : f4add(acc[i], v);
    acc[i] = a;
    t[i] = f4add(u[((size_t)(b * 16 + (g + 1) * 4 + p) * 256 + l) * 64 + c4], a);
}

__global__ void y_store_kernel(const float4* __restrict__ t, float4* __restrict__ y, int g) {
    int i = blockIdx.x * 256 + threadIdx.x;
    int c4 = i & 63;
    int l = (i >> 6) & 255;
    int p = (i >> 14) & 3;
    int b = i >> 16;
    y[((size_t)(b * 16 + g * 4 + p) * 256 + l) * 64 + c4] = t[i];
}

__global__ void fold_kernel(const float4* __restrict__ y, float4* __restrict__ zp) {
    int i = blockIdx.x * 256 + threadIdx.x;
    int c4 = i & 63;
    int wp = (i >> 6) & 63;
    int hp = (i >> 12) & 63;
    int b  = i >> 18;
    int ky = hp & 3, ph = hp >> 2;
    int kx = wp & 3, pw = wp >> 2;
    int j = c_BACK[ky * 4 + kx];
    int l = ph * 16 + pw;
    zp[i] = y[((size_t)(b * 16 + j) * 256 + l) * 64 + c4];
}

// ---------------- layernorm: 4 rows per block, float4 ----------------
__global__ void ln_kernel(const float* __restrict__ in, const float* __restrict__ gw,
                          const float* __restrict__ bw, float* __restrict__ out) {
    int tid = threadIdx.x;
    int r = tid >> 6;
    int t = tid & 63;
    size_t row = (size_t)blockIdx.x * 4 + r;
    float4 v = *(const float4*)(in + row * 256 + t * 4);
    float s  = v.x + v.y + v.z + v.w;
    float sq = v.x * v.x + v.y * v.y + v.z * v.z + v.w * v.w;
    #pragma unroll
    for (int o = 16; o; o >>= 1) {
        s  += __shfl_xor_sync(0xffffffffu, s, o);
        sq += __shfl_xor_sync(0xffffffffu, sq, o);
    }
    __shared__ float ss[8], sqs[8];
    int warp = tid >> 5;
    if ((tid & 31) == 0) { ss[warp] = s; sqs[warp] = sq; }
    __syncthreads();
    s  = ss[r * 2] + ss[r * 2 + 1];
    sq = sqs[r * 2] + sqs[r * 2 + 1];
    float mean = s * (1.f / 256.f);
    float var  = sq * (1.f / 256.f) - mean * mean;
    float rstd = rsqrtf(var + EPSF);
    float4 g4 = *(const float4*)(gw + t * 4);
    float4 b4 = *(const float4*)(bw + t * 4);
    float4 o4;
    o4.x = (v.x - mean) * rstd * g4.x + b4.x;
    o4.y = (v.y - mean) * rstd * g4.y + b4.y;
    o4.z = (v.z - mean) * rstd * g4.z + b4.z;
    o4.w = (v.w - mean) * rstd * g4.w + b4.w;
    *(float4*)(out + row * 256 + t * 4) = o4;
}

// ============ fp16-mma GEMM: BM=128, BN=128, BK=16, 4 warps, 64x64 warp tile ======
// A smem: half2, per-row k interleaved (k' = (j>>1)*4 + g*2 + (j&1), g=k>>3, j=k&7)
//   -> A frag (m16 x k16) = 2x LDS.64
// B smem: half2 [kpair][n] -> B frag = 2x LDS.32 (BLD2=136 -> conflict-free)
// Epilogue: direct register->global float2 (same acc layout as m16n8k8).
#define BM 128
#define BNN 128
#define BK 16
#define ALD2 10
#define BLD2 136

__global__ void __launch_bounds__(128)
gemm128_kernel(const float* __restrict__ A, const float* __restrict__ B,
               const float* __restrict__ B2, int ksplit,
               float* __restrict__ C,
               const float* __restrict__ bias, const float* __restrict__ resid,
               const float* __restrict__ bnG, const float* __restrict__ bnB,
               const float* __restrict__ bnM, const float* __restrict__ bnV,
               int M, int N, int K, int lda, int ldb, int ldc,
               int act, long long sA, long long sB, long long sC) {
    __shared__ __align__(16) __half2 As2[2][BM][ALD2];
    __shared__ __align__(16) __half2 Bs2[2][8][BLD2];
    int z = blockIdx.z;
    A += z * sA; B += z * sB; if (B2) B2 += z * sB;
    C += z * sC;
    const float* R = resid ? resid + z * sC : (const float*)0;
    int bm = blockIdx.y * BM, bn = blockIdx.x * BNN;
    int tid = threadIdx.x, warp = tid >> 5, lane = tid & 31;
    int wr = warp >> 1, wc = warp & 1;
    int lg = lane >> 2, lq = lane & 3;

    float acc[4][8][4];
    #pragma unroll
    for (int r = 0; r < 4; r++)
        #pragma unroll
        for (int c = 0; c < 8; c++)
            #pragma unroll
            for (int e = 0; e < 4; e++)
                acc[r][c][e] = 0.f;

    int aRow0 = tid >> 2, aCol = (tid & 3) * 4;
    int aP0 = ((aCol & 7) >> 1) * 2 + (aCol >> 3);   // first half2 pair slot
    int kpB = (tid >> 5) * 2;                        // kpair base: covers kpB, kpB+1
    int bN = (tid & 31) * 4;
    int cB = bn + bN;
    bool bOK = (cB < N);

    float4 pa[4], pb[4];
    const float4 f4z = make_float4(0.f, 0.f, 0.f, 0.f);

    #pragma unroll
    for (int i = 0; i < 4; i++)
        pa[i] = *(const float4*)(A + (size_t)(bm + aRow0 + 32 * i) * lda + aCol);
    #pragma unroll
    for (int j = 0; j < 4; j++) {
        int k = 2 * kpB + j;
        const float* q = (k < ksplit) ? B + (size_t)k * ldb
                                      : B2 + (size_t)(k - ksplit) * ldb;
        pb[j] = bOK ? *(const float4*)(q + cB) : f4z;
    }
    #pragma unroll
    for (int i = 0; i < 4; i++) {
        As2[0][aRow0 + 32 * i][aP0]     = __floats2half2_rn(pa[i].x, pa[i].y);
        As2[0][aRow0 + 32 * i][aP0 + 2] = __floats2half2_rn(pa[i].z, pa[i].w);
    }
    {
        __half2 h0[4], h1[4];
        h0[0] = __floats2half2_rn(pb[0].x, pb[1].x);
        h0[1] = __floats2half2_rn(pb[0].y, pb[1].y);
        h0[2] = __floats2half2_rn(pb[0].z, pb[1].z);
        h0[3] = __floats2half2_rn(pb[0].w, pb[1].w);
        h1[0] = __floats2half2_rn(pb[2].x, pb[3].x);
        h1[1] = __floats2half2_rn(pb[2].y, pb[3].y);
        h1[2] = __floats2half2_rn(pb[2].z, pb[3].z);
        h1[3] = __floats2half2_rn(pb[2].w, pb[3].w);
        *(uint4*)&Bs2[0][kpB][bN]     = *(uint4*)h0;
        *(uint4*)&Bs2[0][kpB + 1][bN] = *(uint4*)h1;
    }
    __syncthreads();

    int cur = 0;
    for (int k0 = 0; k0 < K; k0 += BK) {
        int kn = k0 + BK;
        if (kn < K) {
            #pragma unroll
            for (int i = 0; i < 4; i++)
                pa[i] = *(const float4*)(A + (size_t)(bm + aRow0 + 32 * i) * lda + kn + aCol);
            #pragma unroll
            for (int j = 0; j < 4; j++) {
                int k = kn + 2 * kpB + j;
                const float* q = (k < ksplit) ? B + (size_t)k * ldb
                                              : B2 + (size_t)(k - ksplit) * ldb;
                pb[j] = bOK ? *(const float4*)(q + cB) : f4z;
            }
        }
        {
            unsigned a[4][4];
            #pragma unroll
            for (int r = 0; r < 4; r++) {
                int row = wr * 64 + r * 16 + lg;
                uint2 lo = *(const uint2*)&As2[cur][row][2 * lq];
                uint2 hi = *(const uint2*)&As2[cur][row + 8][2 * lq];
                a[r][0] = lo.x; a[r][1] = hi.x; a[r][2] = lo.y; a[r][3] = hi.y;
            }
            #pragma unroll
            for (int c = 0; c < 8; c++) {
                int nn = wc * 64 + c * 8 + lg;
                unsigned b0 = *(const unsigned*)&Bs2[cur][lq][nn];
                unsigned b1 = *(const unsigned*)&Bs2[cur][lq + 4][nn];
                #pragma unroll
                for (int r = 0; r < 4; r++)
                    mma16(acc[r][c], a[r], b0, b1);
            }
        }
        if (kn < K) {
            #pragma unroll
            for (int i = 0; i < 4; i++) {
                As2[cur ^ 1][aRow0 + 32 * i][aP0]     = __floats2half2_rn(pa[i].x, pa[i].y);
                As2[cur ^ 1][aRow0 + 32 * i][aP0 + 2] = __floats2half2_rn(pa[i].z, pa[i].w);
            }
            __half2 h0[4], h1[4];
            h0[0] = __floats2half2_rn(pb[0].x, pb[1].x);
            h0[1] = __floats2half2_rn(pb[0].y, pb[1].y);
            h0[2] = __floats2half2_rn(pb[0].z, pb[1].z);
            h0[3] = __floats2half2_rn(pb[0].w, pb[1].w);
            h1[0] = __floats2half2_rn(pb[2].x, pb[3].x);
            h1[1] = __floats2half2_rn(pb[2].y, pb[3].y);
            h1[2] = __floats2half2_rn(pb[2].z, pb[3].z);
            h1[3] = __floats2half2_rn(pb[2].w, pb[3].w);
            *(uint4*)&Bs2[cur ^ 1][kpB][bN]     = *(uint4*)h0;
            *(uint4*)&Bs2[cur ^ 1][kpB + 1][bN] = *(uint4*)h1;
        }
        __syncthreads();
        cur ^= 1;
    }

    // direct epilogue: resid -> bias -> bn-affine(row) -> silu
    #pragma unroll
    for (int r = 0; r < 4; r++) {
        #pragma unroll
        for (int half = 0; half < 2; half++) {
            int row = bm + wr * 64 + r * 16 + lg + half * 8;
            float sc = 1.f, sh = 0.f;
            if (bnG) {
                float s_ = bnG[row] * rsqrtf(bnV[row] + EPSF);
                sc = s_; sh = bnB[row] - bnM[row] * s_;
            }
            #pragma unroll
            for (int c = 0; c < 8; c++) {
                int col = bn + wc * 64 + c * 8 + 2 * lq;
                if (col < N) {
                    float v0 = acc[r][c][half * 2];
                    float v1 = acc[r][c][half * 2 + 1];
                    if (R) {
                        float2 rv = *(const float2*)(R + (size_t)row * ldc + col);
                        v0 += rv.x; v1 += rv.y;
                    }
                    if (bias) {
                        float2 bv = *(const float2*)(bias + col);
                        v0 += bv.x; v1 += bv.y;
                    }
                    v0 = v0 * sc + sh;
                    v1 = v1 * sc + sh;
                    if (act) {
                        v0 = v0 / (1.f + __expf(-v0));
                        v1 = v1 / (1.f + __expf(-v1));
                    }
                    *(float2*)(C + (size_t)row * ldc + col) = make_float2(v0, v1);
                }
            }
        }
    }
}

// ---------------- conv4 implicit GEMM, fp16 mma ----------------
__global__ void __launch_bounds__(128)
conv4_gemm_kernel(const float* __restrict__ W, const float* __restrict__ img,
                  float* __restrict__ C,
                  const float* __restrict__ bnG, const float* __restrict__ bnB,
                  const float* __restrict__ bnM, const float* __restrict__ bnV) {
    __shared__ __align__(16) __half2 As2[2][BM][ALD2];
    __shared__ __align__(16) __half2 Bs2[2][8][BLD2];
    const int K = 2304;
    int z = blockIdx.z;
    img += (size_t)z * 256 * 4096;
    C   += (size_t)z * 256 * 4096;
    int bm = blockIdx.y * BM, bn = blockIdx.x * BNN;
    int tid = threadIdx.x, warp = tid >> 5, lane = tid & 31;
    int wr = warp >> 1, wc = warp & 1;
    int lg = lane >> 2, lq = lane & 3;

    float acc[4][8][4];
    #pragma unroll
    for (int r = 0; r < 4; r++)
        #pragma unroll
        for (int c = 0; c < 8; c++)
            #pragma unroll
            for (int e = 0; e < 4; e++)
                acc[r][c][e] = 0.f;

    int aRow0 = tid >> 2, aCol = (tid & 3) * 4;
    int aP0 = ((aCol & 7) >> 1) * 2 + (aCol >> 3);
    int kpB = (tid >> 5) * 2;
    int bN = (tid & 31) * 4;
    int n = bn + bN;
    int y0 = n >> 6, x0 = n & 63;

    float4 pa[4];
    float pbv[4][4];

    auto loadB = [&](int kbase) {
        #pragma unroll
        for (int j = 0; j < 4; j++) {
            int k = kbase + 2 * kpB + j;
            int ic = k / 9, kk = k - ic * 9;
            int ky = kk / 3, kx = kk - ky * 3;
            int gy = y0 + ky - 1;
            const float* p = img + ((size_t)ic * 64 + gy) * 64;
            bool rok = (unsigned)gy < 64u;
            #pragma unroll
            for (int e = 0; e < 4; e++) {
                int gx = x0 + e + kx - 1;
                pbv[j][e] = (rok && (unsigned)gx < 64u) ? p[gx] : 0.f;
            }
        }
    };
    auto storeB = [&](int st) {
        __half2 h0[4], h1[4];
        #pragma unroll
        for (int e = 0; e < 4; e++) {
            h0[e] = __floats2half2_rn(pbv[0][e], pbv[1][e]);
            h1[e] = __floats2half2_rn(pbv[2][e], pbv[3][e]);
        }
        *(uint4*)&Bs2[st][kpB][bN]     = *(uint4*)h0;
        *(uint4*)&Bs2[st][kpB + 1][bN] = *(uint4*)h1;
    };

    #pragma unroll
    for (int i = 0; i < 4; i++)
        pa[i] = *(const float4*)(W + (size_t)(bm + aRow0 + 32 * i) * 2304 + aCol);
    loadB(0);
    #pragma unroll
    for (int i = 0; i < 4; i++) {
        As2[0][aRow0 + 32 * i][aP0]     = __floats2half2_rn(pa[i].x, pa[i].y);
        As2[0][aRow0 + 32 * i][aP0 + 2] = __floats2half2_rn(pa[i].z, pa[i].w);
    }
    storeB(0);
    __syncthreads();

    int cur = 0;
    for (int k0 = 0; k0 < K; k0 += BK) {
        int kn = k0 + BK;
        if (kn < K) {
            #pragma unroll
            for (int i = 0; i < 4; i++)
                pa[i] = *(const float4*)(W + (size_t)(bm + aRow0 + 32 * i) * 2304 + kn + aCol);
            loadB(kn);
        }
        {
            unsigned a[4][4];
            #pragma unroll
            for (int r = 0; r < 4; r++) {
                int row = wr * 64 + r * 16 + lg;
                uint2 lo = *(const uint2*)&As2[cur][row][2 * lq];
                uint2 hi = *(const uint2*)&As2[cur][row + 8][2 * lq];
                a[r][0] = lo.x; a[r][1] = hi.x; a[r][2] = lo.y; a[r][3] = hi.y;
            }
            #pragma unroll
            for (int c = 0; c < 8; c++) {
                int nn = wc * 64 + c * 8 + lg;
                unsigned b0 = *(const unsigned*)&Bs2[cur][lq][nn];
                unsigned b1 = *(const unsigned*)&Bs2[cur][lq + 4][nn];
                #pragma unroll
                for (int r = 0; r < 4; r++)
                    mma16(acc[r][c], a[r], b0, b1);
            }
        }
        if (kn < K) {
            #pragma unroll
            for (int i = 0; i < 4; i++) {
                As2[cur ^ 1][aRow0 + 32 * i][aP0]     = __floats2half2_rn(pa[i].x, pa[i].y);
                As2[cur ^ 1][aRow0 + 32 * i][aP0 + 2] = __floats2half2_rn(pa[i].z, pa[i].w);
            }
            storeB(cur ^ 1);
        }
        __syncthreads();
        cur ^= 1;
    }

    #pragma unroll
    for (int r = 0; r < 4; r++) {
        #pragma unroll
        for (int half = 0; half < 2; half++) {
            int row = bm + wr * 64 + r * 16 + lg + half * 8;
            float s_ = bnG[row] * rsqrtf(bnV[row] + EPSF);
            float sh = bnB[row] - bnM[row] * s_;
            #pragma unroll
            for (int c = 0; c < 8; c++) {
                int col = bn + wc * 64 + c * 8 + 2 * lq;
                float v0 = acc[r][c][half * 2] * s_ + sh;
                float v1 = acc[r][c][half * 2 + 1] * s_ + sh;
                v0 = v0 / (1.f + __expf(-v0));
                v1 = v1 / (1.f + __expf(-v1));
                *(float2*)(C + (size_t)row * 4096 + col) = make_float2(v0, v1);
            }
        }
    }
}

// ---------------- attention: branch-free softmax (scores are O(0.1)) ----------------
__global__ void attn_kernel(const float* __restrict__ qkv, float* __restrict__ att) {
    int bp = blockIdx.x;
    int h  = blockIdx.y;
    int n  = threadIdx.x;
    __shared__ float ks[256 * 8];
    __shared__ float vs[256 * 8];
    int row = bp * 256 + n;
    const float* base = qkv + (size_t)row * 128 + h * 8;
    float4 q0 = *(const float4*)(base);
    float4 q1 = *(const float4*)(base + 4);
    *(float4*)&ks[n * 8]     = *(const float4*)(base + 32);
    *(float4*)&ks[n * 8 + 4] = *(const float4*)(base + 36);
    *(float4*)&vs[n * 8]     = *(const float4*)(base + 64);
    *(float4*)&vs[n * 8 + 4] = *(const float4*)(base + 68);
    __syncthreads();
    float q[8] = {q0.x, q0.y, q0.z, q0.w, q1.x, q1.y, q1.z, q1.w};
    #pragma unroll
    for (int j = 0; j < 8; j++) q[j] *= 0.35355339059327373f;
    float ssum = 0.f;
    float acc[8] = {};
    for (int m = 0; m < 256; m++) {
        float4 ka = *(const float4*)&ks[m * 8];
        float4 kb = *(const float4*)&ks[m * 8 + 4];
        float d = q[0]*ka.x + q[1]*ka.y + q[2]*ka.z + q[3]*ka.w
                + q[4]*kb.x + q[5]*kb.y + q[6]*kb.z + q[7]*kb.w;
        float w = __expf(d);
        ssum += w;
        float4 va = *(const float4*)&vs[m * 8];
        float4 vb = *(const float4*)&vs[m * 8 + 4];
        acc[0] += w * va.x; acc[1] += w * va.y; acc[2] += w * va.z; acc[3] += w * va.w;
        acc[4] += w * vb.x; acc[5] += w * vb.y; acc[6] += w * vb.z; acc[7] += w * vb.w;
    }
    float inv = 1.f / ssum;
    float* o = att + (size_t)row * 32 + h * 8;
    *(float4*)(o)     = make_float4(acc[0]*inv, acc[1]*inv, acc[2]*inv, acc[3]*inv);
    *(float4*)(o + 4) = make_float4(acc[4]*inv, acc[5]*inv, acc[6]*inv, acc[7]*inv);
}

// ---------------- FFT stage 1: rfft along W ----------------
__global__ void fft1_kernel(const float* __restrict__ zp, float2* __restrict__ f1) {
    __shared__ float sX[64][128];
    __shared__ float2 tw[64];
    int c0 = blockIdx.x * 128;
    int h = blockIdx.y, b = blockIdx.z;
    int tid = threadIdx.x;
    if (tid < 64) {
        float sn, cs; sincosf(tid * PI_OVER_32, &sn, &cs);
        tw[tid] = make_float2(cs, sn);
    }
    const float* src = zp + ((size_t)(b * 64 + h) * 64) * 256 + c0;
    #pragma unroll
    for (int i = 0; i < 8; i++) {
        int idx = tid + i * 256;
        int x = idx >> 5, cc = (idx & 31) * 4;
        *(float4*)&sX[x][cc] = *(const float4*)(src + (size_t)x * 256 + cc);
    }
    __syncthreads();
    int c = tid & 127, wg = tid >> 7;
    int nw = 17 - wg;
    float re[17], im[17];
    #pragma unroll
    for (int j = 0; j < 17; j++) { re[j] = 0.f; im[j] = 0.f; }
    for (int x = 0; x < 64; x++) {
        float g = sX[x][c];
        int m = (wg * x) & 63;
        int step = (2 * x) & 63;
        #pragma unroll
        for (int j = 0; j < 17; j++) {
            if (j < nw) {
                float2 t = tw[m];
                re[j] += g * t.x;
                im[j] -= g * t.y;
                m = (m + step) & 63;
            }
        }
    }
    float2* dst = f1 + ((size_t)(b * 64 + h) * 33) * 256 + c0 + c;
    #pragma unroll
    for (int j = 0; j < 17; j++) {
        if (j < nw) {
            int w = wg + 2 * j;
            dst[(size_t)w * 256] = make_float2(re[j] * 0.125f, im[j] * 0.125f);
        }
    }
}

// ---------------- FFT stages 2+3 fused ----------------
__global__ void fft23_kernel(const float2* __restrict__ f1, const float2* __restrict__ fw,
                             float2* __restrict__ out) {
    __shared__ float2 sA[64][32];
    __shared__ float2 sB[64][32];
    __shared__ float2 tw[64];
    int w = blockIdx.x;
    int c0 = blockIdx.y * 32;
    int b = blockIdx.z;
    int tid = threadIdx.x;
    if (tid < 64) {
        float sn, cs; sincosf(tid * PI_OVER_32, &sn, &cs);
        tw[tid] = make_float2(cs, sn);
    }
    #pragma unroll
    for (int i = 0; i < 8; i++) {
        int idx = tid + i * 256;
        int hh = idx >> 5, cc = idx & 31;
        sA[hh][cc] = f1[((size_t)(b * 64 + hh) * 33 + w) * 256 + c0 + cc];
    }
    __syncthreads();

    int c = tid & 31;
    int kb = tid >> 5;
    {
        float re[8] = {}, im[8] = {};
        for (int hh = 0; hh < 64; hh++) {
            float2 g = sA[hh][c];
            int m = ((kb * 8) * hh) & 63;
            #pragma unroll
            for (int j = 0; j < 8; j++) {
                float2 t = tw[m];
                re[j] += g.x * t.x + g.y * t.y;
                im[j] += g.y * t.x - g.x * t.y;
                m = (m + hh) & 63;
            }
        }
        #pragma unroll
        for (int j = 0; j < 8; j++) {
            int k = kb * 8 + j;
            float2 wc = fw[((size_t)k * 33 + w) * 256 + c0 + c];
            float rr = re[j] * 0.125f, ii = im[j] * 0.125f;
            sB[k][c] = make_float2(rr * wc.x - ii * wc.y, rr * wc.y + ii * wc.x);
        }
    }
    __syncthreads();

    int hb = tid >> 5;
    {
        float re[8] = {}, im[8] = {};
        for (int k = 0; k < 64; k++) {
            float2 g = sB[k][c];
            int m = (k * (hb * 8)) & 63;
            #pragma unroll
            for (int j = 0; j < 8; j++) {
                float2 t = tw[m];
                re[j] += g.x * t.x - g.y * t.y;
                im[j] += g.x * t.y + g.y * t.x;
                m = (m + k) & 63;
            }
        }
        #pragma unroll
        for (int j = 0; j < 8; j++) {
            int hh = hb * 8 + j;
            out[((size_t)(b * 64 + hh) * 33 + w) * 256 + c0 + c] =
                make_float2(re[j] * 0.125f, im[j] * 0.125f);
        }
    }
}

// ---------------- FFT stage 4: irfft along W ----------------
__global__ void fft4_kernel(const float2* __restrict__ A, float* __restrict__ zf) {
    __shared__ float2 sA[33][64];
    __shared__ float2 tw[64];
    int c0 = blockIdx.x * 64;
    int h = blockIdx.y, b = blockIdx.z;
    int tid = threadIdx.x;
    if (tid < 64) {
        float sn, cs; sincosf(tid * PI_OVER_32, &sn, &cs);
        tw[tid] = make_float2(cs, sn);
    }
    const float2* src = A + ((size_t)(b * 64 + h) * 33) * 256 + c0;
    for (int idx = tid; idx < 33 * 64; idx += 256) {
        int w = idx >> 6, cc = idx & 63;
        sA[w][cc] = src[(size_t)w * 256 + cc];
    }
    __syncthreads();
    int c = tid >> 2;
    int x0 = (tid & 3) * 16;
    float r[16];
    {
        float2 a0 = sA[0][c], a32 = sA[32][c];
        #pragma unroll
        for (int j = 0; j < 16; j++)
            r[j] = a0.x + (((x0 + j) & 1) ? -a32.x : a32.x);
    }
    for (int w = 1; w < 32; w++) {
        float2 a = sA[w][c];
        int m = (w * x0) & 63;
        #pragma unroll
        for (int j = 0; j < 16; j++) {
            float2 t = tw[m];
            r[j] += 2.f * (a.x * t.x - a.y * t.y);
            m = (m + w) & 63;
        }
    }
    float* dst = zf + ((size_t)(b * 256 + c0 + c) * 64 + h) * 64 + x0;
    #pragma unroll
    for (int q = 0; q < 4; q++) {
        float4 v = make_float4(r[q*4] * 0.125f, r[q*4+1] * 0.125f,
                               r[q*4+2] * 0.125f, r[q*4+3] * 0.125f);
        *(float4*)(dst + q * 4) = v;
    }
}

// ---------------- host launch ----------------
extern "C" void kernel_launch(void* const* d_in, const int* in_sizes, int n_in,
                              void* d_out, int out_size) {
    const float* x      = (const float*)d_in[0];
    const float* ln1_g  = (const float*)d_in[1];
    const float* ln1_b  = (const float*)d_in[2];
    const float* wqkv   = (const float*)d_in[3];
    const float* wout   = (const float*)d_in[4];
    const float* bout   = (const float*)d_in[5];
    const float* ln2_g  = (const float*)d_in[6];
    const float* ln2_b  = (const float*)d_in[7];
    const float* w1     = (const float*)d_in[8];
    const float* b1     = (const float*)d_in[9];
    const float* w2     = (const float*)d_in[10];
    const float* b2     = (const float*)d_in[11];
    const float* fft_w  = (const float*)d_in[12];
    const float* conv3w = (const float*)d_in[13];
    const float* bn3_g  = (const float*)d_in[14];
    const float* bn3_b  = (const float*)d_in[15];
    const float* bn3_m  = (const float*)d_in[16];
    const float* bn3_v  = (const float*)d_in[17];
    const float* conv4w = (const float*)d_in[18];
    const float* bn4_g  = (const float*)d_in[19];
    const float* bn4_b  = (const float*)d_in[20];
    const float* bn4_m  = (const float*)d_in[21];
    const float* bn4_v  = (const float*)d_in[22];
    float* outp = (float*)d_out;

    float *u, *y, *ac, *t, *lnb, *qk, *at, *mlp, *zp, *zf, *c3;
    float2 *f1, *f2;
    cudaGetSymbolAddress((void**)&u,   g_u);
    cudaGetSymbolAddress((void**)&y,   g_y);
    cudaGetSymbolAddress((void**)&ac,  g_acc);
    cudaGetSymbolAddress((void**)&t,   g_t);
    cudaGetSymbolAddress((void**)&lnb, g_ln);
    cudaGetSymbolAddress((void**)&qk,  g_qkv);
    cudaGetSymbolAddress((void**)&at,  g_att);
    cudaGetSymbolAddress((void**)&mlp, g_mlp);
    cudaGetSymbolAddress((void**)&zp,  g_zp);
    cudaGetSymbolAddress((void**)&f1,  g_f1);
    cudaGetSymbolAddress((void**)&f2,  g_f2);
    cudaGetSymbolAddress((void**)&zf,  g_zf);
    cudaGetSymbolAddress((void**)&c3,  g_c3);

    const float* NUL = (const float*)0;

    unfold_kernel<<<dim3(128, 8, 16), 256>>>(x, u);
    t_init_kernel<<<4096, 256>>>((const float4*)u, (float4*)t);

    for (int g = 0; g < 4; g++) {
        for (int i = 0; i < 2; i++) {
            // --- attention block ---
            ln_kernel<<<4096, 256>>>(t, ln1_g + i * 256, ln1_b + i * 256, lnb);
            gemm128_kernel<<<dim3(1, 128, 1), 128>>>(lnb, wqkv + i * 256 * 96,
                wqkv + i * 256 * 96, 1 << 30, qk,
                NUL, NUL, NUL, NUL, NUL, NUL,
                16384, 96, 256, 256, 96, 128, 0, 0, 0, 0);
            attn_kernel<<<dim3(64, 4), 256>>>(qk, at);
            gemm128_kernel<<<dim3(2, 128, 1), 128>>>(at, wout + i * 32 * 256,
                wout + i * 32 * 256, 1 << 30, t,
                bout + i * 256, t, NUL, NUL, NUL, NUL,
                16384, 256, 32, 32, 256, 256, 0, 0, 0, 0);
            // --- MLP block ---
            ln_kernel<<<4096, 256>>>(t, ln2_g + i * 256, ln2_b + i * 256, lnb);
            gemm128_kernel<<<dim3(4, 128, 1), 128>>>(lnb, w1 + i * 256 * 512,
                w1 + i * 256 * 512, 1 << 30, mlp,
                b1 + i * 512, NUL, NUL, NUL, NUL, NUL,
                16384, 512, 256, 256, 512, 512, 1, 0, 0, 0);
            gemm128_kernel<<<dim3(2, 128, 1), 128>>>(mlp, w2 + i * 512 * 256,
                w2 + i * 512 * 256, 1 << 30, t,
                b2 + i * 256, t, NUL, NUL, NUL, NUL,
                16384, 256, 512, 512, 256, 256, 0, 0, 0, 0);
        }
        if (g < 3)
            group_step_kernel<<<4096, 256>>>((const float4*)u, (float4*)t,
                                             (float4*)y, (float4*)ac, g, g == 0);
        else
            y_store_kernel<<<4096, 256>>>((const float4*)t, (float4*)y, 3);
    }

    fold_kernel<<<16384, 256>>>((const float4*)y, (float4*)zp);

    fft1_kernel<<<dim3(2, 64, 16), 256>>>(zp, f1);
    fft23_kernel<<<dim3(33, 8, 16), 256>>>(f1, (const float2*)fft_w, f2);
    fft4_kernel<<<dim3(4, 64, 16), 256>>>(f2, zf);

    // conv3 (1x1, 512->256): single GEMM, B = [zf ; x] via dual-source, + BN + SiLU
    gemm128_kernel<<<dim3(32, 2, 16), 128>>>(conv3w, zf, x, 256, c3,
        NUL, NUL, bn3_g, bn3_b, bn3_m, bn3_v,
        256, 4096, 512, 512, 4096, 4096, 1, 0, 1048576LL, 1048576LL);

    // conv4 (3x3, 256->256) implicit GEMM + BN + SiLU
    conv4_gemm_kernel<<<dim3(32, 2, 16), 128>>>(conv4w, c3, outp,
                                                bn4_g, bn4_b, bn4_m, bn4_v);
}